// round 7
// baseline (speedup 1.0000x reference)
#include <cuda_runtime.h>
#include <cuda_bf16.h>
#include <math.h>
#include <stdint.h>

#define NN 883
#define NP 896
#define BB 64
#define TT 12
#define HID 64
#define EMBD 10
#define NB 4096
#define NCSEQ 49152
#define NC0 768
typedef __nv_bfloat16 bf16;

__device__ bf16 g_Ahi[NP * NP];
__device__ bf16 g_Alo[NP * NP];
__device__ bf16 g_X0hi[NP * NC0];
__device__ bf16 g_X0lo[NP * NC0];
__device__ bf16 g_AX0hi[NP * NC0];
__device__ bf16 g_AX0lo[NP * NC0];
__device__ bf16 g_WG0h[NN * 144 * 128];
__device__ bf16 g_WG0l[NN * 144 * 128];
__device__ bf16 g_WC0h[NN * 144 * 64];
__device__ bf16 g_WC0l[NN * 144 * 64];
__device__ bf16 g_WG1h[NN * 256 * 128];
__device__ bf16 g_WG1l[NN * 256 * 128];
__device__ bf16 g_WC1h[NN * 256 * 64];
__device__ bf16 g_WC1l[NN * 256 * 64];
__device__ float g_Bg0[NN * 128];
__device__ float g_Bc0[NN * 64];
__device__ float g_Bg1[NN * 128];
__device__ float g_Bc1[NN * 64];
__device__ float g_H[NN * NB];
__device__ float g_R[NN * NB];
__device__ bf16 g_Hhi[NP * NB];
__device__ bf16 g_Hlo[NP * NB];
__device__ bf16 g_ZHhi[NP * NB];
__device__ bf16 g_ZHlo[NP * NB];
__device__ bf16 g_AHhi[NP * NB];
__device__ bf16 g_AHlo[NP * NB];
__device__ bf16 g_AZHhi[NP * NB];
__device__ bf16 g_AZHlo[NP * NB];
__device__ bf16 g_SEQhi[(size_t)NP * NCSEQ];
__device__ bf16 g_SEQlo[(size_t)NP * NCSEQ];
__device__ bf16 g_ASEQhi[(size_t)NP * NCSEQ];
__device__ bf16 g_ASEQlo[(size_t)NP * NCSEQ];

__device__ __forceinline__ void bsplit(float v, bf16& hi, bf16& lo) {
    hi = __float2bfloat16_rn(v);
    lo = __float2bfloat16_rn(v - __bfloat162float(hi));
}
__device__ __forceinline__ unsigned s2u(const void* p) {
    return (unsigned)__cvta_generic_to_shared(p);
}
__device__ __forceinline__ void cp16(void* s, const void* g) {
    asm volatile("cp.async.cg.shared.global [%0], [%1], 16;" :: "r"(s2u(s)), "l"(g));
}
__device__ __forceinline__ void ldsm4(unsigned* r, unsigned a) {
    asm volatile("ldmatrix.sync.aligned.m8n8.x4.shared.b16 {%0,%1,%2,%3}, [%4];"
                 : "=r"(r[0]), "=r"(r[1]), "=r"(r[2]), "=r"(r[3]) : "r"(a));
}
__device__ __forceinline__ void ldsm4t(unsigned* r, unsigned a) {
    asm volatile("ldmatrix.sync.aligned.m8n8.x4.trans.shared.b16 {%0,%1,%2,%3}, [%4];"
                 : "=r"(r[0]), "=r"(r[1]), "=r"(r[2]), "=r"(r[3]) : "r"(a));
}
__device__ __forceinline__ void mma16816(float* c, const unsigned* a, const unsigned* b) {
    asm volatile(
        "mma.sync.aligned.m16n8k16.row.col.f32.bf16.bf16.f32 "
        "{%0,%1,%2,%3},{%4,%5,%6,%7},{%8,%9},{%0,%1,%2,%3};"
        : "+f"(c[0]), "+f"(c[1]), "+f"(c[2]), "+f"(c[3])
        : "r"(a[0]), "r"(a[1]), "r"(a[2]), "r"(a[3]), "r"(b[0]), "r"(b[1]));
}
__device__ __forceinline__ void st2(bf16* p, bf16 a, bf16 b) {
    __nv_bfloat162 v; v.x = a; v.y = b;
    *(__nv_bfloat162*)p = v;
}

// ---------------- adjacency ----------------
__global__ void __launch_bounds__(256) k_supports(const float* __restrict__ E,
                                                  bf16* __restrict__ Ahi,
                                                  bf16* __restrict__ Alo) {
    int n = blockIdx.x, tid = threadIdx.x;
    if (n >= NN) {
        for (int m = tid; m < NP; m += 256) { Ahi[n * NP + m] = __float2bfloat16(0.f); Alo[n * NP + m] = __float2bfloat16(0.f); }
        return;
    }
    __shared__ float row[NN];
    __shared__ float red[8];
    __shared__ float ssum;
    float en[EMBD];
#pragma unroll
    for (int d = 0; d < EMBD; d++) en[d] = E[n * EMBD + d];
    float lmax = -1e30f;
    for (int m = tid; m < NN; m += 256) {
        float s = 0.f;
#pragma unroll
        for (int d = 0; d < EMBD; d++) s = fmaf(en[d], E[m * EMBD + d], s);
        s = fmaxf(s, 0.f);
        row[m] = s;
        lmax = fmaxf(lmax, s);
    }
#pragma unroll
    for (int o = 16; o; o >>= 1) lmax = fmaxf(lmax, __shfl_xor_sync(~0u, lmax, o));
    if ((tid & 31) == 0) red[tid >> 5] = lmax;
    __syncthreads();
    if (tid == 0) { float mx = red[0]; for (int w = 1; w < 8; w++) mx = fmaxf(mx, red[w]); red[0] = mx; }
    __syncthreads();
    float mx = red[0];
    __syncthreads();
    float lsum = 0.f;
    for (int m = tid; m < NN; m += 256) { float e = expf(row[m] - mx); row[m] = e; lsum += e; }
#pragma unroll
    for (int o = 16; o; o >>= 1) lsum += __shfl_xor_sync(~0u, lsum, o);
    if ((tid & 31) == 0) red[tid >> 5] = lsum;
    __syncthreads();
    if (tid == 0) { float s = 0.f; for (int w = 0; w < 8; w++) s += red[w]; ssum = s; }
    __syncthreads();
    float inv = 1.f / ssum;
    for (int m = tid; m < NP; m += 256) {
        float v = (m < NN) ? row[m] * inv : 0.f;
        bf16 h, l; bsplit(v, h, l);
        Ahi[n * NP + m] = h; Alo[n * NP + m] = l;
    }
}

__global__ void k_srcsplit(const float* __restrict__ src, bf16* __restrict__ hi,
                           bf16* __restrict__ lo) {
    int idx = blockIdx.x * 256 + threadIdx.x;
    if (idx >= NP * NC0) return;
    int n = idx / NC0, col = idx % NC0, t = col >> 6, b = col & 63;
    float v = (n < NN) ? src[((size_t)b * TT + t) * NN + n] : 0.f;
    bf16 h, l; bsplit(v, h, l);
    hi[idx] = h; lo[idx] = l;
}

__global__ void k_nodewsplit(const float* __restrict__ E, const float* __restrict__ pool,
                             bf16* __restrict__ Whi, bf16* __restrict__ Wlo,
                             int COUT, int KDp, int layer) {
    long idx = (long)blockIdx.x * 256 + threadIdx.x;
    if (idx >= (long)NN * KDp * COUT) return;
    int o = (int)(idx % COUT);
    long r2 = idx / COUT;
    int k = (int)(r2 % KDp);
    int n = (int)(r2 / KDp);
    int row, ROWS;
    if (layer == 0) {
        ROWS = 130;
        if (k < 64) row = k + 1;
        else if (k < 128) row = k + 2;
        else if (k == 128) row = 0;
        else if (k == 129) row = 65;
        else row = -1;
    } else { ROWS = 256; row = k; }
    float s = 0.f;
    if (row >= 0)
#pragma unroll
        for (int d = 0; d < EMBD; d++)
            s = fmaf(E[n * EMBD + d], pool[((long)d * ROWS + row) * COUT + o], s);
    bf16 h, l; bsplit(s, h, l);
    Whi[idx] = h; Wlo[idx] = l;
}

__global__ void k_nodew(const float* __restrict__ E, const float* __restrict__ pool,
                        float* __restrict__ out, int RC) {
    long idx = (long)blockIdx.x * 256 + threadIdx.x;
    if (idx >= (long)NN * RC) return;
    int n = (int)(idx / RC), rem = (int)(idx % RC);
    float s = 0.f;
#pragma unroll
    for (int d = 0; d < EMBD; d++) s = fmaf(E[n * EMBD + d], pool[(long)d * RC + rem], s);
    out[idx] = s;
}

__global__ void k_zeroH(float* H, bf16* Hhi, bf16* Hlo) {
    int i = blockIdx.x * 256 + threadIdx.x;
    if (i >= NN * NB) return;
    H[i] = 0.f; Hhi[i] = __float2bfloat16(0.f); Hlo[i] = __float2bfloat16(0.f);
}

// ---- dense split-bf16 MMA: C(hi,lo)=A@X. 128x128 tile, BK16, 3-stage, 1 sync
__global__ void __launch_bounds__(256) k_mma(const bf16* __restrict__ Ahi,
                                             const bf16* __restrict__ Alo,
                                             const bf16* __restrict__ Xhi,
                                             const bf16* __restrict__ Xlo,
                                             bf16* __restrict__ Chi,
                                             bf16* __restrict__ Clo, int NCc) {
    extern __shared__ char smem[];
    char* sAh = smem;            // 3 x 4KB
    char* sAl = smem + 12288;    // 3 x 4KB
    char* sXh = smem + 24576;    // 3 x 4KB
    char* sXl = smem + 36864;    // 3 x 4KB
    const int tid = threadIdx.x, lane = tid & 31, warp = tid >> 5;
    const int wm = warp & 1, wn = warp >> 1;
    const int rowBase = blockIdx.y * 128, colBase = blockIdx.x * 128;
    const int ar = tid >> 1, ac = (tid & 1) * 8;
    const int xr = tid >> 4, xcc = tid & 15;
    const int xdst = (xr * 128 + ((xcc ^ xr) & 15) * 8) * 2;  // bytes

    float acc[4][4][4];
#pragma unroll
    for (int i = 0; i < 4; i++)
#pragma unroll
        for (int j = 0; j < 4; j++)
#pragma unroll
            for (int q = 0; q < 4; q++) acc[i][j][q] = 0.f;

    auto prefetch = [&](int kt, int buf) {
        int k0 = kt * 16;
        int adst = buf * 4096 + (ar * 16 + ac) * 2;
        cp16(sAh + adst, Ahi + (size_t)(rowBase + ar) * NP + k0 + ac);
        cp16(sAl + adst, Alo + (size_t)(rowBase + ar) * NP + k0 + ac);
        cp16(sXh + buf * 4096 + xdst, Xhi + (size_t)(k0 + xr) * NCc + colBase + xcc * 8);
        cp16(sXl + buf * 4096 + xdst, Xlo + (size_t)(k0 + xr) * NCc + colBase + xcc * 8);
        asm volatile("cp.async.commit_group;");
    };

    prefetch(0, 0);
    prefetch(1, 1);
    const int aoff = (lane & 15) * 32 + (lane >> 4) * 16;
    const int bk = lane & 15, bch = lane >> 4;
    int buf = 0;
#pragma unroll 1
    for (int kt = 0; kt < 56; ++kt) {
        asm volatile("cp.async.wait_group 1;");
        __syncthreads();
        int nb = buf + 2; if (nb >= 3) nb -= 3;
        if (kt + 2 < 56) prefetch(kt + 2, nb);
        else asm volatile("cp.async.commit_group;");

        unsigned bAh = s2u(sAh) + buf * 4096;
        unsigned bAl = s2u(sAl) + buf * 4096;
        unsigned bXh = s2u(sXh) + buf * 4096;
        unsigned bXl = s2u(sXl) + buf * 4096;
        unsigned ah[4][4], al[4][4], bh[2][4], bl[2][4];
#pragma unroll
        for (int i = 0; i < 4; i++) {
            int m0 = wm * 64 + i * 16;
            ldsm4(ah[i], bAh + m0 * 32 + aoff);
            ldsm4(al[i], bAl + m0 * 32 + aoff);
        }
#pragma unroll
        for (int j = 0; j < 2; j++) {
            int c = wn * 4 + j * 2 + bch;
            int cp = c ^ bk;
            ldsm4t(bh[j], bXh + bk * 256 + cp * 16);
            ldsm4t(bl[j], bXl + bk * 256 + cp * 16);
        }
#pragma unroll
        for (int i = 0; i < 4; i++)
#pragma unroll
            for (int j = 0; j < 2; j++)
#pragma unroll
                for (int h = 0; h < 2; h++) {
                    unsigned bph[2] = {bh[j][h * 2], bh[j][h * 2 + 1]};
                    unsigned bpl[2] = {bl[j][h * 2], bl[j][h * 2 + 1]};
                    float* cc = acc[i][j * 2 + h];
                    mma16816(cc, ah[i], bph);
                    mma16816(cc, ah[i], bpl);
                    mma16816(cc, al[i], bph);
                }
        buf = buf + 1; if (buf == 3) buf = 0;
    }
#pragma unroll
    for (int i = 0; i < 4; i++) {
        int r0 = rowBase + wm * 64 + i * 16 + (lane >> 2);
#pragma unroll
        for (int jn = 0; jn < 4; jn++) {
            int c0 = colBase + wn * 32 + jn * 8 + (lane & 3) * 2;
            bf16 h0, l0, h1, l1;
            bsplit(acc[i][jn][0], h0, l0); bsplit(acc[i][jn][1], h1, l1);
            st2(&Chi[(size_t)r0 * NCc + c0], h0, h1);
            st2(&Clo[(size_t)r0 * NCc + c0], l0, l1);
            bsplit(acc[i][jn][2], h0, l0); bsplit(acc[i][jn][3], h1, l1);
            st2(&Chi[(size_t)(r0 + 8) * NCc + c0], h0, h1);
            st2(&Clo[(size_t)(r0 + 8) * NCc + c0], l0, l1);
        }
    }
}

// ------------ per-node GEMM + fused epilogue, 3-stage, 1 sync/chunk ---------
template <int COUT, bool CAND, bool L0>
__global__ void __launch_bounds__(128) k_pn(
    const bf16* __restrict__ xh, const bf16* __restrict__ xl, size_t xstr, size_t xoff,
    const bf16* __restrict__ hh, const bf16* __restrict__ hl,
    const bf16* __restrict__ axh, const bf16* __restrict__ axl, size_t axstr, size_t axoff,
    const bf16* __restrict__ ahh, const bf16* __restrict__ ahl,
    const bf16* __restrict__ Whi, const bf16* __restrict__ Wlo,
    const float* __restrict__ Bias, float* __restrict__ R, float* __restrict__ Hfp,
    bf16* __restrict__ o1h, bf16* __restrict__ o1l,
    bf16* __restrict__ s1h, bf16* __restrict__ s1l, size_t seqOff) {
    constexpr int NCH = L0 ? 9 : 16;
    constexpr int SLICE = COUT / 4;
    constexpr int NJ = SLICE / 16;
    constexpr int WCH = COUT / 8;
    __shared__ bf16 sXh[3][64 * 24], sXl[3][64 * 24];
    __shared__ bf16 sWh[3][16 * COUT], sWl[3][16 * COUT];
    const int n = blockIdx.x, tid = threadIdx.x, lane = tid & 31, wn = tid >> 5;
    const bf16* Wh = Whi + (size_t)n * NCH * 16 * COUT;
    const bf16* Wl = Wlo + (size_t)n * NCH * 16 * COUT;

    float acc[4][NJ * 2][4];
#pragma unroll
    for (int i = 0; i < 4; i++)
#pragma unroll
        for (int j = 0; j < NJ * 2; j++)
#pragma unroll
            for (int q = 0; q < 4; q++) acc[i][j][q] = 0.f;

    auto prefetch = [&](int c) {
        int buf = c % 3;
#pragma unroll
        for (int q = tid; q < 16 * WCH; q += 128) {
            int r = q / WCH, cc = q % WCH;
            int dst = r * COUT + (cc ^ (r & (WCH - 1))) * 8;
            size_t src = (size_t)(c * 16 + r) * COUT + cc * 8;
            cp16(&sWh[buf][dst], Wh + src);
            cp16(&sWl[buf][dst], Wl + src);
        }
        if (L0 && c == 8) {
            if (tid < 64) {
                int b = tid;
                bf16 z = __float2bfloat16(0.f);
#pragma unroll
                for (int k = 0; k < 16; k++) { sXh[buf][b * 24 + k] = z; sXl[buf][b * 24 + k] = z; }
                sXh[buf][b * 24 + 0] = xh[n * xstr + xoff + b];
                sXl[buf][b * 24 + 0] = xl[n * xstr + xoff + b];
                sXh[buf][b * 24 + 1] = axh[n * axstr + axoff + b];
                sXl[buf][b * 24 + 1] = axl[n * axstr + axoff + b];
            }
        } else {
            int b = tid >> 1, half = tid & 1;
            const bf16 *ph, *pl; size_t base;
            if (L0) {
                if (c < 4) { ph = hh; pl = hl; base = (size_t)n * NB + b * 64 + c * 16 + half * 8; }
                else { ph = ahh; pl = ahl; base = (size_t)n * NB + b * 64 + (c - 4) * 16 + half * 8; }
            } else {
                int g = c >> 2, kl = (c & 3) * 16 + half * 8;
                if (g == 0) { ph = xh; pl = xl; base = (size_t)n * xstr + xoff + b * 64 + kl; }
                else if (g == 1) { ph = hh; pl = hl; base = (size_t)n * NB + b * 64 + kl; }
                else if (g == 2) { ph = axh; pl = axl; base = (size_t)n * axstr + axoff + b * 64 + kl; }
                else { ph = ahh; pl = ahl; base = (size_t)n * NB + b * 64 + kl; }
            }
            cp16(&sXh[buf][b * 24 + half * 8], ph + base);
            cp16(&sXl[buf][b * 24 + half * 8], pl + base);
        }
        asm volatile("cp.async.commit_group;");
    };

    prefetch(0);
    prefetch(1);
#pragma unroll 1
    for (int c = 0; c < NCH; c++) {
        asm volatile("cp.async.wait_group 1;");
        __syncthreads();
        if (c + 2 < NCH) prefetch(c + 2);
        else asm volatile("cp.async.commit_group;");
        int buf = c % 3;
        unsigned bXh = s2u(&sXh[buf][0]);
        unsigned bXl = s2u(&sXl[buf][0]);
        unsigned bWh = s2u(&sWh[buf][0]);
        unsigned bWl = s2u(&sWl[buf][0]);
        unsigned ah[4][4], al[4][4], bh[NJ][4], bl[NJ][4];
#pragma unroll
        for (int i = 0; i < 4; i++) {
            unsigned off = (i * 16 + (lane & 15)) * 48 + (lane >> 4) * 16;
            ldsm4(ah[i], bXh + off);
            ldsm4(al[i], bXl + off);
        }
        int bk = lane & 15;
#pragma unroll
        for (int j = 0; j < NJ; j++) {
            int cch = wn * (SLICE / 8) + j * 2 + (lane >> 4);
            unsigned off = bk * (COUT * 2) + (cch ^ (bk & (WCH - 1))) * 16;
            ldsm4t(bh[j], bWh + off);
            ldsm4t(bl[j], bWl + off);
        }
#pragma unroll
        for (int i = 0; i < 4; i++)
#pragma unroll
            for (int j = 0; j < NJ; j++)
#pragma unroll
                for (int h = 0; h < 2; h++) {
                    unsigned bph[2] = {bh[j][h * 2], bh[j][h * 2 + 1]};
                    unsigned bpl[2] = {bl[j][h * 2], bl[j][h * 2 + 1]};
                    float* cc = acc[i][j * 2 + h];
                    mma16816(cc, ah[i], bph);
                    mma16816(cc, ah[i], bpl);
                    mma16816(cc, al[i], bph);
                }
    }

#pragma unroll
    for (int i = 0; i < 4; i++) {
        int b0 = i * 16 + (lane >> 2);
#pragma unroll
        for (int jn = 0; jn < NJ * 2; jn++) {
            int o = wn * SLICE + jn * 8 + (lane & 3) * 2;
#pragma unroll
            for (int rr = 0; rr < 2; rr++) {
                int b = b0 + rr * 8;
                size_t ix = (size_t)n * NB + b * 64;
                float v0 = acc[i][jn][rr * 2 + 0] + Bias[n * COUT + o];
                float v1 = acc[i][jn][rr * 2 + 1] + Bias[n * COUT + o + 1];
                if (!CAND) {
                    float s0 = 1.f / (1.f + expf(-v0));
                    float s1 = 1.f / (1.f + expf(-v1));
                    if (o < 64) {
                        float z0 = s0 * Hfp[ix + o], z1 = s1 * Hfp[ix + o + 1];
                        bf16 h0, l0, h1, l1;
                        bsplit(z0, h0, l0); bsplit(z1, h1, l1);
                        st2(&o1h[ix + o], h0, h1);
                        st2(&o1l[ix + o], l0, l1);
                    } else {
                        R[ix + o - 64] = s0; R[ix + o - 63] = s1;
                    }
                } else {
                    float hc0 = tanhf(v0), hc1 = tanhf(v1);
                    float r0 = R[ix + o], r1 = R[ix + o + 1];
                    float hn0 = r0 * Hfp[ix + o] + (1.f - r0) * hc0;
                    float hn1 = r1 * Hfp[ix + o + 1] + (1.f - r1) * hc1;
                    Hfp[ix + o] = hn0; Hfp[ix + o + 1] = hn1;
                    bf16 h0, l0, h1, l1;
                    bsplit(hn0, h0, l0); bsplit(hn1, h1, l1);
                    st2(&o1h[ix + o], h0, h1);
                    st2(&o1l[ix + o], l0, l1);
                    if (s1h) {
                        size_t s = (size_t)n * NCSEQ + seqOff + b * 64 + o;
                        st2(&s1h[s], h0, h1);
                        st2(&s1l[s], l0, l1);
                    }
                }
            }
        }
    }
}

__global__ void k_final(const float* __restrict__ H, const float* __restrict__ cw,
                        const float* __restrict__ cb, float* __restrict__ out) {
    int idx = blockIdx.x * 256 + threadIdx.x;
    if (idx >= BB * NN) return;
    int n = idx % NN, b = idx / NN;
    const float* h = H + (size_t)n * NB + b * 64;
    float hv[HID];
#pragma unroll
    for (int j = 0; j < HID; j++) hv[j] = h[j];
#pragma unroll
    for (int o = 0; o < TT; o++) {
        float s = cb[o];
#pragma unroll
        for (int j = 0; j < HID; j++) s = fmaf(hv[j], cw[o * HID + j], s);
        out[((size_t)b * TT + o) * NN + n] = s;
    }
}

extern "C" void kernel_launch(void* const* d_in, const int* in_sizes, int n_in,
                              void* d_out, int out_size) {
    const float* src = (const float*)d_in[0];
    const float* E = (const float*)d_in[1];
    const float* cw = (const float*)d_in[10];
    const float* cb = (const float*)d_in[11];
    float* out = (float*)d_out;

#define SYM(T, v, s) T* v; cudaGetSymbolAddress((void**)&v, s)
    SYM(bf16, Ahi, g_Ahi); SYM(bf16, Alo, g_Alo);
    SYM(bf16, X0hi, g_X0hi); SYM(bf16, X0lo, g_X0lo);
    SYM(bf16, AX0hi, g_AX0hi); SYM(bf16, AX0lo, g_AX0lo);
    SYM(bf16, WG0h, g_WG0h); SYM(bf16, WG0l, g_WG0l);
    SYM(bf16, WC0h, g_WC0h); SYM(bf16, WC0l, g_WC0l);
    SYM(bf16, WG1h, g_WG1h); SYM(bf16, WG1l, g_WG1l);
    SYM(bf16, WC1h, g_WC1h); SYM(bf16, WC1l, g_WC1l);
    SYM(float, Bg0, g_Bg0); SYM(float, Bc0, g_Bc0);
    SYM(float, Bg1, g_Bg1); SYM(float, Bc1, g_Bc1);
    SYM(float, H, g_H); SYM(float, R, g_R);
    SYM(bf16, Hhi, g_Hhi); SYM(bf16, Hlo, g_Hlo);
    SYM(bf16, ZHhi, g_ZHhi); SYM(bf16, ZHlo, g_ZHlo);
    SYM(bf16, AHhi, g_AHhi); SYM(bf16, AHlo, g_AHlo);
    SYM(bf16, AZHhi, g_AZHhi); SYM(bf16, AZHlo, g_AZHlo);
    SYM(bf16, Shi, g_SEQhi); SYM(bf16, Slo, g_SEQlo);
    SYM(bf16, AShi, g_ASEQhi); SYM(bf16, ASlo, g_ASEQlo);

    const int DSM = 49152;
    cudaFuncSetAttribute(k_mma, cudaFuncAttributeMaxDynamicSharedMemorySize, DSM);

    k_supports<<<NP, 256>>>(E, Ahi, Alo);
    k_srcsplit<<<(NP * NC0 + 255) / 256, 256>>>(src, X0hi, X0lo);
    k_nodewsplit<<<(int)(((long)NN * 144 * 128 + 255) / 256), 256>>>(E, (const float*)d_in[2], WG0h, WG0l, 128, 144, 0);
    k_nodew<<<((long)NN * 128 + 255) / 256, 256>>>(E, (const float*)d_in[3], Bg0, 128);
    k_nodewsplit<<<(int)(((long)NN * 144 * 64 + 255) / 256), 256>>>(E, (const float*)d_in[4], WC0h, WC0l, 64, 144, 0);
    k_nodew<<<((long)NN * 64 + 255) / 256, 256>>>(E, (const float*)d_in[5], Bc0, 64);
    k_nodewsplit<<<(int)(((long)NN * 256 * 128 + 255) / 256), 256>>>(E, (const float*)d_in[6], WG1h, WG1l, 128, 256, 1);
    k_nodew<<<((long)NN * 128 + 255) / 256, 256>>>(E, (const float*)d_in[7], Bg1, 128);
    k_nodewsplit<<<(int)(((long)NN * 256 * 64 + 255) / 256), 256>>>(E, (const float*)d_in[8], WC1h, WC1l, 64, 256, 1);
    k_nodew<<<((long)NN * 64 + 255) / 256, 256>>>(E, (const float*)d_in[9], Bc1, 64);

    k_mma<<<dim3(NC0 / 128, 7), 256, DSM>>>(Ahi, Alo, X0hi, X0lo, AX0hi, AX0lo, NC0);

    // layer 0
    k_zeroH<<<(NN * NB + 255) / 256, 256>>>(H, Hhi, Hlo);
    for (int t = 0; t < TT; t++) {
        k_mma<<<dim3(NB / 128, 7), 256, DSM>>>(Ahi, Alo, Hhi, Hlo, AHhi, AHlo, NB);
        k_pn<128, false, true><<<NN, 128>>>(X0hi, X0lo, NC0, (size_t)t * 64,
            Hhi, Hlo, AX0hi, AX0lo, NC0, (size_t)t * 64, AHhi, AHlo,
            WG0h, WG0l, Bg0, R, H, ZHhi, ZHlo, (bf16*)0, (bf16*)0, 0);
        k_mma<<<dim3(NB / 128, 7), 256, DSM>>>(Ahi, Alo, ZHhi, ZHlo, AZHhi, AZHlo, NB);
        k_pn<64, true, true><<<NN, 128>>>(X0hi, X0lo, NC0, (size_t)t * 64,
            ZHhi, ZHlo, AX0hi, AX0lo, NC0, (size_t)t * 64, AZHhi, AZHlo,
            WC0h, WC0l, Bc0, R, H, Hhi, Hlo, Shi, Slo, (size_t)t * NB);
    }

    k_mma<<<dim3(NCSEQ / 128, 7), 256, DSM>>>(Ahi, Alo, Shi, Slo, AShi, ASlo, NCSEQ);

    // layer 1
    k_zeroH<<<(NN * NB + 255) / 256, 256>>>(H, Hhi, Hlo);
    for (int t = 0; t < TT; t++) {
        k_mma<<<dim3(NB / 128, 7), 256, DSM>>>(Ahi, Alo, Hhi, Hlo, AHhi, AHlo, NB);
        k_pn<128, false, false><<<NN, 128>>>(Shi, Slo, NCSEQ, (size_t)t * NB,
            Hhi, Hlo, AShi, ASlo, NCSEQ, (size_t)t * NB, AHhi, AHlo,
            WG1h, WG1l, Bg1, R, H, ZHhi, ZHlo, (bf16*)0, (bf16*)0, 0);
        k_mma<<<dim3(NB / 128, 7), 256, DSM>>>(Ahi, Alo, ZHhi, ZHlo, AZHhi, AZHlo, NB);
        k_pn<64, true, false><<<NN, 128>>>(Shi, Slo, NCSEQ, (size_t)t * NB,
            ZHhi, ZHlo, AShi, ASlo, NCSEQ, (size_t)t * NB, AZHhi, AZHlo,
            WC1h, WC1l, Bc1, R, H, Hhi, Hlo, (bf16*)0, (bf16*)0, 0);
    }

    k_final<<<(BB * NN + 255) / 256, 256>>>(H, cw, cb, out);
}

// round 8
// speedup vs baseline: 1.1375x; 1.1375x over previous
#include <cuda_runtime.h>
#include <cuda_bf16.h>
#include <math.h>
#include <stdint.h>

#define NN 883
#define NP 896
#define BB 64
#define TT 12
#define HID 64
#define EMBD 10
#define NB 4096
#define NCSEQ 49152
#define NC0 768
typedef __nv_bfloat16 bf16;

__device__ bf16 g_Ahi[NP * NP];
__device__ bf16 g_Alo[NP * NP];
__device__ bf16 g_X0hi[NP * NC0];
__device__ bf16 g_X0lo[NP * NC0];
__device__ bf16 g_AX0hi[NP * NC0];
__device__ bf16 g_AX0lo[NP * NC0];
__device__ bf16 g_WG0h[NN * 144 * 128];
__device__ bf16 g_WG0l[NN * 144 * 128];
__device__ bf16 g_WC0h[NN * 144 * 64];
__device__ bf16 g_WC0l[NN * 144 * 64];
__device__ bf16 g_WG1h[NN * 256 * 128];
__device__ bf16 g_WG1l[NN * 256 * 128];
__device__ bf16 g_WC1h[NN * 256 * 64];
__device__ bf16 g_WC1l[NN * 256 * 64];
__device__ float g_Bg0[NN * 128];
__device__ float g_Bc0[NN * 64];
__device__ float g_Bg1[NN * 128];
__device__ float g_Bc1[NN * 64];
__device__ float g_H[NN * NB];
__device__ float g_R[NN * NB];
__device__ bf16 g_Hhi[NP * NB];
__device__ bf16 g_Hlo[NP * NB];
__device__ bf16 g_ZHhi[NP * NB];
__device__ bf16 g_ZHlo[NP * NB];
__device__ bf16 g_AHhi[NP * NB];
__device__ bf16 g_AHlo[NP * NB];
__device__ bf16 g_AZHhi[NP * NB];
__device__ bf16 g_AZHlo[NP * NB];
__device__ bf16 g_SEQhi[(size_t)NP * NCSEQ];
__device__ bf16 g_SEQlo[(size_t)NP * NCSEQ];
__device__ bf16 g_ASEQhi[(size_t)NP * NCSEQ];
__device__ bf16 g_ASEQlo[(size_t)NP * NCSEQ];

__device__ __forceinline__ void bsplit(float v, bf16& hi, bf16& lo) {
    hi = __float2bfloat16_rn(v);
    lo = __float2bfloat16_rn(v - __bfloat162float(hi));
}
__device__ __forceinline__ unsigned s2u(const void* p) {
    return (unsigned)__cvta_generic_to_shared(p);
}
__device__ __forceinline__ void cp16(void* s, const void* g) {
    asm volatile("cp.async.cg.shared.global [%0], [%1], 16;" :: "r"(s2u(s)), "l"(g));
}
__device__ __forceinline__ void ldsm4(unsigned* r, unsigned a) {
    asm volatile("ldmatrix.sync.aligned.m8n8.x4.shared.b16 {%0,%1,%2,%3}, [%4];"
                 : "=r"(r[0]), "=r"(r[1]), "=r"(r[2]), "=r"(r[3]) : "r"(a));
}
__device__ __forceinline__ void ldsm4t(unsigned* r, unsigned a) {
    asm volatile("ldmatrix.sync.aligned.m8n8.x4.trans.shared.b16 {%0,%1,%2,%3}, [%4];"
                 : "=r"(r[0]), "=r"(r[1]), "=r"(r[2]), "=r"(r[3]) : "r"(a));
}
__device__ __forceinline__ void mma16816(float* c, const unsigned* a, const unsigned* b) {
    asm volatile(
        "mma.sync.aligned.m16n8k16.row.col.f32.bf16.bf16.f32 "
        "{%0,%1,%2,%3},{%4,%5,%6,%7},{%8,%9},{%0,%1,%2,%3};"
        : "+f"(c[0]), "+f"(c[1]), "+f"(c[2]), "+f"(c[3])
        : "r"(a[0]), "r"(a[1]), "r"(a[2]), "r"(a[3]), "r"(b[0]), "r"(b[1]));
}
__device__ __forceinline__ void st2(bf16* p, bf16 a, bf16 b) {
    __nv_bfloat162 v; v.x = a; v.y = b;
    *(__nv_bfloat162*)p = v;
}

// ---------------- adjacency ----------------
__global__ void __launch_bounds__(256) k_supports(const float* __restrict__ E,
                                                  bf16* __restrict__ Ahi,
                                                  bf16* __restrict__ Alo) {
    int n = blockIdx.x, tid = threadIdx.x;
    if (n >= NN) {
        for (int m = tid; m < NP; m += 256) { Ahi[n * NP + m] = __float2bfloat16(0.f); Alo[n * NP + m] = __float2bfloat16(0.f); }
        return;
    }
    __shared__ float row[NN];
    __shared__ float red[8];
    __shared__ float ssum;
    float en[EMBD];
#pragma unroll
    for (int d = 0; d < EMBD; d++) en[d] = E[n * EMBD + d];
    float lmax = -1e30f;
    for (int m = tid; m < NN; m += 256) {
        float s = 0.f;
#pragma unroll
        for (int d = 0; d < EMBD; d++) s = fmaf(en[d], E[m * EMBD + d], s);
        s = fmaxf(s, 0.f);
        row[m] = s;
        lmax = fmaxf(lmax, s);
    }
#pragma unroll
    for (int o = 16; o; o >>= 1) lmax = fmaxf(lmax, __shfl_xor_sync(~0u, lmax, o));
    if ((tid & 31) == 0) red[tid >> 5] = lmax;
    __syncthreads();
    if (tid == 0) { float mx = red[0]; for (int w = 1; w < 8; w++) mx = fmaxf(mx, red[w]); red[0] = mx; }
    __syncthreads();
    float mx = red[0];
    __syncthreads();
    float lsum = 0.f;
    for (int m = tid; m < NN; m += 256) { float e = expf(row[m] - mx); row[m] = e; lsum += e; }
#pragma unroll
    for (int o = 16; o; o >>= 1) lsum += __shfl_xor_sync(~0u, lsum, o);
    if ((tid & 31) == 0) red[tid >> 5] = lsum;
    __syncthreads();
    if (tid == 0) { float s = 0.f; for (int w = 0; w < 8; w++) s += red[w]; ssum = s; }
    __syncthreads();
    float inv = 1.f / ssum;
    for (int m = tid; m < NP; m += 256) {
        float v = (m < NN) ? row[m] * inv : 0.f;
        bf16 h, l; bsplit(v, h, l);
        Ahi[n * NP + m] = h; Alo[n * NP + m] = l;
    }
}

__global__ void k_srcsplit(const float* __restrict__ src, bf16* __restrict__ hi,
                           bf16* __restrict__ lo) {
    int idx = blockIdx.x * 256 + threadIdx.x;
    if (idx >= NP * NC0) return;
    int n = idx / NC0, col = idx % NC0, t = col >> 6, b = col & 63;
    float v = (n < NN) ? src[((size_t)b * TT + t) * NN + n] : 0.f;
    bf16 h, l; bsplit(v, h, l);
    hi[idx] = h; lo[idx] = l;
}

__global__ void k_nodewsplit(const float* __restrict__ E, const float* __restrict__ pool,
                             bf16* __restrict__ Whi, bf16* __restrict__ Wlo,
                             int COUT, int KDp, int layer) {
    long idx = (long)blockIdx.x * 256 + threadIdx.x;
    if (idx >= (long)NN * KDp * COUT) return;
    int o = (int)(idx % COUT);
    long r2 = idx / COUT;
    int k = (int)(r2 % KDp);
    int n = (int)(r2 / KDp);
    int row, ROWS;
    if (layer == 0) {
        ROWS = 130;
        if (k < 64) row = k + 1;
        else if (k < 128) row = k + 2;
        else if (k == 128) row = 0;
        else if (k == 129) row = 65;
        else row = -1;
    } else { ROWS = 256; row = k; }
    float s = 0.f;
    if (row >= 0)
#pragma unroll
        for (int d = 0; d < EMBD; d++)
            s = fmaf(E[n * EMBD + d], pool[((long)d * ROWS + row) * COUT + o], s);
    bf16 h, l; bsplit(s, h, l);
    Whi[idx] = h; Wlo[idx] = l;
}

__global__ void k_nodew(const float* __restrict__ E, const float* __restrict__ pool,
                        float* __restrict__ out, int RC) {
    long idx = (long)blockIdx.x * 256 + threadIdx.x;
    if (idx >= (long)NN * RC) return;
    int n = (int)(idx / RC), rem = (int)(idx % RC);
    float s = 0.f;
#pragma unroll
    for (int d = 0; d < EMBD; d++) s = fmaf(E[n * EMBD + d], pool[(long)d * RC + rem], s);
    out[idx] = s;
}

__global__ void k_zeroH(float* H, bf16* Hhi, bf16* Hlo) {
    int i = blockIdx.x * 256 + threadIdx.x;
    if (i >= NN * NB) return;
    H[i] = 0.f; Hhi[i] = __float2bfloat16(0.f); Hlo[i] = __float2bfloat16(0.f);
}

// -- dense split-bf16 MMA: C(hi,lo)=A@X. 64x128 tile, BK16, 128 thr, 2-stage --
__global__ void __launch_bounds__(128) k_mma(const bf16* __restrict__ Ahi,
                                             const bf16* __restrict__ Alo,
                                             const bf16* __restrict__ Xhi,
                                             const bf16* __restrict__ Xlo,
                                             bf16* __restrict__ Chi,
                                             bf16* __restrict__ Clo, int NCc) {
    __shared__ bf16 sAh[2][64 * 16], sAl[2][64 * 16];
    __shared__ bf16 sXh[2][16 * 128], sXl[2][16 * 128];
    const int tid = threadIdx.x, lane = tid & 31, warp = tid >> 5;
    const int rowBase = blockIdx.y * 64, colBase = blockIdx.x * 128;
    const int ar = tid >> 1, ac = (tid & 1) * 8;

    float acc[4][4][4];
#pragma unroll
    for (int i = 0; i < 4; i++)
#pragma unroll
        for (int j = 0; j < 4; j++)
#pragma unroll
            for (int q = 0; q < 4; q++) acc[i][j][q] = 0.f;

    auto prefetch = [&](int kt, int buf) {
        int k0 = kt * 16;
        cp16(&sAh[buf][ar * 16 + ac], Ahi + (size_t)(rowBase + ar) * NP + k0 + ac);
        cp16(&sAl[buf][ar * 16 + ac], Alo + (size_t)(rowBase + ar) * NP + k0 + ac);
#pragma unroll
        for (int i = 0; i < 2; i++) {
            int idx = tid + i * 128;
            int r = idx >> 4, cc = idx & 15;
            int dst = r * 128 + ((cc ^ r) & 15) * 8;
            cp16(&sXh[buf][dst], Xhi + (size_t)(k0 + r) * NCc + colBase + cc * 8);
            cp16(&sXl[buf][dst], Xlo + (size_t)(k0 + r) * NCc + colBase + cc * 8);
        }
        asm volatile("cp.async.commit_group;");
    };

    prefetch(0, 0);
    const int aoff = (lane & 15) * 32 + (lane >> 4) * 16;
    const int bk = lane & 15, bch = lane >> 4;

#pragma unroll 1
    for (int kt = 0; kt < 56; ++kt) {
        if (kt < 55) {
            prefetch(kt + 1, (kt + 1) & 1);
            asm volatile("cp.async.wait_group 1;");
        } else {
            asm volatile("cp.async.wait_group 0;");
        }
        __syncthreads();
        int buf = kt & 1;
        unsigned bAh = s2u(&sAh[buf][0]);
        unsigned bAl = s2u(&sAl[buf][0]);
        unsigned bXh = s2u(&sXh[buf][0]);
        unsigned bXl = s2u(&sXl[buf][0]);
        unsigned ah[4][4], al[4][4], bh[2][4], bl[2][4];
#pragma unroll
        for (int i = 0; i < 4; i++) {
            ldsm4(ah[i], bAh + i * 512 + aoff);
            ldsm4(al[i], bAl + i * 512 + aoff);
        }
#pragma unroll
        for (int j = 0; j < 2; j++) {
            int c = warp * 4 + j * 2 + bch;
            int cp = c ^ bk;
            ldsm4t(bh[j], bXh + bk * 256 + cp * 16);
            ldsm4t(bl[j], bXl + bk * 256 + cp * 16);
        }
#pragma unroll
        for (int i = 0; i < 4; i++)
#pragma unroll
            for (int j = 0; j < 2; j++)
#pragma unroll
                for (int h = 0; h < 2; h++) {
                    unsigned bph[2] = {bh[j][h * 2], bh[j][h * 2 + 1]};
                    unsigned bpl[2] = {bl[j][h * 2], bl[j][h * 2 + 1]};
                    float* cc = acc[i][j * 2 + h];
                    mma16816(cc, ah[i], bph);
                    mma16816(cc, ah[i], bpl);
                    mma16816(cc, al[i], bph);
                }
        __syncthreads();
    }
#pragma unroll
    for (int i = 0; i < 4; i++) {
        int r0 = rowBase + i * 16 + (lane >> 2);
#pragma unroll
        for (int jn = 0; jn < 4; jn++) {
            int c0 = colBase + warp * 32 + jn * 8 + (lane & 3) * 2;
            bf16 h0, l0, h1, l1;
            bsplit(acc[i][jn][0], h0, l0); bsplit(acc[i][jn][1], h1, l1);
            st2(&Chi[(size_t)r0 * NCc + c0], h0, h1);
            st2(&Clo[(size_t)r0 * NCc + c0], l0, l1);
            bsplit(acc[i][jn][2], h0, l0); bsplit(acc[i][jn][3], h1, l1);
            st2(&Chi[(size_t)(r0 + 8) * NCc + c0], h0, h1);
            st2(&Clo[(size_t)(r0 + 8) * NCc + c0], l0, l1);
        }
    }
}

// ---------------- per-node tensor-core GEMM + fused epilogue (R4) ------------
template <int COUT, bool CAND, bool L0>
__global__ void __launch_bounds__(128) k_pn(
    const bf16* __restrict__ xh, const bf16* __restrict__ xl, size_t xstr, size_t xoff,
    const bf16* __restrict__ hh, const bf16* __restrict__ hl,
    const bf16* __restrict__ axh, const bf16* __restrict__ axl, size_t axstr, size_t axoff,
    const bf16* __restrict__ ahh, const bf16* __restrict__ ahl,
    const bf16* __restrict__ Whi, const bf16* __restrict__ Wlo,
    const float* __restrict__ Bias, float* __restrict__ R, float* __restrict__ Hfp,
    bf16* __restrict__ o1h, bf16* __restrict__ o1l,
    bf16* __restrict__ s1h, bf16* __restrict__ s1l, size_t seqOff) {
    constexpr int NCH = L0 ? 9 : 16;
    constexpr int SLICE = COUT / 4;
    constexpr int NJ = SLICE / 16;
    constexpr int WCH = COUT / 8;
    __shared__ bf16 sXh[2][64 * 24], sXl[2][64 * 24];
    __shared__ bf16 sWh[2][16 * COUT], sWl[2][16 * COUT];
    const int n = blockIdx.x, tid = threadIdx.x, lane = tid & 31, wn = tid >> 5;
    const bf16* Wh = Whi + (size_t)n * NCH * 16 * COUT;
    const bf16* Wl = Wlo + (size_t)n * NCH * 16 * COUT;

    float acc[4][NJ * 2][4];
#pragma unroll
    for (int i = 0; i < 4; i++)
#pragma unroll
        for (int j = 0; j < NJ * 2; j++)
#pragma unroll
            for (int q = 0; q < 4; q++) acc[i][j][q] = 0.f;

    auto prefetch = [&](int c) {
        int buf = c & 1;
#pragma unroll
        for (int q = tid; q < 16 * WCH; q += 128) {
            int r = q / WCH, cc = q % WCH;
            int dst = r * COUT + (cc ^ (r & (WCH - 1))) * 8;
            size_t src = (size_t)(c * 16 + r) * COUT + cc * 8;
            cp16(&sWh[buf][dst], Wh + src);
            cp16(&sWl[buf][dst], Wl + src);
        }
        if (L0 && c == 8) {
            if (tid < 64) {
                int b = tid;
                bf16 z = __float2bfloat16(0.f);
#pragma unroll
                for (int k = 0; k < 16; k++) { sXh[buf][b * 24 + k] = z; sXl[buf][b * 24 + k] = z; }
                sXh[buf][b * 24 + 0] = xh[n * xstr + xoff + b];
                sXl[buf][b * 24 + 0] = xl[n * xstr + xoff + b];
                sXh[buf][b * 24 + 1] = axh[n * axstr + axoff + b];
                sXl[buf][b * 24 + 1] = axl[n * axstr + axoff + b];
            }
        } else {
            int b = tid >> 1, half = tid & 1;
            const bf16 *ph, *pl; size_t base;
            if (L0) {
                if (c < 4) { ph = hh; pl = hl; base = (size_t)n * NB + b * 64 + c * 16 + half * 8; }
                else { ph = ahh; pl = ahl; base = (size_t)n * NB + b * 64 + (c - 4) * 16 + half * 8; }
            } else {
                int g = c >> 2, kl = (c & 3) * 16 + half * 8;
                if (g == 0) { ph = xh; pl = xl; base = (size_t)n * xstr + xoff + b * 64 + kl; }
                else if (g == 1) { ph = hh; pl = hl; base = (size_t)n * NB + b * 64 + kl; }
                else if (g == 2) { ph = axh; pl = axl; base = (size_t)n * axstr + axoff + b * 64 + kl; }
                else { ph = ahh; pl = ahl; base = (size_t)n * NB + b * 64 + kl; }
            }
            cp16(&sXh[buf][b * 24 + half * 8], ph + base);
            cp16(&sXl[buf][b * 24 + half * 8], pl + base);
        }
        asm volatile("cp.async.commit_group;");
    };

    prefetch(0);
#pragma unroll 1
    for (int c = 0; c < NCH; c++) {
        if (c + 1 < NCH) { prefetch(c + 1); asm volatile("cp.async.wait_group 1;"); }
        else asm volatile("cp.async.wait_group 0;");
        __syncthreads();
        int buf = c & 1;
        unsigned bXh = s2u(&sXh[buf][0]);
        unsigned bXl = s2u(&sXl[buf][0]);
        unsigned bWh = s2u(&sWh[buf][0]);
        unsigned bWl = s2u(&sWl[buf][0]);
        unsigned ah[4][4], al[4][4], bh[NJ][4], bl[NJ][4];
#pragma unroll
        for (int i = 0; i < 4; i++) {
            unsigned off = (i * 16 + (lane & 15)) * 48 + (lane >> 4) * 16;
            ldsm4(ah[i], bXh + off);
            ldsm4(al[i], bXl + off);
        }
        int bk = lane & 15;
#pragma unroll
        for (int j = 0; j < NJ; j++) {
            int cch = wn * (SLICE / 8) + j * 2 + (lane >> 4);
            unsigned off = bk * (COUT * 2) + (cch ^ (bk & (WCH - 1))) * 16;
            ldsm4t(bh[j], bWh + off);
            ldsm4t(bl[j], bWl + off);
        }
#pragma unroll
        for (int i = 0; i < 4; i++)
#pragma unroll
            for (int j = 0; j < NJ; j++)
#pragma unroll
                for (int h = 0; h < 2; h++) {
                    unsigned bph[2] = {bh[j][h * 2], bh[j][h * 2 + 1]};
                    unsigned bpl[2] = {bl[j][h * 2], bl[j][h * 2 + 1]};
                    float* cc = acc[i][j * 2 + h];
                    mma16816(cc, ah[i], bph);
                    mma16816(cc, ah[i], bpl);
                    mma16816(cc, al[i], bph);
                }
        __syncthreads();
    }

#pragma unroll
    for (int i = 0; i < 4; i++) {
        int b0 = i * 16 + (lane >> 2);
#pragma unroll
        for (int jn = 0; jn < NJ * 2; jn++) {
            int o = wn * SLICE + jn * 8 + (lane & 3) * 2;
#pragma unroll
            for (int rr = 0; rr < 2; rr++) {
                int b = b0 + rr * 8;
                size_t ix = (size_t)n * NB + b * 64;
                float v0 = acc[i][jn][rr * 2 + 0] + Bias[n * COUT + o];
                float v1 = acc[i][jn][rr * 2 + 1] + Bias[n * COUT + o + 1];
                if (!CAND) {
                    float s0 = 1.f / (1.f + expf(-v0));
                    float s1 = 1.f / (1.f + expf(-v1));
                    if (o < 64) {
                        float z0 = s0 * Hfp[ix + o], z1 = s1 * Hfp[ix + o + 1];
                        bf16 h0, l0, h1, l1;
                        bsplit(z0, h0, l0); bsplit(z1, h1, l1);
                        st2(&o1h[ix + o], h0, h1);
                        st2(&o1l[ix + o], l0, l1);
                    } else {
                        R[ix + o - 64] = s0; R[ix + o - 63] = s1;
                    }
                } else {
                    float hc0 = tanhf(v0), hc1 = tanhf(v1);
                    float r0 = R[ix + o], r1 = R[ix + o + 1];
                    float hn0 = r0 * Hfp[ix + o] + (1.f - r0) * hc0;
                    float hn1 = r1 * Hfp[ix + o + 1] + (1.f - r1) * hc1;
                    Hfp[ix + o] = hn0; Hfp[ix + o + 1] = hn1;
                    bf16 h0, l0, h1, l1;
                    bsplit(hn0, h0, l0); bsplit(hn1, h1, l1);
                    st2(&o1h[ix + o], h0, h1);
                    st2(&o1l[ix + o], l0, l1);
                    if (s1h) {
                        size_t s = (size_t)n * NCSEQ + seqOff + b * 64 + o;
                        st2(&s1h[s], h0, h1);
                        st2(&s1l[s], l0, l1);
                    }
                }
            }
        }
    }
}

__global__ void k_final(const float* __restrict__ H, const float* __restrict__ cw,
                        const float* __restrict__ cb, float* __restrict__ out) {
    int idx = blockIdx.x * 256 + threadIdx.x;
    if (idx >= BB * NN) return;
    int n = idx % NN, b = idx / NN;
    const float* h = H + (size_t)n * NB + b * 64;
    float hv[HID];
#pragma unroll
    for (int j = 0; j < HID; j++) hv[j] = h[j];
#pragma unroll
    for (int o = 0; o < TT; o++) {
        float s = cb[o];
#pragma unroll
        for (int j = 0; j < HID; j++) s = fmaf(hv[j], cw[o * HID + j], s);
        out[((size_t)b * TT + o) * NN + n] = s;
    }
}

extern "C" void kernel_launch(void* const* d_in, const int* in_sizes, int n_in,
                              void* d_out, int out_size) {
    const float* src = (const float*)d_in[0];
    const float* E = (const float*)d_in[1];
    const float* cw = (const float*)d_in[10];
    const float* cb = (const float*)d_in[11];
    float* out = (float*)d_out;

#define SYM(T, v, s) T* v; cudaGetSymbolAddress((void**)&v, s)
    SYM(bf16, Ahi, g_Ahi); SYM(bf16, Alo, g_Alo);
    SYM(bf16, X0hi, g_X0hi); SYM(bf16, X0lo, g_X0lo);
    SYM(bf16, AX0hi, g_AX0hi); SYM(bf16, AX0lo, g_AX0lo);
    SYM(bf16, WG0h, g_WG0h); SYM(bf16, WG0l, g_WG0l);
    SYM(bf16, WC0h, g_WC0h); SYM(bf16, WC0l, g_WC0l);
    SYM(bf16, WG1h, g_WG1h); SYM(bf16, WG1l, g_WG1l);
    SYM(bf16, WC1h, g_WC1h); SYM(bf16, WC1l, g_WC1l);
    SYM(float, Bg0, g_Bg0); SYM(float, Bc0, g_Bc0);
    SYM(float, Bg1, g_Bg1); SYM(float, Bc1, g_Bc1);
    SYM(float, H, g_H); SYM(float, R, g_R);
    SYM(bf16, Hhi, g_Hhi); SYM(bf16, Hlo, g_Hlo);
    SYM(bf16, ZHhi, g_ZHhi); SYM(bf16, ZHlo, g_ZHlo);
    SYM(bf16, AHhi, g_AHhi); SYM(bf16, AHlo, g_AHlo);
    SYM(bf16, AZHhi, g_AZHhi); SYM(bf16, AZHlo, g_AZHlo);
    SYM(bf16, Shi, g_SEQhi); SYM(bf16, Slo, g_SEQlo);
    SYM(bf16, AShi, g_ASEQhi); SYM(bf16, ASlo, g_ASEQlo);

    k_supports<<<NP, 256>>>(E, Ahi, Alo);
    k_srcsplit<<<(NP * NC0 + 255) / 256, 256>>>(src, X0hi, X0lo);
    k_nodewsplit<<<(int)(((long)NN * 144 * 128 + 255) / 256), 256>>>(E, (const float*)d_in[2], WG0h, WG0l, 128, 144, 0);
    k_nodew<<<((long)NN * 128 + 255) / 256, 256>>>(E, (const float*)d_in[3], Bg0, 128);
    k_nodewsplit<<<(int)(((long)NN * 144 * 64 + 255) / 256), 256>>>(E, (const float*)d_in[4], WC0h, WC0l, 64, 144, 0);
    k_nodew<<<((long)NN * 64 + 255) / 256, 256>>>(E, (const float*)d_in[5], Bc0, 64);
    k_nodewsplit<<<(int)(((long)NN * 256 * 128 + 255) / 256), 256>>>(E, (const float*)d_in[6], WG1h, WG1l, 128, 256, 1);
    k_nodew<<<((long)NN * 128 + 255) / 256, 256>>>(E, (const float*)d_in[7], Bg1, 128);
    k_nodewsplit<<<(int)(((long)NN * 256 * 64 + 255) / 256), 256>>>(E, (const float*)d_in[8], WC1h, WC1l, 64, 256, 1);
    k_nodew<<<((long)NN * 64 + 255) / 256, 256>>>(E, (const float*)d_in[9], Bc1, 64);

    k_mma<<<dim3(NC0 / 128, 14), 128>>>(Ahi, Alo, X0hi, X0lo, AX0hi, AX0lo, NC0);

    // layer 0
    k_zeroH<<<(NN * NB + 255) / 256, 256>>>(H, Hhi, Hlo);
    for (int t = 0; t < TT; t++) {
        k_mma<<<dim3(NB / 128, 14), 128>>>(Ahi, Alo, Hhi, Hlo, AHhi, AHlo, NB);
        k_pn<128, false, true><<<NN, 128>>>(X0hi, X0lo, NC0, (size_t)t * 64,
            Hhi, Hlo, AX0hi, AX0lo, NC0, (size_t)t * 64, AHhi, AHlo,
            WG0h, WG0l, Bg0, R, H, ZHhi, ZHlo, (bf16*)0, (bf16*)0, 0);
        k_mma<<<dim3(NB / 128, 14), 128>>>(Ahi, Alo, ZHhi, ZHlo, AZHhi, AZHlo, NB);
        k_pn<64, true, true><<<NN, 128>>>(X0hi, X0lo, NC0, (size_t)t * 64,
            ZHhi, ZHlo, AX0hi, AX0lo, NC0, (size_t)t * 64, AZHhi, AZHlo,
            WC0h, WC0l, Bc0, R, H, Hhi, Hlo, Shi, Slo, (size_t)t * NB);
    }

    k_mma<<<dim3(NCSEQ / 128, 14), 128>>>(Ahi, Alo, Shi, Slo, AShi, ASlo, NCSEQ);

    // layer 1
    k_zeroH<<<(NN * NB + 255) / 256, 256>>>(H, Hhi, Hlo);
    for (int t = 0; t < TT; t++) {
        k_mma<<<dim3(NB / 128, 14), 128>>>(Ahi, Alo, Hhi, Hlo, AHhi, AHlo, NB);
        k_pn<128, false, false><<<NN, 128>>>(Shi, Slo, NCSEQ, (size_t)t * NB,
            Hhi, Hlo, AShi, ASlo, NCSEQ, (size_t)t * NB, AHhi, AHlo,
            WG1h, WG1l, Bg1, R, H, ZHhi, ZHlo, (bf16*)0, (bf16*)0, 0);
        k_mma<<<dim3(NB / 128, 14), 128>>>(Ahi, Alo, ZHhi, ZHlo, AZHhi, AZHlo, NB);
        k_pn<64, true, false><<<NN, 128>>>(Shi, Slo, NCSEQ, (size_t)t * NB,
            ZHhi, ZHlo, AShi, ASlo, NCSEQ, (size_t)t * NB, AZHhi, AZHlo,
            WC1h, WC1l, Bc1, R, H, Hhi, Hlo, (bf16*)0, (bf16*)0, 0);
    }

    k_final<<<(BB * NN + 255) / 256, 256>>>(H, cw, cb, out);
}

// round 9
// speedup vs baseline: 1.2085x; 1.0624x over previous
#include <cuda_runtime.h>
#include <cuda_bf16.h>
#include <math.h>
#include <stdint.h>

#define NN 883
#define NP 896
#define BB 64
#define TT 12
#define HID 64
#define EMBD 10
#define NB 4096
#define NCSEQ 49152
#define NC0 768
typedef __nv_bfloat16 bf16;

__device__ bf16 g_Ahi[NP * NP];
__device__ bf16 g_Alo[NP * NP];
__device__ bf16 g_X0hi[NP * NC0];
__device__ bf16 g_X0lo[NP * NC0];
__device__ bf16 g_AX0hi[NP * NC0];
__device__ bf16 g_AX0lo[NP * NC0];
__device__ bf16 g_WG0h[NN * 144 * 128];
__device__ bf16 g_WG0l[NN * 144 * 128];
__device__ bf16 g_WC0h[NN * 144 * 64];
__device__ bf16 g_WC0l[NN * 144 * 64];
__device__ bf16 g_WG1h[NN * 256 * 128];
__device__ bf16 g_WG1l[NN * 256 * 128];
__device__ bf16 g_WC1h[NN * 256 * 64];
__device__ bf16 g_WC1l[NN * 256 * 64];
__device__ float g_Bg0[NN * 128];
__device__ float g_Bc0[NN * 64];
__device__ float g_Bg1[NN * 128];
__device__ float g_Bc1[NN * 64];
__device__ float g_H[NN * NB];
__device__ float g_R[NN * NB];
__device__ bf16 g_Hhi[NP * NB];
__device__ bf16 g_Hlo[NP * NB];
__device__ bf16 g_ZHhi[NP * NB];
__device__ bf16 g_ZHlo[NP * NB];
__device__ bf16 g_AHhi[NP * NB];
__device__ bf16 g_AHlo[NP * NB];
__device__ bf16 g_AZHhi[NP * NB];
__device__ bf16 g_AZHlo[NP * NB];
__device__ bf16 g_SEQhi[(size_t)NP * NCSEQ];
__device__ bf16 g_SEQlo[(size_t)NP * NCSEQ];
__device__ bf16 g_ASEQhi[(size_t)NP * NCSEQ];
__device__ bf16 g_ASEQlo[(size_t)NP * NCSEQ];

__device__ __forceinline__ void bsplit(float v, bf16& hi, bf16& lo) {
    hi = __float2bfloat16_rn(v);
    lo = __float2bfloat16_rn(v - __bfloat162float(hi));
}
__device__ __forceinline__ unsigned s2u(const void* p) {
    return (unsigned)__cvta_generic_to_shared(p);
}
__device__ __forceinline__ void cp16(void* s, const void* g) {
    asm volatile("cp.async.cg.shared.global [%0], [%1], 16;" :: "r"(s2u(s)), "l"(g));
}
__device__ __forceinline__ void ldsm4(unsigned* r, unsigned a) {
    asm volatile("ldmatrix.sync.aligned.m8n8.x4.shared.b16 {%0,%1,%2,%3}, [%4];"
                 : "=r"(r[0]), "=r"(r[1]), "=r"(r[2]), "=r"(r[3]) : "r"(a));
}
__device__ __forceinline__ void ldsm4t(unsigned* r, unsigned a) {
    asm volatile("ldmatrix.sync.aligned.m8n8.x4.trans.shared.b16 {%0,%1,%2,%3}, [%4];"
                 : "=r"(r[0]), "=r"(r[1]), "=r"(r[2]), "=r"(r[3]) : "r"(a));
}
__device__ __forceinline__ void mma16816(float* c, const unsigned* a, const unsigned* b) {
    asm volatile(
        "mma.sync.aligned.m16n8k16.row.col.f32.bf16.bf16.f32 "
        "{%0,%1,%2,%3},{%4,%5,%6,%7},{%8,%9},{%0,%1,%2,%3};"
        : "+f"(c[0]), "+f"(c[1]), "+f"(c[2]), "+f"(c[3])
        : "r"(a[0]), "r"(a[1]), "r"(a[2]), "r"(a[3]), "r"(b[0]), "r"(b[1]));
}
__device__ __forceinline__ void st2(bf16* p, bf16 a, bf16 b) {
    __nv_bfloat162 v; v.x = a; v.y = b;
    *(__nv_bfloat162*)p = v;
}

// ---------------- adjacency ----------------
__global__ void __launch_bounds__(256) k_supports(const float* __restrict__ E,
                                                  bf16* __restrict__ Ahi,
                                                  bf16* __restrict__ Alo) {
    int n = blockIdx.x, tid = threadIdx.x;
    if (n >= NN) {
        for (int m = tid; m < NP; m += 256) { Ahi[n * NP + m] = __float2bfloat16(0.f); Alo[n * NP + m] = __float2bfloat16(0.f); }
        return;
    }
    __shared__ float row[NN];
    __shared__ float red[8];
    __shared__ float ssum;
    float en[EMBD];
#pragma unroll
    for (int d = 0; d < EMBD; d++) en[d] = E[n * EMBD + d];
    float lmax = -1e30f;
    for (int m = tid; m < NN; m += 256) {
        float s = 0.f;
#pragma unroll
        for (int d = 0; d < EMBD; d++) s = fmaf(en[d], E[m * EMBD + d], s);
        s = fmaxf(s, 0.f);
        row[m] = s;
        lmax = fmaxf(lmax, s);
    }
#pragma unroll
    for (int o = 16; o; o >>= 1) lmax = fmaxf(lmax, __shfl_xor_sync(~0u, lmax, o));
    if ((tid & 31) == 0) red[tid >> 5] = lmax;
    __syncthreads();
    if (tid == 0) { float mx = red[0]; for (int w = 1; w < 8; w++) mx = fmaxf(mx, red[w]); red[0] = mx; }
    __syncthreads();
    float mx = red[0];
    __syncthreads();
    float lsum = 0.f;
    for (int m = tid; m < NN; m += 256) { float e = expf(row[m] - mx); row[m] = e; lsum += e; }
#pragma unroll
    for (int o = 16; o; o >>= 1) lsum += __shfl_xor_sync(~0u, lsum, o);
    if ((tid & 31) == 0) red[tid >> 5] = lsum;
    __syncthreads();
    if (tid == 0) { float s = 0.f; for (int w = 0; w < 8; w++) s += red[w]; ssum = s; }
    __syncthreads();
    float inv = 1.f / ssum;
    for (int m = tid; m < NP; m += 256) {
        float v = (m < NN) ? row[m] * inv : 0.f;
        bf16 h, l; bsplit(v, h, l);
        Ahi[n * NP + m] = h; Alo[n * NP + m] = l;
    }
}

__global__ void k_srcsplit(const float* __restrict__ src, bf16* __restrict__ hi,
                           bf16* __restrict__ lo) {
    int idx = blockIdx.x * 256 + threadIdx.x;
    if (idx >= NP * NC0) return;
    int n = idx / NC0, col = idx % NC0, t = col >> 6, b = col & 63;
    float v = (n < NN) ? src[((size_t)b * TT + t) * NN + n] : 0.f;
    bf16 h, l; bsplit(v, h, l);
    hi[idx] = h; lo[idx] = l;
}

// -------- tiled per-node weight pooling: OUT[n, k*COUT+o] = E[n,:]@pool -----
// block = 64 nodes x 256 cols; E-tile and pool-tile staged in smem.
__global__ void __launch_bounds__(256) k_nodewsplit(
    const float* __restrict__ E, const float* __restrict__ pool,
    bf16* __restrict__ Whi, bf16* __restrict__ Wlo, int COUT, int KDp, int layer) {
    __shared__ float Es[64][EMBD];
    __shared__ float Ps[EMBD][256];
    const int tid = threadIdx.x;
    const int colBase = blockIdx.x * 256;
    const int nBase = blockIdx.y * 64;
    const long RC = (long)KDp * COUT;

    for (int i = tid; i < 64 * EMBD; i += 256) {
        int nn = nBase + i / EMBD;
        Es[i / EMBD][i % EMBD] = (nn < NN) ? E[nn * EMBD + i % EMBD] : 0.f;
    }
    {
        int c = colBase + tid;
        int k = c / COUT, o = c % COUT;
        int row, ROWS;
        if (layer == 0) {
            ROWS = 130;
            if (k < 64) row = k + 1;
            else if (k < 128) row = k + 2;
            else if (k == 128) row = 0;
            else if (k == 129) row = 65;
            else row = -1;
        } else { ROWS = 256; row = k; }
#pragma unroll
        for (int d = 0; d < EMBD; d++)
            Ps[d][tid] = (row >= 0) ? pool[((long)d * ROWS + row) * COUT + o] : 0.f;
    }
    __syncthreads();

    float pv[EMBD];
#pragma unroll
    for (int d = 0; d < EMBD; d++) pv[d] = Ps[d][tid];
#pragma unroll 4
    for (int i = 0; i < 64; i++) {
        int nn = nBase + i;
        if (nn >= NN) break;
        float s = 0.f;
#pragma unroll
        for (int d = 0; d < EMBD; d++) s = fmaf(Es[i][d], pv[d], s);
        bf16 h, l; bsplit(s, h, l);
        size_t ix = (size_t)nn * RC + colBase + tid;
        Whi[ix] = h; Wlo[ix] = l;
    }
}

__global__ void k_nodew(const float* __restrict__ E, const float* __restrict__ pool,
                        float* __restrict__ out, int RC) {
    long idx = (long)blockIdx.x * 256 + threadIdx.x;
    if (idx >= (long)NN * RC) return;
    int n = (int)(idx / RC), rem = (int)(idx % RC);
    float s = 0.f;
#pragma unroll
    for (int d = 0; d < EMBD; d++) s = fmaf(E[n * EMBD + d], pool[(long)d * RC + rem], s);
    out[idx] = s;
}

__global__ void k_zeroH(float* H, bf16* Hhi, bf16* Hlo) {
    int i = blockIdx.x * 256 + threadIdx.x;
    if (i >= NN * NB) return;
    H[i] = 0.f; Hhi[i] = __float2bfloat16(0.f); Hlo[i] = __float2bfloat16(0.f);
}

// -- dense split-bf16 MMA: C(hi,lo)=A@X. 64x128 tile, BK16, 128 thr, 2-stage --
__global__ void __launch_bounds__(128) k_mma(const bf16* __restrict__ Ahi,
                                             const bf16* __restrict__ Alo,
                                             const bf16* __restrict__ Xhi,
                                             const bf16* __restrict__ Xlo,
                                             bf16* __restrict__ Chi,
                                             bf16* __restrict__ Clo, int NCc) {
    __shared__ bf16 sAh[2][64 * 16], sAl[2][64 * 16];
    __shared__ bf16 sXh[2][16 * 128], sXl[2][16 * 128];
    const int tid = threadIdx.x, lane = tid & 31, warp = tid >> 5;
    const int rowBase = blockIdx.y * 64, colBase = blockIdx.x * 128;
    const int ar = tid >> 1, ac = (tid & 1) * 8;

    float acc[4][4][4];
#pragma unroll
    for (int i = 0; i < 4; i++)
#pragma unroll
        for (int j = 0; j < 4; j++)
#pragma unroll
            for (int q = 0; q < 4; q++) acc[i][j][q] = 0.f;

    auto prefetch = [&](int kt, int buf) {
        int k0 = kt * 16;
        cp16(&sAh[buf][ar * 16 + ac], Ahi + (size_t)(rowBase + ar) * NP + k0 + ac);
        cp16(&sAl[buf][ar * 16 + ac], Alo + (size_t)(rowBase + ar) * NP + k0 + ac);
#pragma unroll
        for (int i = 0; i < 2; i++) {
            int idx = tid + i * 128;
            int r = idx >> 4, cc = idx & 15;
            int dst = r * 128 + ((cc ^ r) & 15) * 8;
            cp16(&sXh[buf][dst], Xhi + (size_t)(k0 + r) * NCc + colBase + cc * 8);
            cp16(&sXl[buf][dst], Xlo + (size_t)(k0 + r) * NCc + colBase + cc * 8);
        }
        asm volatile("cp.async.commit_group;");
    };

    prefetch(0, 0);
    const int aoff = (lane & 15) * 32 + (lane >> 4) * 16;
    const int bk = lane & 15, bch = lane >> 4;

#pragma unroll 1
    for (int kt = 0; kt < 56; ++kt) {
        if (kt < 55) {
            prefetch(kt + 1, (kt + 1) & 1);
            asm volatile("cp.async.wait_group 1;");
        } else {
            asm volatile("cp.async.wait_group 0;");
        }
        __syncthreads();
        int buf = kt & 1;
        unsigned bAh = s2u(&sAh[buf][0]);
        unsigned bAl = s2u(&sAl[buf][0]);
        unsigned bXh = s2u(&sXh[buf][0]);
        unsigned bXl = s2u(&sXl[buf][0]);
        unsigned ah[4][4], al[4][4], bh[2][4], bl[2][4];
#pragma unroll
        for (int i = 0; i < 4; i++) {
            ldsm4(ah[i], bAh + i * 512 + aoff);
            ldsm4(al[i], bAl + i * 512 + aoff);
        }
#pragma unroll
        for (int j = 0; j < 2; j++) {
            int c = warp * 4 + j * 2 + bch;
            int cp = c ^ bk;
            ldsm4t(bh[j], bXh + bk * 256 + cp * 16);
            ldsm4t(bl[j], bXl + bk * 256 + cp * 16);
        }
#pragma unroll
        for (int i = 0; i < 4; i++)
#pragma unroll
            for (int j = 0; j < 2; j++)
#pragma unroll
                for (int h = 0; h < 2; h++) {
                    unsigned bph[2] = {bh[j][h * 2], bh[j][h * 2 + 1]};
                    unsigned bpl[2] = {bl[j][h * 2], bl[j][h * 2 + 1]};
                    float* cc = acc[i][j * 2 + h];
                    mma16816(cc, ah[i], bph);
                    mma16816(cc, ah[i], bpl);
                    mma16816(cc, al[i], bph);
                }
        __syncthreads();
    }
#pragma unroll
    for (int i = 0; i < 4; i++) {
        int r0 = rowBase + i * 16 + (lane >> 2);
#pragma unroll
        for (int jn = 0; jn < 4; jn++) {
            int c0 = colBase + warp * 32 + jn * 8 + (lane & 3) * 2;
            bf16 h0, l0, h1, l1;
            bsplit(acc[i][jn][0], h0, l0); bsplit(acc[i][jn][1], h1, l1);
            st2(&Chi[(size_t)r0 * NCc + c0], h0, h1);
            st2(&Clo[(size_t)r0 * NCc + c0], l0, l1);
            bsplit(acc[i][jn][2], h0, l0); bsplit(acc[i][jn][3], h1, l1);
            st2(&Chi[(size_t)(r0 + 8) * NCc + c0], h0, h1);
            st2(&Clo[(size_t)(r0 + 8) * NCc + c0], l0, l1);
        }
    }
}

// ---------------- per-node tensor-core GEMM + fused epilogue -----------------
template <int COUT, bool CAND, bool L0>
__global__ void __launch_bounds__(128) k_pn(
    const bf16* __restrict__ xh, const bf16* __restrict__ xl, size_t xstr, size_t xoff,
    const bf16* __restrict__ hh, const bf16* __restrict__ hl,
    const bf16* __restrict__ axh, const bf16* __restrict__ axl, size_t axstr, size_t axoff,
    const bf16* __restrict__ ahh, const bf16* __restrict__ ahl,
    const bf16* __restrict__ Whi, const bf16* __restrict__ Wlo,
    const float* __restrict__ Bias, float* __restrict__ R, float* __restrict__ Hfp,
    bf16* __restrict__ o1h, bf16* __restrict__ o1l,
    bf16* __restrict__ s1h, bf16* __restrict__ s1l, size_t seqOff) {
    constexpr int NCH = L0 ? 9 : 16;
    constexpr int SLICE = COUT / 4;
    constexpr int NJ = SLICE / 16;
    constexpr int WCH = COUT / 8;
    __shared__ bf16 sXh[2][64 * 24], sXl[2][64 * 24];
    __shared__ bf16 sWh[2][16 * COUT], sWl[2][16 * COUT];
    const int n = blockIdx.x, tid = threadIdx.x, lane = tid & 31, wn = tid >> 5;
    const bf16* Wh = Whi + (size_t)n * NCH * 16 * COUT;
    const bf16* Wl = Wlo + (size_t)n * NCH * 16 * COUT;

    float acc[4][NJ * 2][4];
#pragma unroll
    for (int i = 0; i < 4; i++)
#pragma unroll
        for (int j = 0; j < NJ * 2; j++)
#pragma unroll
            for (int q = 0; q < 4; q++) acc[i][j][q] = 0.f;

    auto prefetch = [&](int c) {
        int buf = c & 1;
#pragma unroll
        for (int q = tid; q < 16 * WCH; q += 128) {
            int r = q / WCH, cc = q % WCH;
            int dst = r * COUT + (cc ^ (r & (WCH - 1))) * 8;
            size_t src = (size_t)(c * 16 + r) * COUT + cc * 8;
            cp16(&sWh[buf][dst], Wh + src);
            cp16(&sWl[buf][dst], Wl + src);
        }
        if (L0 && c == 8) {
            if (tid < 64) {
                int b = tid;
                bf16 z = __float2bfloat16(0.f);
#pragma unroll
                for (int k = 0; k < 16; k++) { sXh[buf][b * 24 + k] = z; sXl[buf][b * 24 + k] = z; }
                sXh[buf][b * 24 + 0] = xh[n * xstr + xoff + b];
                sXl[buf][b * 24 + 0] = xl[n * xstr + xoff + b];
                sXh[buf][b * 24 + 1] = axh[n * axstr + axoff + b];
                sXl[buf][b * 24 + 1] = axl[n * axstr + axoff + b];
            }
        } else {
            int b = tid >> 1, half = tid & 1;
            const bf16 *ph, *pl; size_t base;
            if (L0) {
                if (c < 4) { ph = hh; pl = hl; base = (size_t)n * NB + b * 64 + c * 16 + half * 8; }
                else { ph = ahh; pl = ahl; base = (size_t)n * NB + b * 64 + (c - 4) * 16 + half * 8; }
            } else {
                int g = c >> 2, kl = (c & 3) * 16 + half * 8;
                if (g == 0) { ph = xh; pl = xl; base = (size_t)n * xstr + xoff + b * 64 + kl; }
                else if (g == 1) { ph = hh; pl = hl; base = (size_t)n * NB + b * 64 + kl; }
                else if (g == 2) { ph = axh; pl = axl; base = (size_t)n * axstr + axoff + b * 64 + kl; }
                else { ph = ahh; pl = ahl; base = (size_t)n * NB + b * 64 + kl; }
            }
            cp16(&sXh[buf][b * 24 + half * 8], ph + base);
            cp16(&sXl[buf][b * 24 + half * 8], pl + base);
        }
        asm volatile("cp.async.commit_group;");
    };

    prefetch(0);
#pragma unroll 1
    for (int c = 0; c < NCH; c++) {
        if (c + 1 < NCH) { prefetch(c + 1); asm volatile("cp.async.wait_group 1;"); }
        else asm volatile("cp.async.wait_group 0;");
        __syncthreads();
        int buf = c & 1;
        unsigned bXh = s2u(&sXh[buf][0]);
        unsigned bXl = s2u(&sXl[buf][0]);
        unsigned bWh = s2u(&sWh[buf][0]);
        unsigned bWl = s2u(&sWl[buf][0]);
        unsigned ah[4][4], al[4][4], bh[NJ][4], bl[NJ][4];
#pragma unroll
        for (int i = 0; i < 4; i++) {
            unsigned off = (i * 16 + (lane & 15)) * 48 + (lane >> 4) * 16;
            ldsm4(ah[i], bXh + off);
            ldsm4(al[i], bXl + off);
        }
        int bk = lane & 15;
#pragma unroll
        for (int j = 0; j < NJ; j++) {
            int cch = wn * (SLICE / 8) + j * 2 + (lane >> 4);
            unsigned off = bk * (COUT * 2) + (cch ^ (bk & (WCH - 1))) * 16;
            ldsm4t(bh[j], bWh + off);
            ldsm4t(bl[j], bWl + off);
        }
#pragma unroll
        for (int i = 0; i < 4; i++)
#pragma unroll
            for (int j = 0; j < NJ; j++)
#pragma unroll
                for (int h = 0; h < 2; h++) {
                    unsigned bph[2] = {bh[j][h * 2], bh[j][h * 2 + 1]};
                    unsigned bpl[2] = {bl[j][h * 2], bl[j][h * 2 + 1]};
                    float* cc = acc[i][j * 2 + h];
                    mma16816(cc, ah[i], bph);
                    mma16816(cc, ah[i], bpl);
                    mma16816(cc, al[i], bph);
                }
        __syncthreads();
    }

#pragma unroll
    for (int i = 0; i < 4; i++) {
        int b0 = i * 16 + (lane >> 2);
#pragma unroll
        for (int jn = 0; jn < NJ * 2; jn++) {
            int o = wn * SLICE + jn * 8 + (lane & 3) * 2;
#pragma unroll
            for (int rr = 0; rr < 2; rr++) {
                int b = b0 + rr * 8;
                size_t ix = (size_t)n * NB + b * 64;
                float v0 = acc[i][jn][rr * 2 + 0] + Bias[n * COUT + o];
                float v1 = acc[i][jn][rr * 2 + 1] + Bias[n * COUT + o + 1];
                if (!CAND) {
                    float s0 = 1.f / (1.f + expf(-v0));
                    float s1 = 1.f / (1.f + expf(-v1));
                    if (o < 64) {
                        float z0 = s0 * Hfp[ix + o], z1 = s1 * Hfp[ix + o + 1];
                        bf16 h0, l0, h1, l1;
                        bsplit(z0, h0, l0); bsplit(z1, h1, l1);
                        st2(&o1h[ix + o], h0, h1);
                        st2(&o1l[ix + o], l0, l1);
                    } else {
                        R[ix + o - 64] = s0; R[ix + o - 63] = s1;
                    }
                } else {
                    float hc0 = tanhf(v0), hc1 = tanhf(v1);
                    float r0 = R[ix + o], r1 = R[ix + o + 1];
                    float hn0 = r0 * Hfp[ix + o] + (1.f - r0) * hc0;
                    float hn1 = r1 * Hfp[ix + o + 1] + (1.f - r1) * hc1;
                    Hfp[ix + o] = hn0; Hfp[ix + o + 1] = hn1;
                    bf16 h0, l0, h1, l1;
                    bsplit(hn0, h0, l0); bsplit(hn1, h1, l1);
                    st2(&o1h[ix + o], h0, h1);
                    st2(&o1l[ix + o], l0, l1);
                    if (s1h) {
                        size_t s = (size_t)n * NCSEQ + seqOff + b * 64 + o;
                        st2(&s1h[s], h0, h1);
                        st2(&s1l[s], l0, l1);
                    }
                }
            }
        }
    }
}

__global__ void k_final(const float* __restrict__ H, const float* __restrict__ cw,
                        const float* __restrict__ cb, float* __restrict__ out) {
    int idx = blockIdx.x * 256 + threadIdx.x;
    if (idx >= BB * NN) return;
    int n = idx % NN, b = idx / NN;
    const float* h = H + (size_t)n * NB + b * 64;
    float hv[HID];
#pragma unroll
    for (int j = 0; j < HID; j++) hv[j] = h[j];
#pragma unroll
    for (int o = 0; o < TT; o++) {
        float s = cb[o];
#pragma unroll
        for (int j = 0; j < HID; j++) s = fmaf(hv[j], cw[o * HID + j], s);
        out[((size_t)b * TT + o) * NN + n] = s;
    }
}

extern "C" void kernel_launch(void* const* d_in, const int* in_sizes, int n_in,
                              void* d_out, int out_size) {
    const float* src = (const float*)d_in[0];
    const float* E = (const float*)d_in[1];
    const float* cw = (const float*)d_in[10];
    const float* cb = (const float*)d_in[11];
    float* out = (float*)d_out;

#define SYM(T, v, s) T* v; cudaGetSymbolAddress((void**)&v, s)
    SYM(bf16, Ahi, g_Ahi); SYM(bf16, Alo, g_Alo);
    SYM(bf16, X0hi, g_X0hi); SYM(bf16, X0lo, g_X0lo);
    SYM(bf16, AX0hi, g_AX0hi); SYM(bf16, AX0lo, g_AX0lo);
    SYM(bf16, WG0h, g_WG0h); SYM(bf16, WG0l, g_WG0l);
    SYM(bf16, WC0h, g_WC0h); SYM(bf16, WC0l, g_WC0l);
    SYM(bf16, WG1h, g_WG1h); SYM(bf16, WG1l, g_WG1l);
    SYM(bf16, WC1h, g_WC1h); SYM(bf16, WC1l, g_WC1l);
    SYM(float, Bg0, g_Bg0); SYM(float, Bc0, g_Bc0);
    SYM(float, Bg1, g_Bg1); SYM(float, Bc1, g_Bc1);
    SYM(float, H, g_H); SYM(float, R, g_R);
    SYM(bf16, Hhi, g_Hhi); SYM(bf16, Hlo, g_Hlo);
    SYM(bf16, ZHhi, g_ZHhi); SYM(bf16, ZHlo, g_ZHlo);
    SYM(bf16, AHhi, g_AHhi); SYM(bf16, AHlo, g_AHlo);
    SYM(bf16, AZHhi, g_AZHhi); SYM(bf16, AZHlo, g_AZHlo);
    SYM(bf16, Shi, g_SEQhi); SYM(bf16, Slo, g_SEQlo);
    SYM(bf16, AShi, g_ASEQhi); SYM(bf16, ASlo, g_ASEQlo);

    k_supports<<<NP, 256>>>(E, Ahi, Alo);
    k_srcsplit<<<(NP * NC0 + 255) / 256, 256>>>(src, X0hi, X0lo);
    k_nodewsplit<<<dim3(144 * 128 / 256, 14), 256>>>(E, (const float*)d_in[2], WG0h, WG0l, 128, 144, 0);
    k_nodew<<<((long)NN * 128 + 255) / 256, 256>>>(E, (const float*)d_in[3], Bg0, 128);
    k_nodewsplit<<<dim3(144 * 64 / 256, 14), 256>>>(E, (const float*)d_in[4], WC0h, WC0l, 64, 144, 0);
    k_nodew<<<((long)NN * 64 + 255) / 256, 256>>>(E, (const float*)d_in[5], Bc0, 64);
    k_nodewsplit<<<dim3(256 * 128 / 256, 14), 256>>>(E, (const float*)d_in[6], WG1h, WG1l, 128, 256, 1);
    k_nodew<<<((long)NN * 128 + 255) / 256, 256>>>(E, (const float*)d_in[7], Bg1, 128);
    k_nodewsplit<<<dim3(256 * 64 / 256, 14), 256>>>(E, (const float*)d_in[8], WC1h, WC1l, 64, 256, 1);
    k_nodew<<<((long)NN * 64 + 255) / 256, 256>>>(E, (const float*)d_in[9], Bc1, 64);

    k_mma<<<dim3(NC0 / 128, 14), 128>>>(Ahi, Alo, X0hi, X0lo, AX0hi, AX0lo, NC0);

    // layer 0
    k_zeroH<<<(NN * NB + 255) / 256, 256>>>(H, Hhi, Hlo);
    for (int t = 0; t < TT; t++) {
        k_mma<<<dim3(NB / 128, 14), 128>>>(Ahi, Alo, Hhi, Hlo, AHhi, AHlo, NB);
        k_pn<128, false, true><<<NN, 128>>>(X0hi, X0lo, NC0, (size_t)t * 64,
            Hhi, Hlo, AX0hi, AX0lo, NC0, (size_t)t * 64, AHhi, AHlo,
            WG0h, WG0l, Bg0, R, H, ZHhi, ZHlo, (bf16*)0, (bf16*)0, 0);
        k_mma<<<dim3(NB / 128, 14), 128>>>(Ahi, Alo, ZHhi, ZHlo, AZHhi, AZHlo, NB);
        k_pn<64, true, true><<<NN, 128>>>(X0hi, X0lo, NC0, (size_t)t * 64,
            ZHhi, ZHlo, AX0hi, AX0lo, NC0, (size_t)t * 64, AZHhi, AZHlo,
            WC0h, WC0l, Bc0, R, H, Hhi, Hlo, Shi, Slo, (size_t)t * NB);
    }

    k_mma<<<dim3(NCSEQ / 128, 14), 128>>>(Ahi, Alo, Shi, Slo, AShi, ASlo, NCSEQ);

    // layer 1
    k_zeroH<<<(NN * NB + 255) / 256, 256>>>(H, Hhi, Hlo);
    for (int t = 0; t < TT; t++) {
        k_mma<<<dim3(NB / 128, 14), 128>>>(Ahi, Alo, Hhi, Hlo, AHhi, AHlo, NB);
        k_pn<128, false, false><<<NN, 128>>>(Shi, Slo, NCSEQ, (size_t)t * NB,
            Hhi, Hlo, AShi, ASlo, NCSEQ, (size_t)t * NB, AHhi, AHlo,
            WG1h, WG1l, Bg1, R, H, ZHhi, ZHlo, (bf16*)0, (bf16*)0, 0);
        k_mma<<<dim3(NB / 128, 14), 128>>>(Ahi, Alo, ZHhi, ZHlo, AZHhi, AZHlo, NB);
        k_pn<64, true, false><<<NN, 128>>>(Shi, Slo, NCSEQ, (size_t)t * NB,
            ZHhi, ZHlo, AShi, ASlo, NCSEQ, (size_t)t * NB, AZHhi, AZHlo,
            WC1h, WC1l, Bc1, R, H, Hhi, Hlo, (bf16*)0, (bf16*)0, 0);
    }

    k_final<<<(BB * NN + 255) / 256, 256>>>(H, cw, cb, out);
}

// round 11
// speedup vs baseline: 1.2519x; 1.0359x over previous
#include <cuda_runtime.h>
#include <cuda_bf16.h>
#include <math.h>
#include <stdint.h>

#define NN 883
#define NP 896
#define BB 64
#define TT 12
#define HID 64
#define EMBD 10
#define NB 4096
#define NCSEQ 49152
#define NC0 768
typedef __nv_bfloat16 bf16;

__device__ bf16 g_Ahi[NP * NP];
__device__ bf16 g_Alo[NP * NP];
__device__ bf16 g_X0hi[NP * NC0];
__device__ bf16 g_X0lo[NP * NC0];
__device__ bf16 g_AX0hi[NP * NC0];
__device__ bf16 g_AX0lo[NP * NC0];
__device__ bf16 g_WG0h[NN * 144 * 128];
__device__ bf16 g_WG0l[NN * 144 * 128];
__device__ bf16 g_WC0h[NN * 144 * 64];
__device__ bf16 g_WC0l[NN * 144 * 64];
__device__ bf16 g_WG1h[NN * 256 * 128];
__device__ bf16 g_WG1l[NN * 256 * 128];
__device__ bf16 g_WC1h[NN * 256 * 64];
__device__ bf16 g_WC1l[NN * 256 * 64];
__device__ float g_Bg0[NN * 128];
__device__ float g_Bc0[NN * 64];
__device__ float g_Bg1[NN * 128];
__device__ float g_Bc1[NN * 64];
__device__ float g_H[NN * NB];
__device__ float g_R[NN * NB];
__device__ bf16 g_Hhi[NP * NB];
__device__ bf16 g_Hlo[NP * NB];
__device__ bf16 g_ZHhi[NP * NB];
__device__ bf16 g_ZHlo[NP * NB];
__device__ bf16 g_AHhi[NP * NB];
__device__ bf16 g_AHlo[NP * NB];
__device__ bf16 g_AZHhi[NP * NB];
__device__ bf16 g_AZHlo[NP * NB];
__device__ bf16 g_SEQhi[(size_t)NP * NCSEQ];
__device__ bf16 g_SEQlo[(size_t)NP * NCSEQ];
__device__ bf16 g_ASEQhi[(size_t)NP * NCSEQ];
__device__ bf16 g_ASEQlo[(size_t)NP * NCSEQ];

__device__ __forceinline__ void bsplit(float v, bf16& hi, bf16& lo) {
    hi = __float2bfloat16_rn(v);
    lo = __float2bfloat16_rn(v - __bfloat162float(hi));
}
__device__ __forceinline__ unsigned s2u(const void* p) {
    return (unsigned)__cvta_generic_to_shared(p);
}
__device__ __forceinline__ void cp16(void* s, const void* g) {
    asm volatile("cp.async.cg.shared.global [%0], [%1], 16;" :: "r"(s2u(s)), "l"(g));
}
__device__ __forceinline__ void ldsm4(unsigned* r, unsigned a) {
    asm volatile("ldmatrix.sync.aligned.m8n8.x4.shared.b16 {%0,%1,%2,%3}, [%4];"
                 : "=r"(r[0]), "=r"(r[1]), "=r"(r[2]), "=r"(r[3]) : "r"(a));
}
__device__ __forceinline__ void ldsm4t(unsigned* r, unsigned a) {
    asm volatile("ldmatrix.sync.aligned.m8n8.x4.trans.shared.b16 {%0,%1,%2,%3}, [%4];"
                 : "=r"(r[0]), "=r"(r[1]), "=r"(r[2]), "=r"(r[3]) : "r"(a));
}
__device__ __forceinline__ void mma16816(float* c, const unsigned* a, const unsigned* b) {
    asm volatile(
        "mma.sync.aligned.m16n8k16.row.col.f32.bf16.bf16.f32 "
        "{%0,%1,%2,%3},{%4,%5,%6,%7},{%8,%9},{%0,%1,%2,%3};"
        : "+f"(c[0]), "+f"(c[1]), "+f"(c[2]), "+f"(c[3])
        : "r"(a[0]), "r"(a[1]), "r"(a[2]), "r"(a[3]), "r"(b[0]), "r"(b[1]));
}
__device__ __forceinline__ void st2(bf16* p, bf16 a, bf16 b) {
    __nv_bfloat162 v; v.x = a; v.y = b;
    *(__nv_bfloat162*)p = v;
}

// ---------------- adjacency ----------------
__global__ void __launch_bounds__(256) k_supports(const float* __restrict__ E,
                                                  bf16* __restrict__ Ahi,
                                                  bf16* __restrict__ Alo) {
    int n = blockIdx.x, tid = threadIdx.x;
    if (n >= NN) {
        for (int m = tid; m < NP; m += 256) { Ahi[n * NP + m] = __float2bfloat16(0.f); Alo[n * NP + m] = __float2bfloat16(0.f); }
        return;
    }
    __shared__ float row[NN];
    __shared__ float red[8];
    __shared__ float ssum;
    float en[EMBD];
#pragma unroll
    for (int d = 0; d < EMBD; d++) en[d] = E[n * EMBD + d];
    float lmax = -1e30f;
    for (int m = tid; m < NN; m += 256) {
        float s = 0.f;
#pragma unroll
        for (int d = 0; d < EMBD; d++) s = fmaf(en[d], E[m * EMBD + d], s);
        s = fmaxf(s, 0.f);
        row[m] = s;
        lmax = fmaxf(lmax, s);
    }
#pragma unroll
    for (int o = 16; o; o >>= 1) lmax = fmaxf(lmax, __shfl_xor_sync(~0u, lmax, o));
    if ((tid & 31) == 0) red[tid >> 5] = lmax;
    __syncthreads();
    if (tid == 0) { float mx = red[0]; for (int w = 1; w < 8; w++) mx = fmaxf(mx, red[w]); red[0] = mx; }
    __syncthreads();
    float mx = red[0];
    __syncthreads();
    float lsum = 0.f;
    for (int m = tid; m < NN; m += 256) { float e = expf(row[m] - mx); row[m] = e; lsum += e; }
#pragma unroll
    for (int o = 16; o; o >>= 1) lsum += __shfl_xor_sync(~0u, lsum, o);
    if ((tid & 31) == 0) red[tid >> 5] = lsum;
    __syncthreads();
    if (tid == 0) { float s = 0.f; for (int w = 0; w < 8; w++) s += red[w]; ssum = s; }
    __syncthreads();
    float inv = 1.f / ssum;
    for (int m = tid; m < NP; m += 256) {
        float v = (m < NN) ? row[m] * inv : 0.f;
        bf16 h, l; bsplit(v, h, l);
        Ahi[n * NP + m] = h; Alo[n * NP + m] = l;
    }
}

__global__ void k_srcsplit(const float* __restrict__ src, bf16* __restrict__ hi,
                           bf16* __restrict__ lo) {
    int idx = blockIdx.x * 256 + threadIdx.x;
    if (idx >= NP * NC0) return;
    int n = idx / NC0, col = idx % NC0, t = col >> 6, b = col & 63;
    float v = (n < NN) ? src[((size_t)b * TT + t) * NN + n] : 0.f;
    bf16 h, l; bsplit(v, h, l);
    hi[idx] = h; lo[idx] = l;
}

// -------- tiled per-node weight pooling --------
__global__ void __launch_bounds__(256) k_nodewsplit(
    const float* __restrict__ E, const float* __restrict__ pool,
    bf16* __restrict__ Whi, bf16* __restrict__ Wlo, int COUT, int KDp, int layer) {
    __shared__ float Es[64][EMBD];
    __shared__ float Ps[EMBD][256];
    const int tid = threadIdx.x;
    const int colBase = blockIdx.x * 256;
    const int nBase = blockIdx.y * 64;
    const long RC = (long)KDp * COUT;

    for (int i = tid; i < 64 * EMBD; i += 256) {
        int nn = nBase + i / EMBD;
        Es[i / EMBD][i % EMBD] = (nn < NN) ? E[nn * EMBD + i % EMBD] : 0.f;
    }
    {
        int c = colBase + tid;
        int k = c / COUT, o = c % COUT;
        int row, ROWS;
        if (layer == 0) {
            ROWS = 130;
            if (k < 64) row = k + 1;
            else if (k < 128) row = k + 2;
            else if (k == 128) row = 0;
            else if (k == 129) row = 65;
            else row = -1;
        } else { ROWS = 256; row = k; }
#pragma unroll
        for (int d = 0; d < EMBD; d++)
            Ps[d][tid] = (row >= 0) ? pool[((long)d * ROWS + row) * COUT + o] : 0.f;
    }
    __syncthreads();

    float pv[EMBD];
#pragma unroll
    for (int d = 0; d < EMBD; d++) pv[d] = Ps[d][tid];
#pragma unroll 4
    for (int i = 0; i < 64; i++) {
        int nn = nBase + i;
        if (nn >= NN) break;
        float s = 0.f;
#pragma unroll
        for (int d = 0; d < EMBD; d++) s = fmaf(Es[i][d], pv[d], s);
        bf16 h, l; bsplit(s, h, l);
        size_t ix = (size_t)nn * RC + colBase + tid;
        Whi[ix] = h; Wlo[ix] = l;
    }
}

__global__ void k_nodew(const float* __restrict__ E, const float* __restrict__ pool,
                        float* __restrict__ out, int RC) {
    long idx = (long)blockIdx.x * 256 + threadIdx.x;
    if (idx >= (long)NN * RC) return;
    int n = (int)(idx / RC), rem = (int)(idx % RC);
    float s = 0.f;
#pragma unroll
    for (int d = 0; d < EMBD; d++) s = fmaf(E[n * EMBD + d], pool[(long)d * RC + rem], s);
    out[idx] = s;
}

// zero H (fp32, NN*NB) + 6 bf16 buffers (NP*NB each, as uint32 pairs)
__global__ void k_zeroH(float* H, bf16* Hhi, bf16* Hlo, bf16* AHhi, bf16* AHlo,
                        bf16* AZHhi, bf16* AZHlo) {
    int i = blockIdx.x * 256 + threadIdx.x;
    if (i < NN * NB) H[i] = 0.f;
    if (i < NP * NB / 2) {
        ((uint32_t*)Hhi)[i] = 0u; ((uint32_t*)Hlo)[i] = 0u;
        ((uint32_t*)AHhi)[i] = 0u; ((uint32_t*)AHlo)[i] = 0u;
        ((uint32_t*)AZHhi)[i] = 0u; ((uint32_t*)AZHlo)[i] = 0u;
    }
}

// -- dense split-bf16 MMA: C(hi,lo)=A@X. 64x128 tile, BK16, 128 thr, 2-stage --
__global__ void __launch_bounds__(128) k_mma(const bf16* __restrict__ Ahi,
                                             const bf16* __restrict__ Alo,
                                             const bf16* __restrict__ Xhi,
                                             const bf16* __restrict__ Xlo,
                                             bf16* __restrict__ Chi,
                                             bf16* __restrict__ Clo, int NCc) {
    __shared__ bf16 sAh[2][64 * 16], sAl[2][64 * 16];
    __shared__ bf16 sXh[2][16 * 128], sXl[2][16 * 128];
    const int tid = threadIdx.x, lane = tid & 31, warp = tid >> 5;
    const int rowBase = blockIdx.y * 64, colBase = blockIdx.x * 128;
    const int ar = tid >> 1, ac = (tid & 1) * 8;

    float acc[4][4][4];
#pragma unroll
    for (int i = 0; i < 4; i++)
#pragma unroll
        for (int j = 0; j < 4; j++)
#pragma unroll
            for (int q = 0; q < 4; q++) acc[i][j][q] = 0.f;

    auto prefetch = [&](int kt, int buf) {
        int k0 = kt * 16;
        cp16(&sAh[buf][ar * 16 + ac], Ahi + (size_t)(rowBase + ar) * NP + k0 + ac);
        cp16(&sAl[buf][ar * 16 + ac], Alo + (size_t)(rowBase + ar) * NP + k0 + ac);
#pragma unroll
        for (int i = 0; i < 2; i++) {
            int idx = tid + i * 128;
            int r = idx >> 4, cc = idx & 15;
            int dst = r * 128 + ((cc ^ r) & 15) * 8;
            cp16(&sXh[buf][dst], Xhi + (size_t)(k0 + r) * NCc + colBase + cc * 8);
            cp16(&sXl[buf][dst], Xlo + (size_t)(k0 + r) * NCc + colBase + cc * 8);
        }
        asm volatile("cp.async.commit_group;");
    };

    prefetch(0, 0);
    const int aoff = (lane & 15) * 32 + (lane >> 4) * 16;
    const int bk = lane & 15, bch = lane >> 4;

#pragma unroll 1
    for (int kt = 0; kt < 56; ++kt) {
        if (kt < 55) {
            prefetch(kt + 1, (kt + 1) & 1);
            asm volatile("cp.async.wait_group 1;");
        } else {
            asm volatile("cp.async.wait_group 0;");
        }
        __syncthreads();
        int buf = kt & 1;
        unsigned bAh = s2u(&sAh[buf][0]);
        unsigned bAl = s2u(&sAl[buf][0]);
        unsigned bXh = s2u(&sXh[buf][0]);
        unsigned bXl = s2u(&sXl[buf][0]);
        unsigned ah[4][4], al[4][4], bh[2][4], bl[2][4];
#pragma unroll
        for (int i = 0; i < 4; i++) {
            ldsm4(ah[i], bAh + i * 512 + aoff);
            ldsm4(al[i], bAl + i * 512 + aoff);
        }
#pragma unroll
        for (int j = 0; j < 2; j++) {
            int c = warp * 4 + j * 2 + bch;
            int cp = c ^ bk;
            ldsm4t(bh[j], bXh + bk * 256 + cp * 16);
            ldsm4t(bl[j], bXl + bk * 256 + cp * 16);
        }
#pragma unroll
        for (int i = 0; i < 4; i++)
#pragma unroll
            for (int j = 0; j < 2; j++)
#pragma unroll
                for (int h = 0; h < 2; h++) {
                    unsigned bph[2] = {bh[j][h * 2], bh[j][h * 2 + 1]};
                    unsigned bpl[2] = {bl[j][h * 2], bl[j][h * 2 + 1]};
                    float* cc = acc[i][j * 2 + h];
                    mma16816(cc, ah[i], bph);
                    mma16816(cc, ah[i], bpl);
                    mma16816(cc, al[i], bph);
                }
        __syncthreads();
    }
#pragma unroll
    for (int i = 0; i < 4; i++) {
        int r0 = rowBase + i * 16 + (lane >> 2);
#pragma unroll
        for (int jn = 0; jn < 4; jn++) {
            int c0 = colBase + warp * 32 + jn * 8 + (lane & 3) * 2;
            bf16 h0, l0, h1, l1;
            bsplit(acc[i][jn][0], h0, l0); bsplit(acc[i][jn][1], h1, l1);
            st2(&Chi[(size_t)r0 * NCc + c0], h0, h1);
            st2(&Clo[(size_t)r0 * NCc + c0], l0, l1);
            bsplit(acc[i][jn][2], h0, l0); bsplit(acc[i][jn][3], h1, l1);
            st2(&Chi[(size_t)(r0 + 8) * NCc + c0], h0, h1);
            st2(&Clo[(size_t)(r0 + 8) * NCc + c0], l0, l1);
        }
    }
}

// ---------------- per-node tensor-core GEMM + fused epilogue -----------------
template <int COUT, bool CAND, bool L0>
__global__ void __launch_bounds__(128) k_pn(
    const bf16* __restrict__ xh, const bf16* __restrict__ xl, size_t xstr, size_t xoff,
    const bf16* __restrict__ hh, const bf16* __restrict__ hl,
    const bf16* __restrict__ axh, const bf16* __restrict__ axl, size_t axstr, size_t axoff,
    const bf16* __restrict__ ahh, const bf16* __restrict__ ahl,
    const bf16* __restrict__ Whi, const bf16* __restrict__ Wlo,
    const float* __restrict__ Bias, float* __restrict__ R, float* __restrict__ Hfp,
    bf16* __restrict__ o1h, bf16* __restrict__ o1l,
    bf16* __restrict__ s1h, bf16* __restrict__ s1l, size_t seqOff) {
    constexpr int NCH = L0 ? 9 : 16;
    constexpr int SLICE = COUT / 4;
    constexpr int NJ = SLICE / 16;
    constexpr int WCH = COUT / 8;
    __shared__ bf16 sXh[2][64 * 24], sXl[2][64 * 24];
    __shared__ bf16 sWh[2][16 * COUT], sWl[2][16 * COUT];
    const int n = blockIdx.x, tid = threadIdx.x, lane = tid & 31, wn = tid >> 5;
    const bf16* Wh = Whi + (size_t)n * NCH * 16 * COUT;
    const bf16* Wl = Wlo + (size_t)n * NCH * 16 * COUT;

    float acc[4][NJ * 2][4];
#pragma unroll
    for (int i = 0; i < 4; i++)
#pragma unroll
        for (int j = 0; j < NJ * 2; j++)
#pragma unroll
            for (int q = 0; q < 4; q++) acc[i][j][q] = 0.f;

    auto prefetch = [&](int c) {
        int buf = c & 1;
#pragma unroll
        for (int q = tid; q < 16 * WCH; q += 128) {
            int r = q / WCH, cc = q % WCH;
            int dst = r * COUT + (cc ^ (r & (WCH - 1))) * 8;
            size_t src = (size_t)(c * 16 + r) * COUT + cc * 8;
            cp16(&sWh[buf][dst], Wh + src);
            cp16(&sWl[buf][dst], Wl + src);
        }
        if (L0 && c == 8) {
            if (tid < 64) {
                int b = tid;
                bf16 z = __float2bfloat16(0.f);
#pragma unroll
                for (int k = 0; k < 16; k++) { sXh[buf][b * 24 + k] = z; sXl[buf][b * 24 + k] = z; }
                sXh[buf][b * 24 + 0] = xh[n * xstr + xoff + b];
                sXl[buf][b * 24 + 0] = xl[n * xstr + xoff + b];
                sXh[buf][b * 24 + 1] = axh[n * axstr + axoff + b];
                sXl[buf][b * 24 + 1] = axl[n * axstr + axoff + b];
            }
        } else {
            int b = tid >> 1, half = tid & 1;
            const bf16 *ph, *pl; size_t base;
            if (L0) {
                if (c < 4) { ph = hh; pl = hl; base = (size_t)n * NB + b * 64 + c * 16 + half * 8; }
                else { ph = ahh; pl = ahl; base = (size_t)n * NB + b * 64 + (c - 4) * 16 + half * 8; }
            } else {
                int g = c >> 2, kl = (c & 3) * 16 + half * 8;
                if (g == 0) { ph = xh; pl = xl; base = (size_t)n * xstr + xoff + b * 64 + kl; }
                else if (g == 1) { ph = hh; pl = hl; base = (size_t)n * NB + b * 64 + kl; }
                else if (g == 2) { ph = axh; pl = axl; base = (size_t)n * axstr + axoff + b * 64 + kl; }
                else { ph = ahh; pl = ahl; base = (size_t)n * NB + b * 64 + kl; }
            }
            cp16(&sXh[buf][b * 24 + half * 8], ph + base);
            cp16(&sXl[buf][b * 24 + half * 8], pl + base);
        }
        asm volatile("cp.async.commit_group;");
    };

    prefetch(0);
#pragma unroll 1
    for (int c = 0; c < NCH; c++) {
        if (c + 1 < NCH) { prefetch(c + 1); asm volatile("cp.async.wait_group 1;"); }
        else asm volatile("cp.async.wait_group 0;");
        __syncthreads();
        int buf = c & 1;
        unsigned bXh = s2u(&sXh[buf][0]);
        unsigned bXl = s2u(&sXl[buf][0]);
        unsigned bWh = s2u(&sWh[buf][0]);
        unsigned bWl = s2u(&sWl[buf][0]);
        unsigned ah[4][4], al[4][4], bh[NJ][4], bl[NJ][4];
#pragma unroll
        for (int i = 0; i < 4; i++) {
            unsigned off = (i * 16 + (lane & 15)) * 48 + (lane >> 4) * 16;
            ldsm4(ah[i], bXh + off);
            ldsm4(al[i], bXl + off);
        }
        int bk = lane & 15;
#pragma unroll
        for (int j = 0; j < NJ; j++) {
            int cch = wn * (SLICE / 8) + j * 2 + (lane >> 4);
            unsigned off = bk * (COUT * 2) + (cch ^ (bk & (WCH - 1))) * 16;
            ldsm4t(bh[j], bWh + off);
            ldsm4t(bl[j], bWl + off);
        }
#pragma unroll
        for (int i = 0; i < 4; i++)
#pragma unroll
            for (int j = 0; j < NJ; j++)
#pragma unroll
                for (int h = 0; h < 2; h++) {
                    unsigned bph[2] = {bh[j][h * 2], bh[j][h * 2 + 1]};
                    unsigned bpl[2] = {bl[j][h * 2], bl[j][h * 2 + 1]};
                    float* cc = acc[i][j * 2 + h];
                    mma16816(cc, ah[i], bph);
                    mma16816(cc, ah[i], bpl);
                    mma16816(cc, al[i], bph);
                }
        __syncthreads();
    }

#pragma unroll
    for (int i = 0; i < 4; i++) {
        int b0 = i * 16 + (lane >> 2);
#pragma unroll
        for (int jn = 0; jn < NJ * 2; jn++) {
            int o = wn * SLICE + jn * 8 + (lane & 3) * 2;
#pragma unroll
            for (int rr = 0; rr < 2; rr++) {
                int b = b0 + rr * 8;
                size_t ix = (size_t)n * NB + b * 64;
                float v0 = acc[i][jn][rr * 2 + 0] + Bias[n * COUT + o];
                float v1 = acc[i][jn][rr * 2 + 1] + Bias[n * COUT + o + 1];
                if (!CAND) {
                    float s0 = 1.f / (1.f + expf(-v0));
                    float s1 = 1.f / (1.f + expf(-v1));
                    if (o < 64) {
                        float z0 = s0 * Hfp[ix + o], z1 = s1 * Hfp[ix + o + 1];
                        bf16 h0, l0, h1, l1;
                        bsplit(z0, h0, l0); bsplit(z1, h1, l1);
                        st2(&o1h[ix + o], h0, h1);
                        st2(&o1l[ix + o], l0, l1);
                    } else {
                        R[ix + o - 64] = s0; R[ix + o - 63] = s1;
                    }
                } else {
                    float hc0 = tanhf(v0), hc1 = tanhf(v1);
                    float r0 = R[ix + o], r1 = R[ix + o + 1];
                    float hn0 = r0 * Hfp[ix + o] + (1.f - r0) * hc0;
                    float hn1 = r1 * Hfp[ix + o + 1] + (1.f - r1) * hc1;
                    Hfp[ix + o] = hn0; Hfp[ix + o + 1] = hn1;
                    bf16 h0, l0, h1, l1;
                    bsplit(hn0, h0, l0); bsplit(hn1, h1, l1);
                    st2(&o1h[ix + o], h0, h1);
                    st2(&o1l[ix + o], l0, l1);
                    if (s1h) {
                        size_t s = (size_t)n * NCSEQ + seqOff + b * 64 + o;
                        st2(&s1h[s], h0, h1);
                        st2(&s1l[s], l0, l1);
                    }
                }
            }
        }
    }
}

__global__ void k_final(const float* __restrict__ H, const float* __restrict__ cw,
                        const float* __restrict__ cb, float* __restrict__ out) {
    int idx = blockIdx.x * 256 + threadIdx.x;
    if (idx >= BB * NN) return;
    int n = idx % NN, b = idx / NN;
    const float* h = H + (size_t)n * NB + b * 64;
    float hv[HID];
#pragma unroll
    for (int j = 0; j < HID; j++) hv[j] = h[j];
#pragma unroll
    for (int o = 0; o < TT; o++) {
        float s = cb[o];
#pragma unroll
        for (int j = 0; j < HID; j++) s = fmaf(hv[j], cw[o * HID + j], s);
        out[((size_t)b * TT + o) * NN + n] = s;
    }
}

extern "C" void kernel_launch(void* const* d_in, const int* in_sizes, int n_in,
                              void* d_out, int out_size) {
    const float* src = (const float*)d_in[0];
    const float* E = (const float*)d_in[1];
    const float* cw = (const float*)d_in[10];
    const float* cb = (const float*)d_in[11];
    float* out = (float*)d_out;

#define SYM(T, v, s) T* v; cudaGetSymbolAddress((void**)&v, s)
    SYM(bf16, Ahi, g_Ahi); SYM(bf16, Alo, g_Alo);
    SYM(bf16, X0hi, g_X0hi); SYM(bf16, X0lo, g_X0lo);
    SYM(bf16, AX0hi, g_AX0hi); SYM(bf16, AX0lo, g_AX0lo);
    SYM(bf16, WG0h, g_WG0h); SYM(bf16, WG0l, g_WG0l);
    SYM(bf16, WC0h, g_WC0h); SYM(bf16, WC0l, g_WC0l);
    SYM(bf16, WG1h, g_WG1h); SYM(bf16, WG1l, g_WG1l);
    SYM(bf16, WC1h, g_WC1h); SYM(bf16, WC1l, g_WC1l);
    SYM(float, Bg0, g_Bg0); SYM(float, Bc0, g_Bc0);
    SYM(float, Bg1, g_Bg1); SYM(float, Bc1, g_Bc1);
    SYM(float, H, g_H); SYM(float, R, g_R);
    SYM(bf16, Hhi, g_Hhi); SYM(bf16, Hlo, g_Hlo);
    SYM(bf16, ZHhi, g_ZHhi); SYM(bf16, ZHlo, g_ZHlo);
    SYM(bf16, AHhi, g_AHhi); SYM(bf16, AHlo, g_AHlo);
    SYM(bf16, AZHhi, g_AZHhi); SYM(bf16, AZHlo, g_AZHlo);
    SYM(bf16, Shi, g_SEQhi); SYM(bf16, Slo, g_SEQlo);
    SYM(bf16, AShi, g_ASEQhi); SYM(bf16, ASlo, g_ASEQlo);

    k_supports<<<NP, 256>>>(E, Ahi, Alo);
    k_srcsplit<<<(NP * NC0 + 255) / 256, 256>>>(src, X0hi, X0lo);
    k_nodewsplit<<<dim3(144 * 128 / 256, 14), 256>>>(E, (const float*)d_in[2], WG0h, WG0l, 128, 144, 0);
    k_nodew<<<((long)NN * 128 + 255) / 256, 256>>>(E, (const float*)d_in[3], Bg0, 128);
    k_nodewsplit<<<dim3(144 * 64 / 256, 14), 256>>>(E, (const float*)d_in[4], WC0h, WC0l, 64, 144, 0);
    k_nodew<<<((long)NN * 64 + 255) / 256, 256>>>(E, (const float*)d_in[5], Bc0, 64);
    k_nodewsplit<<<dim3(256 * 128 / 256, 14), 256>>>(E, (const float*)d_in[6], WG1h, WG1l, 128, 256, 1);
    k_nodew<<<((long)NN * 128 + 255) / 256, 256>>>(E, (const float*)d_in[7], Bg1, 128);
    k_nodewsplit<<<dim3(256 * 64 / 256, 14), 256>>>(E, (const float*)d_in[8], WC1h, WC1l, 64, 256, 1);
    k_nodew<<<((long)NN * 64 + 255) / 256, 256>>>(E, (const float*)d_in[9], Bc1, 64);

    k_mma<<<dim3(NC0 / 128, 14), 128>>>(Ahi, Alo, X0hi, X0lo, AX0hi, AX0lo, NC0);

    // FIX: grid must cover the fp32 H clear (NN*NB), which exceeds NP*NB/2
    const int ZG = (NN * NB + 255) / 256;

    // layer 0
    k_zeroH<<<ZG, 256>>>(H, Hhi, Hlo, AHhi, AHlo, AZHhi, AZHlo);
    for (int t = 0; t < TT; t++) {
        if (t > 0)  // H==0 at t=0 -> A@H == 0 (buffers pre-zeroed)
            k_mma<<<dim3(NB / 128, 14), 128>>>(Ahi, Alo, Hhi, Hlo, AHhi, AHlo, NB);
        k_pn<128, false, true><<<NN, 128>>>(X0hi, X0lo, NC0, (size_t)t * 64,
            Hhi, Hlo, AX0hi, AX0lo, NC0, (size_t)t * 64, AHhi, AHlo,
            WG0h, WG0l, Bg0, R, H, ZHhi, ZHlo, (bf16*)0, (bf16*)0, 0);
        if (t > 0)  // ZH = z*H == 0 at t=0 -> A@ZH == 0
            k_mma<<<dim3(NB / 128, 14), 128>>>(Ahi, Alo, ZHhi, ZHlo, AZHhi, AZHlo, NB);
        k_pn<64, true, true><<<NN, 128>>>(X0hi, X0lo, NC0, (size_t)t * 64,
            ZHhi, ZHlo, AX0hi, AX0lo, NC0, (size_t)t * 64, AZHhi, AZHlo,
            WC0h, WC0l, Bc0, R, H, Hhi, Hlo, Shi, Slo, (size_t)t * NB);
    }

    k_mma<<<dim3(NCSEQ / 128, 14), 128>>>(Ahi, Alo, Shi, Slo, AShi, ASlo, NCSEQ);

    // layer 1
    k_zeroH<<<ZG, 256>>>(H, Hhi, Hlo, AHhi, AHlo, AZHhi, AZHlo);
    for (int t = 0; t < TT; t++) {
        if (t > 0)
            k_mma<<<dim3(NB / 128, 14), 128>>>(Ahi, Alo, Hhi, Hlo, AHhi, AHlo, NB);
        k_pn<128, false, false><<<NN, 128>>>(Shi, Slo, NCSEQ, (size_t)t * NB,
            Hhi, Hlo, AShi, ASlo, NCSEQ, (size_t)t * NB, AHhi, AHlo,
            WG1h, WG1l, Bg1, R, H, ZHhi, ZHlo, (bf16*)0, (bf16*)0, 0);
        if (t > 0)
            k_mma<<<dim3(NB / 128, 14), 128>>>(Ahi, Alo, ZHhi, ZHlo, AZHhi, AZHlo, NB);
        k_pn<64, true, false><<<NN, 128>>>(Shi, Slo, NCSEQ, (size_t)t * NB,
            ZHhi, ZHlo, AShi, ASlo, NCSEQ, (size_t)t * NB, AZHhi, AZHlo,
            WC1h, WC1l, Bc1, R, H, Hhi, Hlo, (bf16*)0, (bf16*)0, 0);
    }

    k_final<<<(BB * NN + 255) / 256, 256>>>(H, cw, cb, out);
}

// round 12
// speedup vs baseline: 1.3977x; 1.1165x over previous
#include <cuda_runtime.h>
#include <cuda_bf16.h>
#include <math.h>
#include <stdint.h>

#define NN 883
#define NP 896
#define BB 64
#define TT 12
#define HID 64
#define EMBD 10
#define NB 4096
#define NCSEQ 49152
#define NC0 768
typedef __nv_bfloat16 bf16;

__device__ bf16 g_Ahi[NP * NP];
__device__ bf16 g_Alo[NP * NP];
__device__ bf16 g_X0hi[NP * NC0];
__device__ bf16 g_X0lo[NP * NC0];
__device__ bf16 g_AX0hi[NP * NC0];
__device__ bf16 g_AX0lo[NP * NC0];
__device__ bf16 g_WG0h[NN * 144 * 128];
__device__ bf16 g_WG0l[NN * 144 * 128];
__device__ bf16 g_WC0h[NN * 144 * 64];
__device__ bf16 g_WC0l[NN * 144 * 64];
__device__ bf16 g_WG1h[NN * 256 * 128];
__device__ bf16 g_WG1l[NN * 256 * 128];
__device__ bf16 g_WC1h[NN * 256 * 64];
__device__ bf16 g_WC1l[NN * 256 * 64];
__device__ float g_Bg0[NN * 128];
__device__ float g_Bc0[NN * 64];
__device__ float g_Bg1[NN * 128];
__device__ float g_Bc1[NN * 64];
__device__ float g_H[NN * NB];
__device__ float g_R[NN * NB];
__device__ bf16 g_Hhi[NP * NB];
__device__ bf16 g_Hlo[NP * NB];
__device__ bf16 g_ZHhi[NP * NB];
__device__ bf16 g_ZHlo[NP * NB];
__device__ bf16 g_AHhi[NP * NB];
__device__ bf16 g_AHlo[NP * NB];
__device__ bf16 g_AZHhi[NP * NB];
__device__ bf16 g_AZHlo[NP * NB];
__device__ bf16 g_SEQhi[(size_t)NP * NCSEQ];
__device__ bf16 g_SEQlo[(size_t)NP * NCSEQ];
__device__ bf16 g_ASEQhi[(size_t)NP * NCSEQ];
__device__ bf16 g_ASEQlo[(size_t)NP * NCSEQ];

__device__ __forceinline__ void bsplit(float v, bf16& hi, bf16& lo) {
    hi = __float2bfloat16_rn(v);
    lo = __float2bfloat16_rn(v - __bfloat162float(hi));
}
__device__ __forceinline__ unsigned s2u(const void* p) {
    return (unsigned)__cvta_generic_to_shared(p);
}
__device__ __forceinline__ void cp16(void* s, const void* g) {
    asm volatile("cp.async.cg.shared.global [%0], [%1], 16;" :: "r"(s2u(s)), "l"(g));
}
__device__ __forceinline__ void ldsm4(unsigned* r, unsigned a) {
    asm volatile("ldmatrix.sync.aligned.m8n8.x4.shared.b16 {%0,%1,%2,%3}, [%4];"
                 : "=r"(r[0]), "=r"(r[1]), "=r"(r[2]), "=r"(r[3]) : "r"(a));
}
__device__ __forceinline__ void ldsm4t(unsigned* r, unsigned a) {
    asm volatile("ldmatrix.sync.aligned.m8n8.x4.trans.shared.b16 {%0,%1,%2,%3}, [%4];"
                 : "=r"(r[0]), "=r"(r[1]), "=r"(r[2]), "=r"(r[3]) : "r"(a));
}
__device__ __forceinline__ void mma16816(float* c, const unsigned* a, const unsigned* b) {
    asm volatile(
        "mma.sync.aligned.m16n8k16.row.col.f32.bf16.bf16.f32 "
        "{%0,%1,%2,%3},{%4,%5,%6,%7},{%8,%9},{%0,%1,%2,%3};"
        : "+f"(c[0]), "+f"(c[1]), "+f"(c[2]), "+f"(c[3])
        : "r"(a[0]), "r"(a[1]), "r"(a[2]), "r"(a[3]), "r"(b[0]), "r"(b[1]));
}
__device__ __forceinline__ void st2(bf16* p, bf16 a, bf16 b) {
    __nv_bfloat162 v; v.x = a; v.y = b;
    *(__nv_bfloat162*)p = v;
}

// ---------------- adjacency ----------------
__global__ void __launch_bounds__(256) k_supports(const float* __restrict__ E,
                                                  bf16* __restrict__ Ahi,
                                                  bf16* __restrict__ Alo) {
    int n = blockIdx.x, tid = threadIdx.x;
    if (n >= NN) {
        for (int m = tid; m < NP; m += 256) { Ahi[n * NP + m] = __float2bfloat16(0.f); Alo[n * NP + m] = __float2bfloat16(0.f); }
        return;
    }
    __shared__ float row[NN];
    __shared__ float red[8];
    __shared__ float ssum;
    float en[EMBD];
#pragma unroll
    for (int d = 0; d < EMBD; d++) en[d] = E[n * EMBD + d];
    float lmax = -1e30f;
    for (int m = tid; m < NN; m += 256) {
        float s = 0.f;
#pragma unroll
        for (int d = 0; d < EMBD; d++) s = fmaf(en[d], E[m * EMBD + d], s);
        s = fmaxf(s, 0.f);
        row[m] = s;
        lmax = fmaxf(lmax, s);
    }
#pragma unroll
    for (int o = 16; o; o >>= 1) lmax = fmaxf(lmax, __shfl_xor_sync(~0u, lmax, o));
    if ((tid & 31) == 0) red[tid >> 5] = lmax;
    __syncthreads();
    if (tid == 0) { float mx = red[0]; for (int w = 1; w < 8; w++) mx = fmaxf(mx, red[w]); red[0] = mx; }
    __syncthreads();
    float mx = red[0];
    __syncthreads();
    float lsum = 0.f;
    for (int m = tid; m < NN; m += 256) { float e = expf(row[m] - mx); row[m] = e; lsum += e; }
#pragma unroll
    for (int o = 16; o; o >>= 1) lsum += __shfl_xor_sync(~0u, lsum, o);
    if ((tid & 31) == 0) red[tid >> 5] = lsum;
    __syncthreads();
    if (tid == 0) { float s = 0.f; for (int w = 0; w < 8; w++) s += red[w]; ssum = s; }
    __syncthreads();
    float inv = 1.f / ssum;
    for (int m = tid; m < NP; m += 256) {
        float v = (m < NN) ? row[m] * inv : 0.f;
        bf16 h, l; bsplit(v, h, l);
        Ahi[n * NP + m] = h; Alo[n * NP + m] = l;
    }
}

__global__ void k_srcsplit(const float* __restrict__ src, bf16* __restrict__ hi,
                           bf16* __restrict__ lo) {
    int idx = blockIdx.x * 256 + threadIdx.x;
    if (idx >= NP * NC0) return;
    int n = idx / NC0, col = idx % NC0, t = col >> 6, b = col & 63;
    float v = (n < NN) ? src[((size_t)b * TT + t) * NN + n] : 0.f;
    bf16 h, l; bsplit(v, h, l);
    hi[idx] = h; lo[idx] = l;
}

// -------- tiled per-node weight pooling --------
__global__ void __launch_bounds__(256) k_nodewsplit(
    const float* __restrict__ E, const float* __restrict__ pool,
    bf16* __restrict__ Whi, bf16* __restrict__ Wlo, int COUT, int KDp, int layer) {
    __shared__ float Es[64][EMBD];
    __shared__ float Ps[EMBD][256];
    const int tid = threadIdx.x;
    const int colBase = blockIdx.x * 256;
    const int nBase = blockIdx.y * 64;
    const long RC = (long)KDp * COUT;

    for (int i = tid; i < 64 * EMBD; i += 256) {
        int nn = nBase + i / EMBD;
        Es[i / EMBD][i % EMBD] = (nn < NN) ? E[nn * EMBD + i % EMBD] : 0.f;
    }
    {
        int c = colBase + tid;
        int k = c / COUT, o = c % COUT;
        int row, ROWS;
        if (layer == 0) {
            ROWS = 130;
            if (k < 64) row = k + 1;
            else if (k < 128) row = k + 2;
            else if (k == 128) row = 0;
            else if (k == 129) row = 65;
            else row = -1;
        } else { ROWS = 256; row = k; }
#pragma unroll
        for (int d = 0; d < EMBD; d++)
            Ps[d][tid] = (row >= 0) ? pool[((long)d * ROWS + row) * COUT + o] : 0.f;
    }
    __syncthreads();

    float pv[EMBD];
#pragma unroll
    for (int d = 0; d < EMBD; d++) pv[d] = Ps[d][tid];
#pragma unroll 4
    for (int i = 0; i < 64; i++) {
        int nn = nBase + i;
        if (nn >= NN) break;
        float s = 0.f;
#pragma unroll
        for (int d = 0; d < EMBD; d++) s = fmaf(Es[i][d], pv[d], s);
        bf16 h, l; bsplit(s, h, l);
        size_t ix = (size_t)nn * RC + colBase + tid;
        Whi[ix] = h; Wlo[ix] = l;
    }
}

__global__ void k_nodew(const float* __restrict__ E, const float* __restrict__ pool,
                        float* __restrict__ out, int RC) {
    long idx = (long)blockIdx.x * 256 + threadIdx.x;
    if (idx >= (long)NN * RC) return;
    int n = (int)(idx / RC), rem = (int)(idx % RC);
    float s = 0.f;
#pragma unroll
    for (int d = 0; d < EMBD; d++) s = fmaf(E[n * EMBD + d], pool[(long)d * RC + rem], s);
    out[idx] = s;
}

// zero H (fp32, NN*NB) + 6 bf16 buffers (NP*NB each, as uint32 pairs)
__global__ void k_zeroH(float* H, bf16* Hhi, bf16* Hlo, bf16* AHhi, bf16* AHlo,
                        bf16* AZHhi, bf16* AZHlo) {
    int i = blockIdx.x * 256 + threadIdx.x;
    if (i < NN * NB) H[i] = 0.f;
    if (i < NP * NB / 2) {
        ((uint32_t*)Hhi)[i] = 0u; ((uint32_t*)Hlo)[i] = 0u;
        ((uint32_t*)AHhi)[i] = 0u; ((uint32_t*)AHlo)[i] = 0u;
        ((uint32_t*)AZHhi)[i] = 0u; ((uint32_t*)AZHlo)[i] = 0u;
    }
}

// -- dense split-bf16 MMA: C(hi,lo)=A@X. 64x128 tile, BK16, 128 thr, 2-stage --
// Separate input/output column strides so results can land inside ASEQ slots.
__global__ void __launch_bounds__(128) k_mma(const bf16* __restrict__ Ahi,
                                             const bf16* __restrict__ Alo,
                                             const bf16* __restrict__ Xhi,
                                             const bf16* __restrict__ Xlo,
                                             bf16* __restrict__ Chi,
                                             bf16* __restrict__ Clo,
                                             int NCin, int NCout) {
    __shared__ bf16 sAh[2][64 * 16], sAl[2][64 * 16];
    __shared__ bf16 sXh[2][16 * 128], sXl[2][16 * 128];
    const int tid = threadIdx.x, lane = tid & 31, warp = tid >> 5;
    const int rowBase = blockIdx.y * 64, colBase = blockIdx.x * 128;
    const int ar = tid >> 1, ac = (tid & 1) * 8;

    float acc[4][4][4];
#pragma unroll
    for (int i = 0; i < 4; i++)
#pragma unroll
        for (int j = 0; j < 4; j++)
#pragma unroll
            for (int q = 0; q < 4; q++) acc[i][j][q] = 0.f;

    auto prefetch = [&](int kt, int buf) {
        int k0 = kt * 16;
        cp16(&sAh[buf][ar * 16 + ac], Ahi + (size_t)(rowBase + ar) * NP + k0 + ac);
        cp16(&sAl[buf][ar * 16 + ac], Alo + (size_t)(rowBase + ar) * NP + k0 + ac);
#pragma unroll
        for (int i = 0; i < 2; i++) {
            int idx = tid + i * 128;
            int r = idx >> 4, cc = idx & 15;
            int dst = r * 128 + ((cc ^ r) & 15) * 8;
            cp16(&sXh[buf][dst], Xhi + (size_t)(k0 + r) * NCin + colBase + cc * 8);
            cp16(&sXl[buf][dst], Xlo + (size_t)(k0 + r) * NCin + colBase + cc * 8);
        }
        asm volatile("cp.async.commit_group;");
    };

    prefetch(0, 0);
    const int aoff = (lane & 15) * 32 + (lane >> 4) * 16;
    const int bk = lane & 15, bch = lane >> 4;

#pragma unroll 1
    for (int kt = 0; kt < 56; ++kt) {
        if (kt < 55) {
            prefetch(kt + 1, (kt + 1) & 1);
            asm volatile("cp.async.wait_group 1;");
        } else {
            asm volatile("cp.async.wait_group 0;");
        }
        __syncthreads();
        int buf = kt & 1;
        unsigned bAh = s2u(&sAh[buf][0]);
        unsigned bAl = s2u(&sAl[buf][0]);
        unsigned bXh = s2u(&sXh[buf][0]);
        unsigned bXl = s2u(&sXl[buf][0]);
        unsigned ah[4][4], al[4][4], bh[2][4], bl[2][4];
#pragma unroll
        for (int i = 0; i < 4; i++) {
            ldsm4(ah[i], bAh + i * 512 + aoff);
            ldsm4(al[i], bAl + i * 512 + aoff);
        }
#pragma unroll
        for (int j = 0; j < 2; j++) {
            int c = warp * 4 + j * 2 + bch;
            int cp = c ^ bk;
            ldsm4t(bh[j], bXh + bk * 256 + cp * 16);
            ldsm4t(bl[j], bXl + bk * 256 + cp * 16);
        }
#pragma unroll
        for (int i = 0; i < 4; i++)
#pragma unroll
            for (int j = 0; j < 2; j++)
#pragma unroll
                for (int h = 0; h < 2; h++) {
                    unsigned bph[2] = {bh[j][h * 2], bh[j][h * 2 + 1]};
                    unsigned bpl[2] = {bl[j][h * 2], bl[j][h * 2 + 1]};
                    float* cc = acc[i][j * 2 + h];
                    mma16816(cc, ah[i], bph);
                    mma16816(cc, ah[i], bpl);
                    mma16816(cc, al[i], bph);
                }
        __syncthreads();
    }
#pragma unroll
    for (int i = 0; i < 4; i++) {
        int r0 = rowBase + i * 16 + (lane >> 2);
#pragma unroll
        for (int jn = 0; jn < 4; jn++) {
            int c0 = colBase + warp * 32 + jn * 8 + (lane & 3) * 2;
            bf16 h0, l0, h1, l1;
            bsplit(acc[i][jn][0], h0, l0); bsplit(acc[i][jn][1], h1, l1);
            st2(&Chi[(size_t)r0 * NCout + c0], h0, h1);
            st2(&Clo[(size_t)r0 * NCout + c0], l0, l1);
            bsplit(acc[i][jn][2], h0, l0); bsplit(acc[i][jn][3], h1, l1);
            st2(&Chi[(size_t)(r0 + 8) * NCout + c0], h0, h1);
            st2(&Clo[(size_t)(r0 + 8) * NCout + c0], l0, l1);
        }
    }
}

// ---------------- per-node tensor-core GEMM + fused epilogue -----------------
template <int COUT, bool CAND, bool L0>
__global__ void __launch_bounds__(128) k_pn(
    const bf16* __restrict__ xh, const bf16* __restrict__ xl, size_t xstr, size_t xoff,
    const bf16* __restrict__ hh, const bf16* __restrict__ hl,
    const bf16* __restrict__ axh, const bf16* __restrict__ axl, size_t axstr, size_t axoff,
    const bf16* __restrict__ ahh, const bf16* __restrict__ ahl, size_t ahstr,
    const bf16* __restrict__ Whi, const bf16* __restrict__ Wlo,
    const float* __restrict__ Bias, float* __restrict__ R, float* __restrict__ Hfp,
    bf16* __restrict__ o1h, bf16* __restrict__ o1l,
    bf16* __restrict__ s1h, bf16* __restrict__ s1l, size_t seqOff) {
    constexpr int NCH = L0 ? 9 : 16;
    constexpr int SLICE = COUT / 4;
    constexpr int NJ = SLICE / 16;
    constexpr int WCH = COUT / 8;
    __shared__ bf16 sXh[2][64 * 24], sXl[2][64 * 24];
    __shared__ bf16 sWh[2][16 * COUT], sWl[2][16 * COUT];
    const int n = blockIdx.x, tid = threadIdx.x, lane = tid & 31, wn = tid >> 5;
    const bf16* Wh = Whi + (size_t)n * NCH * 16 * COUT;
    const bf16* Wl = Wlo + (size_t)n * NCH * 16 * COUT;

    float acc[4][NJ * 2][4];
#pragma unroll
    for (int i = 0; i < 4; i++)
#pragma unroll
        for (int j = 0; j < NJ * 2; j++)
#pragma unroll
            for (int q = 0; q < 4; q++) acc[i][j][q] = 0.f;

    auto prefetch = [&](int c) {
        int buf = c & 1;
#pragma unroll
        for (int q = tid; q < 16 * WCH; q += 128) {
            int r = q / WCH, cc = q % WCH;
            int dst = r * COUT + (cc ^ (r & (WCH - 1))) * 8;
            size_t src = (size_t)(c * 16 + r) * COUT + cc * 8;
            cp16(&sWh[buf][dst], Wh + src);
            cp16(&sWl[buf][dst], Wl + src);
        }
        if (L0 && c == 8) {
            if (tid < 64) {
                int b = tid;
                bf16 z = __float2bfloat16(0.f);
#pragma unroll
                for (int k = 0; k < 16; k++) { sXh[buf][b * 24 + k] = z; sXl[buf][b * 24 + k] = z; }
                sXh[buf][b * 24 + 0] = xh[n * xstr + xoff + b];
                sXl[buf][b * 24 + 0] = xl[n * xstr + xoff + b];
                sXh[buf][b * 24 + 1] = axh[n * axstr + axoff + b];
                sXl[buf][b * 24 + 1] = axl[n * axstr + axoff + b];
            }
        } else {
            int b = tid >> 1, half = tid & 1;
            const bf16 *ph, *pl; size_t base;
            if (L0) {
                if (c < 4) { ph = hh; pl = hl; base = (size_t)n * NB + b * 64 + c * 16 + half * 8; }
                else { ph = ahh; pl = ahl; base = (size_t)n * ahstr + b * 64 + (c - 4) * 16 + half * 8; }
            } else {
                int g = c >> 2, kl = (c & 3) * 16 + half * 8;
                if (g == 0) { ph = xh; pl = xl; base = (size_t)n * xstr + xoff + b * 64 + kl; }
                else if (g == 1) { ph = hh; pl = hl; base = (size_t)n * NB + b * 64 + kl; }
                else if (g == 2) { ph = axh; pl = axl; base = (size_t)n * axstr + axoff + b * 64 + kl; }
                else { ph = ahh; pl = ahl; base = (size_t)n * ahstr + b * 64 + kl; }
            }
            cp16(&sXh[buf][b * 24 + half * 8], ph + base);
            cp16(&sXl[buf][b * 24 + half * 8], pl + base);
        }
        asm volatile("cp.async.commit_group;");
    };

    prefetch(0);
#pragma unroll 1
    for (int c = 0; c < NCH; c++) {
        if (c + 1 < NCH) { prefetch(c + 1); asm volatile("cp.async.wait_group 1;"); }
        else asm volatile("cp.async.wait_group 0;");
        __syncthreads();
        int buf = c & 1;
        unsigned bXh = s2u(&sXh[buf][0]);
        unsigned bXl = s2u(&sXl[buf][0]);
        unsigned bWh = s2u(&sWh[buf][0]);
        unsigned bWl = s2u(&sWl[buf][0]);
        unsigned ah[4][4], al[4][4], bh[NJ][4], bl[NJ][4];
#pragma unroll
        for (int i = 0; i < 4; i++) {
            unsigned off = (i * 16 + (lane & 15)) * 48 + (lane >> 4) * 16;
            ldsm4(ah[i], bXh + off);
            ldsm4(al[i], bXl + off);
        }
        int bk = lane & 15;
#pragma unroll
        for (int j = 0; j < NJ; j++) {
            int cch = wn * (SLICE / 8) + j * 2 + (lane >> 4);
            unsigned off = bk * (COUT * 2) + (cch ^ (bk & (WCH - 1))) * 16;
            ldsm4t(bh[j], bWh + off);
            ldsm4t(bl[j], bWl + off);
        }
#pragma unroll
        for (int i = 0; i < 4; i++)
#pragma unroll
            for (int j = 0; j < NJ; j++)
#pragma unroll
                for (int h = 0; h < 2; h++) {
                    unsigned bph[2] = {bh[j][h * 2], bh[j][h * 2 + 1]};
                    unsigned bpl[2] = {bl[j][h * 2], bl[j][h * 2 + 1]};
                    float* cc = acc[i][j * 2 + h];
                    mma16816(cc, ah[i], bph);
                    mma16816(cc, ah[i], bpl);
                    mma16816(cc, al[i], bph);
                }
        __syncthreads();
    }

#pragma unroll
    for (int i = 0; i < 4; i++) {
        int b0 = i * 16 + (lane >> 2);
#pragma unroll
        for (int jn = 0; jn < NJ * 2; jn++) {
            int o = wn * SLICE + jn * 8 + (lane & 3) * 2;
#pragma unroll
            for (int rr = 0; rr < 2; rr++) {
                int b = b0 + rr * 8;
                size_t ix = (size_t)n * NB + b * 64;
                float v0 = acc[i][jn][rr * 2 + 0] + Bias[n * COUT + o];
                float v1 = acc[i][jn][rr * 2 + 1] + Bias[n * COUT + o + 1];
                if (!CAND) {
                    float s0 = 1.f / (1.f + expf(-v0));
                    float s1 = 1.f / (1.f + expf(-v1));
                    if (o < 64) {
                        float z0 = s0 * Hfp[ix + o], z1 = s1 * Hfp[ix + o + 1];
                        bf16 h0, l0, h1, l1;
                        bsplit(z0, h0, l0); bsplit(z1, h1, l1);
                        st2(&o1h[ix + o], h0, h1);
                        st2(&o1l[ix + o], l0, l1);
                    } else {
                        R[ix + o - 64] = s0; R[ix + o - 63] = s1;
                    }
                } else {
                    float hc0 = tanhf(v0), hc1 = tanhf(v1);
                    float r0 = R[ix + o], r1 = R[ix + o + 1];
                    float hn0 = r0 * Hfp[ix + o] + (1.f - r0) * hc0;
                    float hn1 = r1 * Hfp[ix + o + 1] + (1.f - r1) * hc1;
                    Hfp[ix + o] = hn0; Hfp[ix + o + 1] = hn1;
                    bf16 h0, l0, h1, l1;
                    bsplit(hn0, h0, l0); bsplit(hn1, h1, l1);
                    st2(&o1h[ix + o], h0, h1);
                    st2(&o1l[ix + o], l0, l1);
                    if (s1h) {
                        size_t s = (size_t)n * NCSEQ + seqOff + b * 64 + o;
                        st2(&s1h[s], h0, h1);
                        st2(&s1l[s], l0, l1);
                    }
                }
            }
        }
    }
}

__global__ void k_final(const float* __restrict__ H, const float* __restrict__ cw,
                        const float* __restrict__ cb, float* __restrict__ out) {
    int idx = blockIdx.x * 256 + threadIdx.x;
    if (idx >= BB * NN) return;
    int n = idx % NN, b = idx / NN;
    const float* h = H + (size_t)n * NB + b * 64;
    float hv[HID];
#pragma unroll
    for (int j = 0; j < HID; j++) hv[j] = h[j];
#pragma unroll
    for (int o = 0; o < TT; o++) {
        float s = cb[o];
#pragma unroll
        for (int j = 0; j < HID; j++) s = fmaf(hv[j], cw[o * HID + j], s);
        out[((size_t)b * TT + o) * NN + n] = s;
    }
}

extern "C" void kernel_launch(void* const* d_in, const int* in_sizes, int n_in,
                              void* d_out, int out_size) {
    const float* src = (const float*)d_in[0];
    const float* E = (const float*)d_in[1];
    const float* cw = (const float*)d_in[10];
    const float* cb = (const float*)d_in[11];
    float* out = (float*)d_out;

#define SYM(T, v, s) T* v; cudaGetSymbolAddress((void**)&v, s)
    SYM(bf16, Ahi, g_Ahi); SYM(bf16, Alo, g_Alo);
    SYM(bf16, X0hi, g_X0hi); SYM(bf16, X0lo, g_X0lo);
    SYM(bf16, AX0hi, g_AX0hi); SYM(bf16, AX0lo, g_AX0lo);
    SYM(bf16, WG0h, g_WG0h); SYM(bf16, WG0l, g_WG0l);
    SYM(bf16, WC0h, g_WC0h); SYM(bf16, WC0l, g_WC0l);
    SYM(bf16, WG1h, g_WG1h); SYM(bf16, WG1l, g_WG1l);
    SYM(bf16, WC1h, g_WC1h); SYM(bf16, WC1l, g_WC1l);
    SYM(float, Bg0, g_Bg0); SYM(float, Bc0, g_Bc0);
    SYM(float, Bg1, g_Bg1); SYM(float, Bc1, g_Bc1);
    SYM(float, H, g_H); SYM(float, R, g_R);
    SYM(bf16, Hhi, g_Hhi); SYM(bf16, Hlo, g_Hlo);
    SYM(bf16, ZHhi, g_ZHhi); SYM(bf16, ZHlo, g_ZHlo);
    SYM(bf16, AHhi, g_AHhi); SYM(bf16, AHlo, g_AHlo);
    SYM(bf16, AZHhi, g_AZHhi); SYM(bf16, AZHlo, g_AZHlo);
    SYM(bf16, Shi, g_SEQhi); SYM(bf16, Slo, g_SEQlo);
    SYM(bf16, AShi, g_ASEQhi); SYM(bf16, ASlo, g_ASEQlo);

    k_supports<<<NP, 256>>>(E, Ahi, Alo);
    k_srcsplit<<<(NP * NC0 + 255) / 256, 256>>>(src, X0hi, X0lo);
    k_nodewsplit<<<dim3(144 * 128 / 256, 14), 256>>>(E, (const float*)d_in[2], WG0h, WG0l, 128, 144, 0);
    k_nodew<<<((long)NN * 128 + 255) / 256, 256>>>(E, (const float*)d_in[3], Bg0, 128);
    k_nodewsplit<<<dim3(144 * 64 / 256, 14), 256>>>(E, (const float*)d_in[4], WC0h, WC0l, 64, 144, 0);
    k_nodew<<<((long)NN * 64 + 255) / 256, 256>>>(E, (const float*)d_in[5], Bc0, 64);
    k_nodewsplit<<<dim3(256 * 128 / 256, 14), 256>>>(E, (const float*)d_in[6], WG1h, WG1l, 128, 256, 1);
    k_nodew<<<((long)NN * 128 + 255) / 256, 256>>>(E, (const float*)d_in[7], Bg1, 128);
    k_nodewsplit<<<dim3(256 * 64 / 256, 14), 256>>>(E, (const float*)d_in[8], WC1h, WC1l, 64, 256, 1);
    k_nodew<<<((long)NN * 64 + 255) / 256, 256>>>(E, (const float*)d_in[9], Bc1, 64);

    k_mma<<<dim3(NC0 / 128, 14), 128>>>(Ahi, Alo, X0hi, X0lo, AX0hi, AX0lo, NC0, NC0);

    const int ZG = (NN * NB + 255) / 256;
    const dim3 GSTEP(NB / 128, 14);

    // layer 0: per-step A@H lands directly into ASEQ slot (t-1)
    k_zeroH<<<ZG, 256>>>(H, Hhi, Hlo, AHhi, AHlo, AZHhi, AZHlo);
    for (int t = 0; t < TT; t++) {
        const bf16* ahh = AHhi; const bf16* ahl = AHlo; size_t ahstr = NB;
        if (t > 0) {
            bf16* dsth = AShi + (size_t)(t - 1) * NB;
            bf16* dstl = ASlo + (size_t)(t - 1) * NB;
            k_mma<<<GSTEP, 128>>>(Ahi, Alo, Hhi, Hlo, dsth, dstl, NB, NCSEQ);
            ahh = dsth; ahl = dstl; ahstr = NCSEQ;
        }
        k_pn<128, false, true><<<NN, 128>>>(X0hi, X0lo, NC0, (size_t)t * 64,
            Hhi, Hlo, AX0hi, AX0lo, NC0, (size_t)t * 64, ahh, ahl, ahstr,
            WG0h, WG0l, Bg0, R, H, ZHhi, ZHlo, (bf16*)0, (bf16*)0, 0);
        if (t > 0)
            k_mma<<<GSTEP, 128>>>(Ahi, Alo, ZHhi, ZHlo, AZHhi, AZHlo, NB, NB);
        k_pn<64, true, true><<<NN, 128>>>(X0hi, X0lo, NC0, (size_t)t * 64,
            ZHhi, ZHlo, AX0hi, AX0lo, NC0, (size_t)t * 64, AZHhi, AZHlo, (size_t)NB,
            WC0h, WC0l, Bc0, R, H, Hhi, Hlo, Shi, Slo, (size_t)t * NB);
    }
    // last ASEQ slot (A@SEQ[11]) never produced by the loop
    k_mma<<<GSTEP, 128>>>(Ahi, Alo, Shi + (size_t)11 * NB, Slo + (size_t)11 * NB,
                          AShi + (size_t)11 * NB, ASlo + (size_t)11 * NB, NCSEQ, NCSEQ);

    // layer 1
    k_zeroH<<<ZG, 256>>>(H, Hhi, Hlo, AHhi, AHlo, AZHhi, AZHlo);
    for (int t = 0; t < TT; t++) {
        if (t > 0)
            k_mma<<<GSTEP, 128>>>(Ahi, Alo, Hhi, Hlo, AHhi, AHlo, NB, NB);
        k_pn<128, false, false><<<NN, 128>>>(Shi, Slo, NCSEQ, (size_t)t * NB,
            Hhi, Hlo, AShi, ASlo, NCSEQ, (size_t)t * NB, AHhi, AHlo, (size_t)NB,
            WG1h, WG1l, Bg1, R, H, ZHhi, ZHlo, (bf16*)0, (bf16*)0, 0);
        if (t > 0)
            k_mma<<<GSTEP, 128>>>(Ahi, Alo, ZHhi, ZHlo, AZHhi, AZHlo, NB, NB);
        k_pn<64, true, false><<<NN, 128>>>(Shi, Slo, NCSEQ, (size_t)t * NB,
            ZHhi, ZHlo, AShi, ASlo, NCSEQ, (size_t)t * NB, AZHhi, AZHlo, (size_t)NB,
            WC1h, WC1l, Bc1, R, H, Hhi, Hlo, (bf16*)0, (bf16*)0, 0);
    }

    k_final<<<(BB * NN + 255) / 256, 256>>>(H, cw, cb, out);
}

// round 13
// speedup vs baseline: 1.6678x; 1.1932x over previous
#include <cuda_runtime.h>
#include <cuda_bf16.h>
#include <math.h>
#include <stdint.h>

#define NN 883
#define NP 896
#define BB 64
#define TT 12
#define HID 64
#define EMBD 10
#define NB 4096
#define NCSEQ 49152
#define NC0 768
typedef __nv_bfloat16 bf16;

__device__ bf16 g_Ahi[NP * NP];
__device__ bf16 g_Alo[NP * NP];
__device__ bf16 g_X0hi[NP * NC0];
__device__ bf16 g_X0lo[NP * NC0];
__device__ bf16 g_AX0hi[NP * NC0];
__device__ bf16 g_AX0lo[NP * NC0];
__device__ bf16 g_WG0h[NN * 144 * 128];
__device__ bf16 g_WG0l[NN * 144 * 128];
__device__ bf16 g_WC0h[NN * 144 * 64];
__device__ bf16 g_WC0l[NN * 144 * 64];
__device__ bf16 g_WG1h[NN * 256 * 128];
__device__ bf16 g_WG1l[NN * 256 * 128];
__device__ bf16 g_WC1h[NN * 256 * 64];
__device__ bf16 g_WC1l[NN * 256 * 64];
__device__ float g_Bg0[NN * 128];
__device__ float g_Bc0[NN * 64];
__device__ float g_Bg1[NN * 128];
__device__ float g_Bc1[NN * 64];
// layer-0 state
__device__ float g_H[NN * NB];
__device__ float g_R[NN * NB];
__device__ bf16 g_Hhi[NP * NB];
__device__ bf16 g_Hlo[NP * NB];
__device__ bf16 g_ZHhi[NP * NB];
__device__ bf16 g_ZHlo[NP * NB];
__device__ bf16 g_AHhi[NP * NB];
__device__ bf16 g_AHlo[NP * NB];
__device__ bf16 g_AZHhi[NP * NB];
__device__ bf16 g_AZHlo[NP * NB];
// layer-1 private state (stream-2)
__device__ float g_H2[NN * NB];
__device__ float g_R2[NN * NB];
__device__ bf16 g_H2hi[NP * NB];
__device__ bf16 g_H2lo[NP * NB];
__device__ bf16 g_ZH2hi[NP * NB];
__device__ bf16 g_ZH2lo[NP * NB];
__device__ bf16 g_AH2hi[NP * NB];
__device__ bf16 g_AH2lo[NP * NB];
__device__ bf16 g_AZH2hi[NP * NB];
__device__ bf16 g_AZH2lo[NP * NB];
__device__ bf16 g_SEQhi[(size_t)NP * NCSEQ];
__device__ bf16 g_SEQlo[(size_t)NP * NCSEQ];
__device__ bf16 g_ASEQhi[(size_t)NP * NCSEQ];
__device__ bf16 g_ASEQlo[(size_t)NP * NCSEQ];

__device__ __forceinline__ void bsplit(float v, bf16& hi, bf16& lo) {
    hi = __float2bfloat16_rn(v);
    lo = __float2bfloat16_rn(v - __bfloat162float(hi));
}
__device__ __forceinline__ unsigned s2u(const void* p) {
    return (unsigned)__cvta_generic_to_shared(p);
}
__device__ __forceinline__ void cp16(void* s, const void* g) {
    asm volatile("cp.async.cg.shared.global [%0], [%1], 16;" :: "r"(s2u(s)), "l"(g));
}
__device__ __forceinline__ void ldsm4(unsigned* r, unsigned a) {
    asm volatile("ldmatrix.sync.aligned.m8n8.x4.shared.b16 {%0,%1,%2,%3}, [%4];"
                 : "=r"(r[0]), "=r"(r[1]), "=r"(r[2]), "=r"(r[3]) : "r"(a));
}
__device__ __forceinline__ void ldsm4t(unsigned* r, unsigned a) {
    asm volatile("ldmatrix.sync.aligned.m8n8.x4.trans.shared.b16 {%0,%1,%2,%3}, [%4];"
                 : "=r"(r[0]), "=r"(r[1]), "=r"(r[2]), "=r"(r[3]) : "r"(a));
}
__device__ __forceinline__ void mma16816(float* c, const unsigned* a, const unsigned* b) {
    asm volatile(
        "mma.sync.aligned.m16n8k16.row.col.f32.bf16.bf16.f32 "
        "{%0,%1,%2,%3},{%4,%5,%6,%7},{%8,%9},{%0,%1,%2,%3};"
        : "+f"(c[0]), "+f"(c[1]), "+f"(c[2]), "+f"(c[3])
        : "r"(a[0]), "r"(a[1]), "r"(a[2]), "r"(a[3]), "r"(b[0]), "r"(b[1]));
}
__device__ __forceinline__ void st2(bf16* p, bf16 a, bf16 b) {
    __nv_bfloat162 v; v.x = a; v.y = b;
    *(__nv_bfloat162*)p = v;
}

// ---------------- adjacency ----------------
__global__ void __launch_bounds__(256) k_supports(const float* __restrict__ E,
                                                  bf16* __restrict__ Ahi,
                                                  bf16* __restrict__ Alo) {
    int n = blockIdx.x, tid = threadIdx.x;
    if (n >= NN) {
        for (int m = tid; m < NP; m += 256) { Ahi[n * NP + m] = __float2bfloat16(0.f); Alo[n * NP + m] = __float2bfloat16(0.f); }
        return;
    }
    __shared__ float row[NN];
    __shared__ float red[8];
    __shared__ float ssum;
    float en[EMBD];
#pragma unroll
    for (int d = 0; d < EMBD; d++) en[d] = E[n * EMBD + d];
    float lmax = -1e30f;
    for (int m = tid; m < NN; m += 256) {
        float s = 0.f;
#pragma unroll
        for (int d = 0; d < EMBD; d++) s = fmaf(en[d], E[m * EMBD + d], s);
        s = fmaxf(s, 0.f);
        row[m] = s;
        lmax = fmaxf(lmax, s);
    }
#pragma unroll
    for (int o = 16; o; o >>= 1) lmax = fmaxf(lmax, __shfl_xor_sync(~0u, lmax, o));
    if ((tid & 31) == 0) red[tid >> 5] = lmax;
    __syncthreads();
    if (tid == 0) { float mx = red[0]; for (int w = 1; w < 8; w++) mx = fmaxf(mx, red[w]); red[0] = mx; }
    __syncthreads();
    float mx = red[0];
    __syncthreads();
    float lsum = 0.f;
    for (int m = tid; m < NN; m += 256) { float e = expf(row[m] - mx); row[m] = e; lsum += e; }
#pragma unroll
    for (int o = 16; o; o >>= 1) lsum += __shfl_xor_sync(~0u, lsum, o);
    if ((tid & 31) == 0) red[tid >> 5] = lsum;
    __syncthreads();
    if (tid == 0) { float s = 0.f; for (int w = 0; w < 8; w++) s += red[w]; ssum = s; }
    __syncthreads();
    float inv = 1.f / ssum;
    for (int m = tid; m < NP; m += 256) {
        float v = (m < NN) ? row[m] * inv : 0.f;
        bf16 h, l; bsplit(v, h, l);
        Ahi[n * NP + m] = h; Alo[n * NP + m] = l;
    }
}

__global__ void k_srcsplit(const float* __restrict__ src, bf16* __restrict__ hi,
                           bf16* __restrict__ lo) {
    int idx = blockIdx.x * 256 + threadIdx.x;
    if (idx >= NP * NC0) return;
    int n = idx / NC0, col = idx % NC0, t = col >> 6, b = col & 63;
    float v = (n < NN) ? src[((size_t)b * TT + t) * NN + n] : 0.f;
    bf16 h, l; bsplit(v, h, l);
    hi[idx] = h; lo[idx] = l;
}

// -------- tiled per-node weight pooling --------
__global__ void __launch_bounds__(256) k_nodewsplit(
    const float* __restrict__ E, const float* __restrict__ pool,
    bf16* __restrict__ Whi, bf16* __restrict__ Wlo, int COUT, int KDp, int layer) {
    __shared__ float Es[64][EMBD];
    __shared__ float Ps[EMBD][256];
    const int tid = threadIdx.x;
    const int colBase = blockIdx.x * 256;
    const int nBase = blockIdx.y * 64;
    const long RC = (long)KDp * COUT;

    for (int i = tid; i < 64 * EMBD; i += 256) {
        int nn = nBase + i / EMBD;
        Es[i / EMBD][i % EMBD] = (nn < NN) ? E[nn * EMBD + i % EMBD] : 0.f;
    }
    {
        int c = colBase + tid;
        int k = c / COUT, o = c % COUT;
        int row, ROWS;
        if (layer == 0) {
            ROWS = 130;
            if (k < 64) row = k + 1;
            else if (k < 128) row = k + 2;
            else if (k == 128) row = 0;
            else if (k == 129) row = 65;
            else row = -1;
        } else { ROWS = 256; row = k; }
#pragma unroll
        for (int d = 0; d < EMBD; d++)
            Ps[d][tid] = (row >= 0) ? pool[((long)d * ROWS + row) * COUT + o] : 0.f;
    }
    __syncthreads();

    float pv[EMBD];
#pragma unroll
    for (int d = 0; d < EMBD; d++) pv[d] = Ps[d][tid];
#pragma unroll 4
    for (int i = 0; i < 64; i++) {
        int nn = nBase + i;
        if (nn >= NN) break;
        float s = 0.f;
#pragma unroll
        for (int d = 0; d < EMBD; d++) s = fmaf(Es[i][d], pv[d], s);
        bf16 h, l; bsplit(s, h, l);
        size_t ix = (size_t)nn * RC + colBase + tid;
        Whi[ix] = h; Wlo[ix] = l;
    }
}

__global__ void k_nodew(const float* __restrict__ E, const float* __restrict__ pool,
                        float* __restrict__ out, int RC) {
    long idx = (long)blockIdx.x * 256 + threadIdx.x;
    if (idx >= (long)NN * RC) return;
    int n = (int)(idx / RC), rem = (int)(idx % RC);
    float s = 0.f;
#pragma unroll
    for (int d = 0; d < EMBD; d++) s = fmaf(E[n * EMBD + d], pool[(long)d * RC + rem], s);
    out[idx] = s;
}

// zero H (fp32, NN*NB) + 6 bf16 buffers (NP*NB each, as uint32 pairs)
__global__ void k_zeroH(float* H, bf16* Hhi, bf16* Hlo, bf16* AHhi, bf16* AHlo,
                        bf16* AZHhi, bf16* AZHlo) {
    int i = blockIdx.x * 256 + threadIdx.x;
    if (i < NN * NB) H[i] = 0.f;
    if (i < NP * NB / 2) {
        ((uint32_t*)Hhi)[i] = 0u; ((uint32_t*)Hlo)[i] = 0u;
        ((uint32_t*)AHhi)[i] = 0u; ((uint32_t*)AHlo)[i] = 0u;
        ((uint32_t*)AZHhi)[i] = 0u; ((uint32_t*)AZHlo)[i] = 0u;
    }
}

// -- dense split-bf16 MMA: C(hi,lo)=A@X. 64x128 tile, BK16, 128 thr, 2-stage --
__global__ void __launch_bounds__(128) k_mma(const bf16* __restrict__ Ahi,
                                             const bf16* __restrict__ Alo,
                                             const bf16* __restrict__ Xhi,
                                             const bf16* __restrict__ Xlo,
                                             bf16* __restrict__ Chi,
                                             bf16* __restrict__ Clo,
                                             int NCin, int NCout) {
    __shared__ bf16 sAh[2][64 * 16], sAl[2][64 * 16];
    __shared__ bf16 sXh[2][16 * 128], sXl[2][16 * 128];
    const int tid = threadIdx.x, lane = tid & 31, warp = tid >> 5;
    const int rowBase = blockIdx.y * 64, colBase = blockIdx.x * 128;
    const int ar = tid >> 1, ac = (tid & 1) * 8;

    float acc[4][4][4];
#pragma unroll
    for (int i = 0; i < 4; i++)
#pragma unroll
        for (int j = 0; j < 4; j++)
#pragma unroll
            for (int q = 0; q < 4; q++) acc[i][j][q] = 0.f;

    auto prefetch = [&](int kt, int buf) {
        int k0 = kt * 16;
        cp16(&sAh[buf][ar * 16 + ac], Ahi + (size_t)(rowBase + ar) * NP + k0 + ac);
        cp16(&sAl[buf][ar * 16 + ac], Alo + (size_t)(rowBase + ar) * NP + k0 + ac);
#pragma unroll
        for (int i = 0; i < 2; i++) {
            int idx = tid + i * 128;
            int r = idx >> 4, cc = idx & 15;
            int dst = r * 128 + ((cc ^ r) & 15) * 8;
            cp16(&sXh[buf][dst], Xhi + (size_t)(k0 + r) * NCin + colBase + cc * 8);
            cp16(&sXl[buf][dst], Xlo + (size_t)(k0 + r) * NCin + colBase + cc * 8);
        }
        asm volatile("cp.async.commit_group;");
    };

    prefetch(0, 0);
    const int aoff = (lane & 15) * 32 + (lane >> 4) * 16;
    const int bk = lane & 15, bch = lane >> 4;

#pragma unroll 1
    for (int kt = 0; kt < 56; ++kt) {
        if (kt < 55) {
            prefetch(kt + 1, (kt + 1) & 1);
            asm volatile("cp.async.wait_group 1;");
        } else {
            asm volatile("cp.async.wait_group 0;");
        }
        __syncthreads();
        int buf = kt & 1;
        unsigned bAh = s2u(&sAh[buf][0]);
        unsigned bAl = s2u(&sAl[buf][0]);
        unsigned bXh = s2u(&sXh[buf][0]);
        unsigned bXl = s2u(&sXl[buf][0]);
        unsigned ah[4][4], al[4][4], bh[2][4], bl[2][4];
#pragma unroll
        for (int i = 0; i < 4; i++) {
            ldsm4(ah[i], bAh + i * 512 + aoff);
            ldsm4(al[i], bAl + i * 512 + aoff);
        }
#pragma unroll
        for (int j = 0; j < 2; j++) {
            int c = warp * 4 + j * 2 + bch;
            int cp = c ^ bk;
            ldsm4t(bh[j], bXh + bk * 256 + cp * 16);
            ldsm4t(bl[j], bXl + bk * 256 + cp * 16);
        }
#pragma unroll
        for (int i = 0; i < 4; i++)
#pragma unroll
            for (int j = 0; j < 2; j++)
#pragma unroll
                for (int h = 0; h < 2; h++) {
                    unsigned bph[2] = {bh[j][h * 2], bh[j][h * 2 + 1]};
                    unsigned bpl[2] = {bl[j][h * 2], bl[j][h * 2 + 1]};
                    float* cc = acc[i][j * 2 + h];
                    mma16816(cc, ah[i], bph);
                    mma16816(cc, ah[i], bpl);
                    mma16816(cc, al[i], bph);
                }
        __syncthreads();
    }
#pragma unroll
    for (int i = 0; i < 4; i++) {
        int r0 = rowBase + i * 16 + (lane >> 2);
#pragma unroll
        for (int jn = 0; jn < 4; jn++) {
            int c0 = colBase + warp * 32 + jn * 8 + (lane & 3) * 2;
            bf16 h0, l0, h1, l1;
            bsplit(acc[i][jn][0], h0, l0); bsplit(acc[i][jn][1], h1, l1);
            st2(&Chi[(size_t)r0 * NCout + c0], h0, h1);
            st2(&Clo[(size_t)r0 * NCout + c0], l0, l1);
            bsplit(acc[i][jn][2], h0, l0); bsplit(acc[i][jn][3], h1, l1);
            st2(&Chi[(size_t)(r0 + 8) * NCout + c0], h0, h1);
            st2(&Clo[(size_t)(r0 + 8) * NCout + c0], l0, l1);
        }
    }
}

// ---------------- per-node tensor-core GEMM + fused epilogue -----------------
template <int COUT, bool CAND, bool L0>
__global__ void __launch_bounds__(128) k_pn(
    const bf16* __restrict__ xh, const bf16* __restrict__ xl, size_t xstr, size_t xoff,
    const bf16* __restrict__ hh, const bf16* __restrict__ hl,
    const bf16* __restrict__ axh, const bf16* __restrict__ axl, size_t axstr, size_t axoff,
    const bf16* __restrict__ ahh, const bf16* __restrict__ ahl, size_t ahstr,
    const bf16* __restrict__ Whi, const bf16* __restrict__ Wlo,
    const float* __restrict__ Bias, float* __restrict__ R, float* __restrict__ Hfp,
    bf16* __restrict__ o1h, bf16* __restrict__ o1l,
    bf16* __restrict__ s1h, bf16* __restrict__ s1l, size_t seqOff) {
    constexpr int NCH = L0 ? 9 : 16;
    constexpr int SLICE = COUT / 4;
    constexpr int NJ = SLICE / 16;
    constexpr int WCH = COUT / 8;
    __shared__ bf16 sXh[2][64 * 24], sXl[2][64 * 24];
    __shared__ bf16 sWh[2][16 * COUT], sWl[2][16 * COUT];
    const int n = blockIdx.x, tid = threadIdx.x, lane = tid & 31, wn = tid >> 5;
    const bf16* Wh = Whi + (size_t)n * NCH * 16 * COUT;
    const bf16* Wl = Wlo + (size_t)n * NCH * 16 * COUT;

    float acc[4][NJ * 2][4];
#pragma unroll
    for (int i = 0; i < 4; i++)
#pragma unroll
        for (int j = 0; j < NJ * 2; j++)
#pragma unroll
            for (int q = 0; q < 4; q++) acc[i][j][q] = 0.f;

    auto prefetch = [&](int c) {
        int buf = c & 1;
#pragma unroll
        for (int q = tid; q < 16 * WCH; q += 128) {
            int r = q / WCH, cc = q % WCH;
            int dst = r * COUT + (cc ^ (r & (WCH - 1))) * 8;
            size_t src = (size_t)(c * 16 + r) * COUT + cc * 8;
            cp16(&sWh[buf][dst], Wh + src);
            cp16(&sWl[buf][dst], Wl + src);
        }
        if (L0 && c == 8) {
            if (tid < 64) {
                int b = tid;
                bf16 z = __float2bfloat16(0.f);
#pragma unroll
                for (int k = 0; k < 16; k++) { sXh[buf][b * 24 + k] = z; sXl[buf][b * 24 + k] = z; }
                sXh[buf][b * 24 + 0] = xh[n * xstr + xoff + b];
                sXl[buf][b * 24 + 0] = xl[n * xstr + xoff + b];
                sXh[buf][b * 24 + 1] = axh[n * axstr + axoff + b];
                sXl[buf][b * 24 + 1] = axl[n * axstr + axoff + b];
            }
        } else {
            int b = tid >> 1, half = tid & 1;
            const bf16 *ph, *pl; size_t base;
            if (L0) {
                if (c < 4) { ph = hh; pl = hl; base = (size_t)n * NB + b * 64 + c * 16 + half * 8; }
                else { ph = ahh; pl = ahl; base = (size_t)n * ahstr + b * 64 + (c - 4) * 16 + half * 8; }
            } else {
                int g = c >> 2, kl = (c & 3) * 16 + half * 8;
                if (g == 0) { ph = xh; pl = xl; base = (size_t)n * xstr + xoff + b * 64 + kl; }
                else if (g == 1) { ph = hh; pl = hl; base = (size_t)n * NB + b * 64 + kl; }
                else if (g == 2) { ph = axh; pl = axl; base = (size_t)n * axstr + axoff + b * 64 + kl; }
                else { ph = ahh; pl = ahl; base = (size_t)n * ahstr + b * 64 + kl; }
            }
            cp16(&sXh[buf][b * 24 + half * 8], ph + base);
            cp16(&sXl[buf][b * 24 + half * 8], pl + base);
        }
        asm volatile("cp.async.commit_group;");
    };

    prefetch(0);
#pragma unroll 1
    for (int c = 0; c < NCH; c++) {
        if (c + 1 < NCH) { prefetch(c + 1); asm volatile("cp.async.wait_group 1;"); }
        else asm volatile("cp.async.wait_group 0;");
        __syncthreads();
        int buf = c & 1;
        unsigned bXh = s2u(&sXh[buf][0]);
        unsigned bXl = s2u(&sXl[buf][0]);
        unsigned bWh = s2u(&sWh[buf][0]);
        unsigned bWl = s2u(&sWl[buf][0]);
        unsigned ah[4][4], al[4][4], bh[NJ][4], bl[NJ][4];
#pragma unroll
        for (int i = 0; i < 4; i++) {
            unsigned off = (i * 16 + (lane & 15)) * 48 + (lane >> 4) * 16;
            ldsm4(ah[i], bXh + off);
            ldsm4(al[i], bXl + off);
        }
        int bk = lane & 15;
#pragma unroll
        for (int j = 0; j < NJ; j++) {
            int cch = wn * (SLICE / 8) + j * 2 + (lane >> 4);
            unsigned off = bk * (COUT * 2) + (cch ^ (bk & (WCH - 1))) * 16;
            ldsm4t(bh[j], bWh + off);
            ldsm4t(bl[j], bWl + off);
        }
#pragma unroll
        for (int i = 0; i < 4; i++)
#pragma unroll
            for (int j = 0; j < NJ; j++)
#pragma unroll
                for (int h = 0; h < 2; h++) {
                    unsigned bph[2] = {bh[j][h * 2], bh[j][h * 2 + 1]};
                    unsigned bpl[2] = {bl[j][h * 2], bl[j][h * 2 + 1]};
                    float* cc = acc[i][j * 2 + h];
                    mma16816(cc, ah[i], bph);
                    mma16816(cc, ah[i], bpl);
                    mma16816(cc, al[i], bph);
                }
        __syncthreads();
    }

#pragma unroll
    for (int i = 0; i < 4; i++) {
        int b0 = i * 16 + (lane >> 2);
#pragma unroll
        for (int jn = 0; jn < NJ * 2; jn++) {
            int o = wn * SLICE + jn * 8 + (lane & 3) * 2;
#pragma unroll
            for (int rr = 0; rr < 2; rr++) {
                int b = b0 + rr * 8;
                size_t ix = (size_t)n * NB + b * 64;
                float v0 = acc[i][jn][rr * 2 + 0] + Bias[n * COUT + o];
                float v1 = acc[i][jn][rr * 2 + 1] + Bias[n * COUT + o + 1];
                if (!CAND) {
                    float s0 = 1.f / (1.f + expf(-v0));
                    float s1 = 1.f / (1.f + expf(-v1));
                    if (o < 64) {
                        float z0 = s0 * Hfp[ix + o], z1 = s1 * Hfp[ix + o + 1];
                        bf16 h0, l0, h1, l1;
                        bsplit(z0, h0, l0); bsplit(z1, h1, l1);
                        st2(&o1h[ix + o], h0, h1);
                        st2(&o1l[ix + o], l0, l1);
                    } else {
                        R[ix + o - 64] = s0; R[ix + o - 63] = s1;
                    }
                } else {
                    float hc0 = tanhf(v0), hc1 = tanhf(v1);
                    float r0 = R[ix + o], r1 = R[ix + o + 1];
                    float hn0 = r0 * Hfp[ix + o] + (1.f - r0) * hc0;
                    float hn1 = r1 * Hfp[ix + o + 1] + (1.f - r1) * hc1;
                    Hfp[ix + o] = hn0; Hfp[ix + o + 1] = hn1;
                    bf16 h0, l0, h1, l1;
                    bsplit(hn0, h0, l0); bsplit(hn1, h1, l1);
                    st2(&o1h[ix + o], h0, h1);
                    st2(&o1l[ix + o], l0, l1);
                    if (s1h) {
                        size_t s = (size_t)n * NCSEQ + seqOff + b * 64 + o;
                        st2(&s1h[s], h0, h1);
                        st2(&s1l[s], l0, l1);
                    }
                }
            }
        }
    }
}

__global__ void k_final(const float* __restrict__ H, const float* __restrict__ cw,
                        const float* __restrict__ cb, float* __restrict__ out) {
    int idx = blockIdx.x * 256 + threadIdx.x;
    if (idx >= BB * NN) return;
    int n = idx % NN, b = idx / NN;
    const float* h = H + (size_t)n * NB + b * 64;
    float hv[HID];
#pragma unroll
    for (int j = 0; j < HID; j++) hv[j] = h[j];
#pragma unroll
    for (int o = 0; o < TT; o++) {
        float s = cb[o];
#pragma unroll
        for (int j = 0; j < HID; j++) s = fmaf(hv[j], cw[o * HID + j], s);
        out[((size_t)b * TT + o) * NN + n] = s;
    }
}

extern "C" void kernel_launch(void* const* d_in, const int* in_sizes, int n_in,
                              void* d_out, int out_size) {
    const float* src = (const float*)d_in[0];
    const float* E = (const float*)d_in[1];
    const float* cw = (const float*)d_in[10];
    const float* cb = (const float*)d_in[11];
    float* out = (float*)d_out;

#define SYM(T, v, s) T* v; cudaGetSymbolAddress((void**)&v, s)
    SYM(bf16, Ahi, g_Ahi); SYM(bf16, Alo, g_Alo);
    SYM(bf16, X0hi, g_X0hi); SYM(bf16, X0lo, g_X0lo);
    SYM(bf16, AX0hi, g_AX0hi); SYM(bf16, AX0lo, g_AX0lo);
    SYM(bf16, WG0h, g_WG0h); SYM(bf16, WG0l, g_WG0l);
    SYM(bf16, WC0h, g_WC0h); SYM(bf16, WC0l, g_WC0l);
    SYM(bf16, WG1h, g_WG1h); SYM(bf16, WG1l, g_WG1l);
    SYM(bf16, WC1h, g_WC1h); SYM(bf16, WC1l, g_WC1l);
    SYM(float, Bg0, g_Bg0); SYM(float, Bc0, g_Bc0);
    SYM(float, Bg1, g_Bg1); SYM(float, Bc1, g_Bc1);
    SYM(float, H, g_H); SYM(float, R, g_R);
    SYM(bf16, Hhi, g_Hhi); SYM(bf16, Hlo, g_Hlo);
    SYM(bf16, ZHhi, g_ZHhi); SYM(bf16, ZHlo, g_ZHlo);
    SYM(bf16, AHhi, g_AHhi); SYM(bf16, AHlo, g_AHlo);
    SYM(bf16, AZHhi, g_AZHhi); SYM(bf16, AZHlo, g_AZHlo);
    SYM(float, H2, g_H2); SYM(float, R2, g_R2);
    SYM(bf16, H2hi, g_H2hi); SYM(bf16, H2lo, g_H2lo);
    SYM(bf16, ZH2hi, g_ZH2hi); SYM(bf16, ZH2lo, g_ZH2lo);
    SYM(bf16, AH2hi, g_AH2hi); SYM(bf16, AH2lo, g_AH2lo);
    SYM(bf16, AZH2hi, g_AZH2hi); SYM(bf16, AZH2lo, g_AZH2lo);
    SYM(bf16, Shi, g_SEQhi); SYM(bf16, Slo, g_SEQlo);
    SYM(bf16, AShi, g_ASEQhi); SYM(bf16, ASlo, g_ASEQlo);

    // second stream + events (fork/join works both live and under capture)
    cudaStream_t s0 = 0, s2;
    cudaStreamCreateWithFlags(&s2, cudaStreamNonBlocking);
    cudaEvent_t ev[TT], evFork, evJoin;
    for (int i = 0; i < TT; i++) cudaEventCreateWithFlags(&ev[i], cudaEventDisableTiming);
    cudaEventCreateWithFlags(&evFork, cudaEventDisableTiming);
    cudaEventCreateWithFlags(&evJoin, cudaEventDisableTiming);

    k_supports<<<NP, 256, 0, s0>>>(E, Ahi, Alo);
    k_srcsplit<<<(NP * NC0 + 255) / 256, 256, 0, s0>>>(src, X0hi, X0lo);
    k_nodewsplit<<<dim3(144 * 128 / 256, 14), 256, 0, s0>>>(E, (const float*)d_in[2], WG0h, WG0l, 128, 144, 0);
    k_nodew<<<((long)NN * 128 + 255) / 256, 256, 0, s0>>>(E, (const float*)d_in[3], Bg0, 128);
    k_nodewsplit<<<dim3(144 * 64 / 256, 14), 256, 0, s0>>>(E, (const float*)d_in[4], WC0h, WC0l, 64, 144, 0);
    k_nodew<<<((long)NN * 64 + 255) / 256, 256, 0, s0>>>(E, (const float*)d_in[5], Bc0, 64);
    k_nodewsplit<<<dim3(256 * 128 / 256, 14), 256, 0, s0>>>(E, (const float*)d_in[6], WG1h, WG1l, 128, 256, 1);
    k_nodew<<<((long)NN * 128 + 255) / 256, 256, 0, s0>>>(E, (const float*)d_in[7], Bg1, 128);
    k_nodewsplit<<<dim3(256 * 64 / 256, 14), 256, 0, s0>>>(E, (const float*)d_in[8], WC1h, WC1l, 64, 256, 1);
    k_nodew<<<((long)NN * 64 + 255) / 256, 256, 0, s0>>>(E, (const float*)d_in[9], Bc1, 64);

    k_mma<<<dim3(NC0 / 128, 14), 128, 0, s0>>>(Ahi, Alo, X0hi, X0lo, AX0hi, AX0lo, NC0, NC0);

    const int ZG = (NN * NB + 255) / 256;
    const dim3 GSTEP(NB / 128, 14);

    // fork: stream2 branch starts after prologue
    cudaEventRecord(evFork, s0);
    cudaStreamWaitEvent(s2, evFork, 0);
    k_zeroH<<<ZG, 256, 0, s2>>>(H2, H2hi, H2lo, AH2hi, AH2lo, AZH2hi, AZH2lo);

    // layer 0 on s0; per-step A@H lands directly into ASEQ slot (t-1)
    k_zeroH<<<ZG, 256, 0, s0>>>(H, Hhi, Hlo, AHhi, AHlo, AZHhi, AZHlo);
    for (int t = 0; t < TT; t++) {
        const bf16* ahh = AHhi; const bf16* ahl = AHlo; size_t ahstr = NB;
        if (t > 0) {
            bf16* dsth = AShi + (size_t)(t - 1) * NB;
            bf16* dstl = ASlo + (size_t)(t - 1) * NB;
            k_mma<<<GSTEP, 128, 0, s0>>>(Ahi, Alo, Hhi, Hlo, dsth, dstl, NB, NCSEQ);
            cudaEventRecord(ev[t - 1], s0);   // SEQ[t-1] (earlier) + ASEQ[t-1] now final
            ahh = dsth; ahl = dstl; ahstr = NCSEQ;
        }
        k_pn<128, false, true><<<NN, 128, 0, s0>>>(X0hi, X0lo, NC0, (size_t)t * 64,
            Hhi, Hlo, AX0hi, AX0lo, NC0, (size_t)t * 64, ahh, ahl, ahstr,
            WG0h, WG0l, Bg0, R, H, ZHhi, ZHlo, (bf16*)0, (bf16*)0, 0);
        if (t > 0)
            k_mma<<<GSTEP, 128, 0, s0>>>(Ahi, Alo, ZHhi, ZHlo, AZHhi, AZHlo, NB, NB);
        k_pn<64, true, true><<<NN, 128, 0, s0>>>(X0hi, X0lo, NC0, (size_t)t * 64,
            ZHhi, ZHlo, AX0hi, AX0lo, NC0, (size_t)t * 64, AZHhi, AZHlo, (size_t)NB,
            WC0h, WC0l, Bc0, R, H, Hhi, Hlo, Shi, Slo, (size_t)t * NB);
    }
    k_mma<<<GSTEP, 128, 0, s0>>>(Ahi, Alo, Shi + (size_t)11 * NB, Slo + (size_t)11 * NB,
                                 AShi + (size_t)11 * NB, ASlo + (size_t)11 * NB, NCSEQ, NCSEQ);
    cudaEventRecord(ev[11], s0);

    // layer 1 on s2, gated per step
    for (int t = 0; t < TT; t++) {
        cudaStreamWaitEvent(s2, ev[t], 0);
        if (t > 0)
            k_mma<<<GSTEP, 128, 0, s2>>>(Ahi, Alo, H2hi, H2lo, AH2hi, AH2lo, NB, NB);
        k_pn<128, false, false><<<NN, 128, 0, s2>>>(Shi, Slo, NCSEQ, (size_t)t * NB,
            H2hi, H2lo, AShi, ASlo, NCSEQ, (size_t)t * NB, AH2hi, AH2lo, (size_t)NB,
            WG1h, WG1l, Bg1, R2, H2, ZH2hi, ZH2lo, (bf16*)0, (bf16*)0, 0);
        if (t > 0)
            k_mma<<<GSTEP, 128, 0, s2>>>(Ahi, Alo, ZH2hi, ZH2lo, AZH2hi, AZH2lo, NB, NB);
        k_pn<64, true, false><<<NN, 128, 0, s2>>>(Shi, Slo, NCSEQ, (size_t)t * NB,
            ZH2hi, ZH2lo, AShi, ASlo, NCSEQ, (size_t)t * NB, AZH2hi, AZH2lo, (size_t)NB,
            WC1h, WC1l, Bc1, R2, H2, H2hi, H2lo, (bf16*)0, (bf16*)0, 0);
    }
    k_final<<<(BB * NN + 255) / 256, 256, 0, s2>>>(H2, cw, cb, out);

    // join back to the main stream
    cudaEventRecord(evJoin, s2);
    cudaStreamWaitEvent(s0, evJoin, 0);

    // destroy only when not capturing (destroy mid-capture would invalidate it)
    cudaStreamCaptureStatus st = cudaStreamCaptureStatusNone;
    cudaStreamIsCapturing(s0, &st);
    if (st == cudaStreamCaptureStatusNone) {
        cudaStreamDestroy(s2);
        for (int i = 0; i < TT; i++) cudaEventDestroy(ev[i]);
        cudaEventDestroy(evFork);
        cudaEventDestroy(evJoin);
    }
}

// round 14
// speedup vs baseline: 1.6713x; 1.0021x over previous
#include <cuda_runtime.h>
#include <cuda_bf16.h>
#include <math.h>
#include <stdint.h>

#define NN 883
#define NP 896
#define BB 64
#define TT 12
#define HID 64
#define EMBD 10
#define NB 4096
#define NCSEQ 49152
#define NC0 768
typedef __nv_bfloat16 bf16;

__device__ bf16 g_Ahi[NP * NP];
__device__ bf16 g_Alo[NP * NP];
__device__ bf16 g_X0hi[NP * NC0];
__device__ bf16 g_X0lo[NP * NC0];
__device__ bf16 g_AX0hi[NP * NC0];
__device__ bf16 g_AX0lo[NP * NC0];
__device__ bf16 g_WG0h[NN * 144 * 128];
__device__ bf16 g_WG0l[NN * 144 * 128];
__device__ bf16 g_WC0h[NN * 144 * 64];
__device__ bf16 g_WC0l[NN * 144 * 64];
__device__ bf16 g_WG1h[NN * 256 * 128];
__device__ bf16 g_WG1l[NN * 256 * 128];
__device__ bf16 g_WC1h[NN * 256 * 64];
__device__ bf16 g_WC1l[NN * 256 * 64];
__device__ float g_Bg0[NN * 128];
__device__ float g_Bc0[NN * 64];
__device__ float g_Bg1[NN * 128];
__device__ float g_Bc1[NN * 64];
// layer-0 state
__device__ float g_H[NN * NB];
__device__ float g_R[NN * NB];
__device__ bf16 g_Hhi[NP * NB];
__device__ bf16 g_Hlo[NP * NB];
__device__ bf16 g_ZHhi[NP * NB];
__device__ bf16 g_ZHlo[NP * NB];
__device__ bf16 g_AHhi[NP * NB];
__device__ bf16 g_AHlo[NP * NB];
__device__ bf16 g_AZHhi[NP * NB];
__device__ bf16 g_AZHlo[NP * NB];
// layer-1 private state (stream-2)
__device__ float g_H2[NN * NB];
__device__ float g_R2[NN * NB];
__device__ bf16 g_H2hi[NP * NB];
__device__ bf16 g_H2lo[NP * NB];
__device__ bf16 g_ZH2hi[NP * NB];
__device__ bf16 g_ZH2lo[NP * NB];
__device__ bf16 g_AH2hi[NP * NB];
__device__ bf16 g_AH2lo[NP * NB];
__device__ bf16 g_AZH2hi[NP * NB];
__device__ bf16 g_AZH2lo[NP * NB];
__device__ bf16 g_SEQhi[(size_t)NP * NCSEQ];
__device__ bf16 g_SEQlo[(size_t)NP * NCSEQ];
__device__ bf16 g_ASEQhi[(size_t)NP * NCSEQ];
__device__ bf16 g_ASEQlo[(size_t)NP * NCSEQ];

__device__ __forceinline__ void bsplit(float v, bf16& hi, bf16& lo) {
    hi = __float2bfloat16_rn(v);
    lo = __float2bfloat16_rn(v - __bfloat162float(hi));
}
__device__ __forceinline__ unsigned s2u(const void* p) {
    return (unsigned)__cvta_generic_to_shared(p);
}
__device__ __forceinline__ void cp16(void* s, const void* g) {
    asm volatile("cp.async.cg.shared.global [%0], [%1], 16;" :: "r"(s2u(s)), "l"(g));
}
__device__ __forceinline__ void ldsm4(unsigned* r, unsigned a) {
    asm volatile("ldmatrix.sync.aligned.m8n8.x4.shared.b16 {%0,%1,%2,%3}, [%4];"
                 : "=r"(r[0]), "=r"(r[1]), "=r"(r[2]), "=r"(r[3]) : "r"(a));
}
__device__ __forceinline__ void ldsm4t(unsigned* r, unsigned a) {
    asm volatile("ldmatrix.sync.aligned.m8n8.x4.trans.shared.b16 {%0,%1,%2,%3}, [%4];"
                 : "=r"(r[0]), "=r"(r[1]), "=r"(r[2]), "=r"(r[3]) : "r"(a));
}
__device__ __forceinline__ void mma16816(float* c, const unsigned* a, const unsigned* b) {
    asm volatile(
        "mma.sync.aligned.m16n8k16.row.col.f32.bf16.bf16.f32 "
        "{%0,%1,%2,%3},{%4,%5,%6,%7},{%8,%9},{%0,%1,%2,%3};"
        : "+f"(c[0]), "+f"(c[1]), "+f"(c[2]), "+f"(c[3])
        : "r"(a[0]), "r"(a[1]), "r"(a[2]), "r"(a[3]), "r"(b[0]), "r"(b[1]));
}
__device__ __forceinline__ void st2(bf16* p, bf16 a, bf16 b) {
    __nv_bfloat162 v; v.x = a; v.y = b;
    *(__nv_bfloat162*)p = v;
}

// ---------------- adjacency ----------------
__global__ void __launch_bounds__(256) k_supports(const float* __restrict__ E,
                                                  bf16* __restrict__ Ahi,
                                                  bf16* __restrict__ Alo) {
    int n = blockIdx.x, tid = threadIdx.x;
    if (n >= NN) {
        for (int m = tid; m < NP; m += 256) { Ahi[n * NP + m] = __float2bfloat16(0.f); Alo[n * NP + m] = __float2bfloat16(0.f); }
        return;
    }
    __shared__ float row[NN];
    __shared__ float red[8];
    __shared__ float ssum;
    float en[EMBD];
#pragma unroll
    for (int d = 0; d < EMBD; d++) en[d] = E[n * EMBD + d];
    float lmax = -1e30f;
    for (int m = tid; m < NN; m += 256) {
        float s = 0.f;
#pragma unroll
        for (int d = 0; d < EMBD; d++) s = fmaf(en[d], E[m * EMBD + d], s);
        s = fmaxf(s, 0.f);
        row[m] = s;
        lmax = fmaxf(lmax, s);
    }
#pragma unroll
    for (int o = 16; o; o >>= 1) lmax = fmaxf(lmax, __shfl_xor_sync(~0u, lmax, o));
    if ((tid & 31) == 0) red[tid >> 5] = lmax;
    __syncthreads();
    if (tid == 0) { float mx = red[0]; for (int w = 1; w < 8; w++) mx = fmaxf(mx, red[w]); red[0] = mx; }
    __syncthreads();
    float mx = red[0];
    __syncthreads();
    float lsum = 0.f;
    for (int m = tid; m < NN; m += 256) { float e = expf(row[m] - mx); row[m] = e; lsum += e; }
#pragma unroll
    for (int o = 16; o; o >>= 1) lsum += __shfl_xor_sync(~0u, lsum, o);
    if ((tid & 31) == 0) red[tid >> 5] = lsum;
    __syncthreads();
    if (tid == 0) { float s = 0.f; for (int w = 0; w < 8; w++) s += red[w]; ssum = s; }
    __syncthreads();
    float inv = 1.f / ssum;
    for (int m = tid; m < NP; m += 256) {
        float v = (m < NN) ? row[m] * inv : 0.f;
        bf16 h, l; bsplit(v, h, l);
        Ahi[n * NP + m] = h; Alo[n * NP + m] = l;
    }
}

__global__ void k_srcsplit(const float* __restrict__ src, bf16* __restrict__ hi,
                           bf16* __restrict__ lo) {
    int idx = blockIdx.x * 256 + threadIdx.x;
    if (idx >= NP * NC0) return;
    int n = idx / NC0, col = idx % NC0, t = col >> 6, b = col & 63;
    float v = (n < NN) ? src[((size_t)b * TT + t) * NN + n] : 0.f;
    bf16 h, l; bsplit(v, h, l);
    hi[idx] = h; lo[idx] = l;
}

// -------- tiled per-node weight pooling --------
__global__ void __launch_bounds__(256) k_nodewsplit(
    const float* __restrict__ E, const float* __restrict__ pool,
    bf16* __restrict__ Whi, bf16* __restrict__ Wlo, int COUT, int KDp, int layer) {
    __shared__ float Es[64][EMBD];
    __shared__ float Ps[EMBD][256];
    const int tid = threadIdx.x;
    const int colBase = blockIdx.x * 256;
    const int nBase = blockIdx.y * 64;
    const long RC = (long)KDp * COUT;

    for (int i = tid; i < 64 * EMBD; i += 256) {
        int nn = nBase + i / EMBD;
        Es[i / EMBD][i % EMBD] = (nn < NN) ? E[nn * EMBD + i % EMBD] : 0.f;
    }
    {
        int c = colBase + tid;
        int k = c / COUT, o = c % COUT;
        int row, ROWS;
        if (layer == 0) {
            ROWS = 130;
            if (k < 64) row = k + 1;
            else if (k < 128) row = k + 2;
            else if (k == 128) row = 0;
            else if (k == 129) row = 65;
            else row = -1;
        } else { ROWS = 256; row = k; }
#pragma unroll
        for (int d = 0; d < EMBD; d++)
            Ps[d][tid] = (row >= 0) ? pool[((long)d * ROWS + row) * COUT + o] : 0.f;
    }
    __syncthreads();

    float pv[EMBD];
#pragma unroll
    for (int d = 0; d < EMBD; d++) pv[d] = Ps[d][tid];
#pragma unroll 4
    for (int i = 0; i < 64; i++) {
        int nn = nBase + i;
        if (nn >= NN) break;
        float s = 0.f;
#pragma unroll
        for (int d = 0; d < EMBD; d++) s = fmaf(Es[i][d], pv[d], s);
        bf16 h, l; bsplit(s, h, l);
        size_t ix = (size_t)nn * RC + colBase + tid;
        Whi[ix] = h; Wlo[ix] = l;
    }
}

__global__ void k_nodew(const float* __restrict__ E, const float* __restrict__ pool,
                        float* __restrict__ out, int RC) {
    long idx = (long)blockIdx.x * 256 + threadIdx.x;
    if (idx >= (long)NN * RC) return;
    int n = (int)(idx / RC), rem = (int)(idx % RC);
    float s = 0.f;
#pragma unroll
    for (int d = 0; d < EMBD; d++) s = fmaf(E[n * EMBD + d], pool[(long)d * RC + rem], s);
    out[idx] = s;
}

// zero H (fp32, NN*NB) + 6 bf16 buffers (NP*NB each, as uint32 pairs)
__global__ void k_zeroH(float* H, bf16* Hhi, bf16* Hlo, bf16* AHhi, bf16* AHlo,
                        bf16* AZHhi, bf16* AZHlo) {
    int i = blockIdx.x * 256 + threadIdx.x;
    if (i < NN * NB) H[i] = 0.f;
    if (i < NP * NB / 2) {
        ((uint32_t*)Hhi)[i] = 0u; ((uint32_t*)Hlo)[i] = 0u;
        ((uint32_t*)AHhi)[i] = 0u; ((uint32_t*)AHlo)[i] = 0u;
        ((uint32_t*)AZHhi)[i] = 0u; ((uint32_t*)AZHlo)[i] = 0u;
    }
}

// -- dense split-bf16 MMA: C(hi,lo)=A@X. 64x128 tile, BK16, 128 thr, 2-stage --
__global__ void __launch_bounds__(128) k_mma(const bf16* __restrict__ Ahi,
                                             const bf16* __restrict__ Alo,
                                             const bf16* __restrict__ Xhi,
                                             const bf16* __restrict__ Xlo,
                                             bf16* __restrict__ Chi,
                                             bf16* __restrict__ Clo,
                                             int NCin, int NCout) {
    __shared__ bf16 sAh[2][64 * 16], sAl[2][64 * 16];
    __shared__ bf16 sXh[2][16 * 128], sXl[2][16 * 128];
    const int tid = threadIdx.x, lane = tid & 31, warp = tid >> 5;
    const int rowBase = blockIdx.y * 64, colBase = blockIdx.x * 128;
    const int ar = tid >> 1, ac = (tid & 1) * 8;

    float acc[4][4][4];
#pragma unroll
    for (int i = 0; i < 4; i++)
#pragma unroll
        for (int j = 0; j < 4; j++)
#pragma unroll
            for (int q = 0; q < 4; q++) acc[i][j][q] = 0.f;

    auto prefetch = [&](int kt, int buf) {
        int k0 = kt * 16;
        cp16(&sAh[buf][ar * 16 + ac], Ahi + (size_t)(rowBase + ar) * NP + k0 + ac);
        cp16(&sAl[buf][ar * 16 + ac], Alo + (size_t)(rowBase + ar) * NP + k0 + ac);
#pragma unroll
        for (int i = 0; i < 2; i++) {
            int idx = tid + i * 128;
            int r = idx >> 4, cc = idx & 15;
            int dst = r * 128 + ((cc ^ r) & 15) * 8;
            cp16(&sXh[buf][dst], Xhi + (size_t)(k0 + r) * NCin + colBase + cc * 8);
            cp16(&sXl[buf][dst], Xlo + (size_t)(k0 + r) * NCin + colBase + cc * 8);
        }
        asm volatile("cp.async.commit_group;");
    };

    prefetch(0, 0);
    const int aoff = (lane & 15) * 32 + (lane >> 4) * 16;
    const int bk = lane & 15, bch = lane >> 4;

#pragma unroll 1
    for (int kt = 0; kt < 56; ++kt) {
        if (kt < 55) {
            prefetch(kt + 1, (kt + 1) & 1);
            asm volatile("cp.async.wait_group 1;");
        } else {
            asm volatile("cp.async.wait_group 0;");
        }
        __syncthreads();
        int buf = kt & 1;
        unsigned bAh = s2u(&sAh[buf][0]);
        unsigned bAl = s2u(&sAl[buf][0]);
        unsigned bXh = s2u(&sXh[buf][0]);
        unsigned bXl = s2u(&sXl[buf][0]);
        unsigned ah[4][4], al[4][4], bh[2][4], bl[2][4];
#pragma unroll
        for (int i = 0; i < 4; i++) {
            ldsm4(ah[i], bAh + i * 512 + aoff);
            ldsm4(al[i], bAl + i * 512 + aoff);
        }
#pragma unroll
        for (int j = 0; j < 2; j++) {
            int c = warp * 4 + j * 2 + bch;
            int cp = c ^ bk;
            ldsm4t(bh[j], bXh + bk * 256 + cp * 16);
            ldsm4t(bl[j], bXl + bk * 256 + cp * 16);
        }
#pragma unroll
        for (int i = 0; i < 4; i++)
#pragma unroll
            for (int j = 0; j < 2; j++)
#pragma unroll
                for (int h = 0; h < 2; h++) {
                    unsigned bph[2] = {bh[j][h * 2], bh[j][h * 2 + 1]};
                    unsigned bpl[2] = {bl[j][h * 2], bl[j][h * 2 + 1]};
                    float* cc = acc[i][j * 2 + h];
                    mma16816(cc, ah[i], bph);
                    mma16816(cc, ah[i], bpl);
                    mma16816(cc, al[i], bph);
                }
        __syncthreads();
    }
#pragma unroll
    for (int i = 0; i < 4; i++) {
        int r0 = rowBase + i * 16 + (lane >> 2);
#pragma unroll
        for (int jn = 0; jn < 4; jn++) {
            int c0 = colBase + warp * 32 + jn * 8 + (lane & 3) * 2;
            bf16 h0, l0, h1, l1;
            bsplit(acc[i][jn][0], h0, l0); bsplit(acc[i][jn][1], h1, l1);
            st2(&Chi[(size_t)r0 * NCout + c0], h0, h1);
            st2(&Clo[(size_t)r0 * NCout + c0], l0, l1);
            bsplit(acc[i][jn][2], h0, l0); bsplit(acc[i][jn][3], h1, l1);
            st2(&Chi[(size_t)(r0 + 8) * NCout + c0], h0, h1);
            st2(&Clo[(size_t)(r0 + 8) * NCout + c0], l0, l1);
        }
    }
}

// ---------------- per-node tensor-core GEMM + fused epilogue -----------------
template <int COUT, bool CAND, bool L0>
__global__ void __launch_bounds__(128) k_pn(
    const bf16* __restrict__ xh, const bf16* __restrict__ xl, size_t xstr, size_t xoff,
    const bf16* __restrict__ hh, const bf16* __restrict__ hl,
    const bf16* __restrict__ axh, const bf16* __restrict__ axl, size_t axstr, size_t axoff,
    const bf16* __restrict__ ahh, const bf16* __restrict__ ahl, size_t ahstr,
    const bf16* __restrict__ Whi, const bf16* __restrict__ Wlo,
    const float* __restrict__ Bias, float* __restrict__ R, float* __restrict__ Hfp,
    bf16* __restrict__ o1h, bf16* __restrict__ o1l,
    bf16* __restrict__ s1h, bf16* __restrict__ s1l, size_t seqOff) {
    constexpr int NCH = L0 ? 9 : 16;
    constexpr int SLICE = COUT / 4;
    constexpr int NJ = SLICE / 16;
    constexpr int WCH = COUT / 8;
    __shared__ bf16 sXh[2][64 * 24], sXl[2][64 * 24];
    __shared__ bf16 sWh[2][16 * COUT], sWl[2][16 * COUT];
    const int n = blockIdx.x, tid = threadIdx.x, lane = tid & 31, wn = tid >> 5;
    const bf16* Wh = Whi + (size_t)n * NCH * 16 * COUT;
    const bf16* Wl = Wlo + (size_t)n * NCH * 16 * COUT;

    float acc[4][NJ * 2][4];
#pragma unroll
    for (int i = 0; i < 4; i++)
#pragma unroll
        for (int j = 0; j < NJ * 2; j++)
#pragma unroll
            for (int q = 0; q < 4; q++) acc[i][j][q] = 0.f;

    auto prefetch = [&](int c) {
        int buf = c & 1;
#pragma unroll
        for (int q = tid; q < 16 * WCH; q += 128) {
            int r = q / WCH, cc = q % WCH;
            int dst = r * COUT + (cc ^ (r & (WCH - 1))) * 8;
            size_t src = (size_t)(c * 16 + r) * COUT + cc * 8;
            cp16(&sWh[buf][dst], Wh + src);
            cp16(&sWl[buf][dst], Wl + src);
        }
        if (L0 && c == 8) {
            if (tid < 64) {
                int b = tid;
                bf16 z = __float2bfloat16(0.f);
#pragma unroll
                for (int k = 0; k < 16; k++) { sXh[buf][b * 24 + k] = z; sXl[buf][b * 24 + k] = z; }
                sXh[buf][b * 24 + 0] = xh[n * xstr + xoff + b];
                sXl[buf][b * 24 + 0] = xl[n * xstr + xoff + b];
                sXh[buf][b * 24 + 1] = axh[n * axstr + axoff + b];
                sXl[buf][b * 24 + 1] = axl[n * axstr + axoff + b];
            }
        } else {
            int b = tid >> 1, half = tid & 1;
            const bf16 *ph, *pl; size_t base;
            if (L0) {
                if (c < 4) { ph = hh; pl = hl; base = (size_t)n * NB + b * 64 + c * 16 + half * 8; }
                else { ph = ahh; pl = ahl; base = (size_t)n * ahstr + b * 64 + (c - 4) * 16 + half * 8; }
            } else {
                int g = c >> 2, kl = (c & 3) * 16 + half * 8;
                if (g == 0) { ph = xh; pl = xl; base = (size_t)n * xstr + xoff + b * 64 + kl; }
                else if (g == 1) { ph = hh; pl = hl; base = (size_t)n * NB + b * 64 + kl; }
                else if (g == 2) { ph = axh; pl = axl; base = (size_t)n * axstr + axoff + b * 64 + kl; }
                else { ph = ahh; pl = ahl; base = (size_t)n * ahstr + b * 64 + kl; }
            }
            cp16(&sXh[buf][b * 24 + half * 8], ph + base);
            cp16(&sXl[buf][b * 24 + half * 8], pl + base);
        }
        asm volatile("cp.async.commit_group;");
    };

    prefetch(0);
#pragma unroll 1
    for (int c = 0; c < NCH; c++) {
        if (c + 1 < NCH) { prefetch(c + 1); asm volatile("cp.async.wait_group 1;"); }
        else asm volatile("cp.async.wait_group 0;");
        __syncthreads();
        int buf = c & 1;
        unsigned bXh = s2u(&sXh[buf][0]);
        unsigned bXl = s2u(&sXl[buf][0]);
        unsigned bWh = s2u(&sWh[buf][0]);
        unsigned bWl = s2u(&sWl[buf][0]);
        unsigned ah[4][4], al[4][4], bh[NJ][4], bl[NJ][4];
#pragma unroll
        for (int i = 0; i < 4; i++) {
            unsigned off = (i * 16 + (lane & 15)) * 48 + (lane >> 4) * 16;
            ldsm4(ah[i], bXh + off);
            ldsm4(al[i], bXl + off);
        }
        int bk = lane & 15;
#pragma unroll
        for (int j = 0; j < NJ; j++) {
            int cch = wn * (SLICE / 8) + j * 2 + (lane >> 4);
            unsigned off = bk * (COUT * 2) + (cch ^ (bk & (WCH - 1))) * 16;
            ldsm4t(bh[j], bWh + off);
            ldsm4t(bl[j], bWl + off);
        }
#pragma unroll
        for (int i = 0; i < 4; i++)
#pragma unroll
            for (int j = 0; j < NJ; j++)
#pragma unroll
                for (int h = 0; h < 2; h++) {
                    unsigned bph[2] = {bh[j][h * 2], bh[j][h * 2 + 1]};
                    unsigned bpl[2] = {bl[j][h * 2], bl[j][h * 2 + 1]};
                    float* cc = acc[i][j * 2 + h];
                    mma16816(cc, ah[i], bph);
                    mma16816(cc, ah[i], bpl);
                    mma16816(cc, al[i], bph);
                }
        __syncthreads();
    }

#pragma unroll
    for (int i = 0; i < 4; i++) {
        int b0 = i * 16 + (lane >> 2);
#pragma unroll
        for (int jn = 0; jn < NJ * 2; jn++) {
            int o = wn * SLICE + jn * 8 + (lane & 3) * 2;
#pragma unroll
            for (int rr = 0; rr < 2; rr++) {
                int b = b0 + rr * 8;
                size_t ix = (size_t)n * NB + b * 64;
                float v0 = acc[i][jn][rr * 2 + 0] + Bias[n * COUT + o];
                float v1 = acc[i][jn][rr * 2 + 1] + Bias[n * COUT + o + 1];
                if (!CAND) {
                    float s0 = 1.f / (1.f + expf(-v0));
                    float s1 = 1.f / (1.f + expf(-v1));
                    if (o < 64) {
                        float z0 = s0 * Hfp[ix + o], z1 = s1 * Hfp[ix + o + 1];
                        bf16 h0, l0, h1, l1;
                        bsplit(z0, h0, l0); bsplit(z1, h1, l1);
                        st2(&o1h[ix + o], h0, h1);
                        st2(&o1l[ix + o], l0, l1);
                    } else {
                        R[ix + o - 64] = s0; R[ix + o - 63] = s1;
                    }
                } else {
                    float hc0 = tanhf(v0), hc1 = tanhf(v1);
                    float r0 = R[ix + o], r1 = R[ix + o + 1];
                    float hn0 = r0 * Hfp[ix + o] + (1.f - r0) * hc0;
                    float hn1 = r1 * Hfp[ix + o + 1] + (1.f - r1) * hc1;
                    Hfp[ix + o] = hn0; Hfp[ix + o + 1] = hn1;
                    bf16 h0, l0, h1, l1;
                    bsplit(hn0, h0, l0); bsplit(hn1, h1, l1);
                    st2(&o1h[ix + o], h0, h1);
                    st2(&o1l[ix + o], l0, l1);
                    if (s1h) {
                        size_t s = (size_t)n * NCSEQ + seqOff + b * 64 + o;
                        st2(&s1h[s], h0, h1);
                        st2(&s1l[s], l0, l1);
                    }
                }
            }
        }
    }
}

__global__ void k_final(const float* __restrict__ H, const float* __restrict__ cw,
                        const float* __restrict__ cb, float* __restrict__ out) {
    int idx = blockIdx.x * 256 + threadIdx.x;
    if (idx >= BB * NN) return;
    int n = idx % NN, b = idx / NN;
    const float* h = H + (size_t)n * NB + b * 64;
    float hv[HID];
#pragma unroll
    for (int j = 0; j < HID; j++) hv[j] = h[j];
#pragma unroll
    for (int o = 0; o < TT; o++) {
        float s = cb[o];
#pragma unroll
        for (int j = 0; j < HID; j++) s = fmaf(hv[j], cw[o * HID + j], s);
        out[((size_t)b * TT + o) * NN + n] = s;
    }
}

extern "C" void kernel_launch(void* const* d_in, const int* in_sizes, int n_in,
                              void* d_out, int out_size) {
    const float* src = (const float*)d_in[0];
    const float* E = (const float*)d_in[1];
    const float* cw = (const float*)d_in[10];
    const float* cb = (const float*)d_in[11];
    float* out = (float*)d_out;

#define SYM(T, v, s) T* v; cudaGetSymbolAddress((void**)&v, s)
    SYM(bf16, Ahi, g_Ahi); SYM(bf16, Alo, g_Alo);
    SYM(bf16, X0hi, g_X0hi); SYM(bf16, X0lo, g_X0lo);
    SYM(bf16, AX0hi, g_AX0hi); SYM(bf16, AX0lo, g_AX0lo);
    SYM(bf16, WG0h, g_WG0h); SYM(bf16, WG0l, g_WG0l);
    SYM(bf16, WC0h, g_WC0h); SYM(bf16, WC0l, g_WC0l);
    SYM(bf16, WG1h, g_WG1h); SYM(bf16, WG1l, g_WG1l);
    SYM(bf16, WC1h, g_WC1h); SYM(bf16, WC1l, g_WC1l);
    SYM(float, Bg0, g_Bg0); SYM(float, Bc0, g_Bc0);
    SYM(float, Bg1, g_Bg1); SYM(float, Bc1, g_Bc1);
    SYM(float, H, g_H); SYM(float, R, g_R);
    SYM(bf16, Hhi, g_Hhi); SYM(bf16, Hlo, g_Hlo);
    SYM(bf16, ZHhi, g_ZHhi); SYM(bf16, ZHlo, g_ZHlo);
    SYM(bf16, AHhi, g_AHhi); SYM(bf16, AHlo, g_AHlo);
    SYM(bf16, AZHhi, g_AZHhi); SYM(bf16, AZHlo, g_AZHlo);
    SYM(float, H2, g_H2); SYM(float, R2, g_R2);
    SYM(bf16, H2hi, g_H2hi); SYM(bf16, H2lo, g_H2lo);
    SYM(bf16, ZH2hi, g_ZH2hi); SYM(bf16, ZH2lo, g_ZH2lo);
    SYM(bf16, AH2hi, g_AH2hi); SYM(bf16, AH2lo, g_AH2lo);
    SYM(bf16, AZH2hi, g_AZH2hi); SYM(bf16, AZH2lo, g_AZH2lo);
    SYM(bf16, Shi, g_SEQhi); SYM(bf16, Slo, g_SEQlo);
    SYM(bf16, AShi, g_ASEQhi); SYM(bf16, ASlo, g_ASEQlo);

    cudaStream_t s0 = 0, s2;
    cudaStreamCreateWithFlags(&s2, cudaStreamNonBlocking);
    cudaEvent_t ev[TT], evFork, evJoin;
    for (int i = 0; i < TT; i++) cudaEventCreateWithFlags(&ev[i], cudaEventDisableTiming);
    cudaEventCreateWithFlags(&evFork, cudaEventDisableTiming);
    cudaEventCreateWithFlags(&evJoin, cudaEventDisableTiming);

    const int ZG = (NN * NB + 255) / 256;
    const dim3 GSTEP(NB / 128, 14);

    // fork s2 immediately: layer-1-private prologue overlaps s0's prologue
    cudaEventRecord(evFork, s0);
    cudaStreamWaitEvent(s2, evFork, 0);
    k_nodewsplit<<<dim3(256 * 128 / 256, 14), 256, 0, s2>>>(E, (const float*)d_in[6], WG1h, WG1l, 128, 256, 1);
    k_nodew<<<((long)NN * 128 + 255) / 256, 256, 0, s2>>>(E, (const float*)d_in[7], Bg1, 128);
    k_nodewsplit<<<dim3(256 * 64 / 256, 14), 256, 0, s2>>>(E, (const float*)d_in[8], WC1h, WC1l, 64, 256, 1);
    k_nodew<<<((long)NN * 64 + 255) / 256, 256, 0, s2>>>(E, (const float*)d_in[9], Bc1, 64);
    k_zeroH<<<ZG, 256, 0, s2>>>(H2, H2hi, H2lo, AH2hi, AH2lo, AZH2hi, AZH2lo);

    // s0 prologue (layer-0 deps only)
    k_supports<<<NP, 256, 0, s0>>>(E, Ahi, Alo);
    k_srcsplit<<<(NP * NC0 + 255) / 256, 256, 0, s0>>>(src, X0hi, X0lo);
    k_nodewsplit<<<dim3(144 * 128 / 256, 14), 256, 0, s0>>>(E, (const float*)d_in[2], WG0h, WG0l, 128, 144, 0);
    k_nodew<<<((long)NN * 128 + 255) / 256, 256, 0, s0>>>(E, (const float*)d_in[3], Bg0, 128);
    k_nodewsplit<<<dim3(144 * 64 / 256, 14), 256, 0, s0>>>(E, (const float*)d_in[4], WC0h, WC0l, 64, 144, 0);
    k_nodew<<<((long)NN * 64 + 255) / 256, 256, 0, s0>>>(E, (const float*)d_in[5], Bc0, 64);
    k_mma<<<dim3(NC0 / 128, 14), 128, 0, s0>>>(Ahi, Alo, X0hi, X0lo, AX0hi, AX0lo, NC0, NC0);

    // layer 0 on s0; per-step A@H lands directly into ASEQ slot (t-1)
    k_zeroH<<<ZG, 256, 0, s0>>>(H, Hhi, Hlo, AHhi, AHlo, AZHhi, AZHlo);
    for (int t = 0; t < TT; t++) {
        const bf16* ahh = AHhi; const bf16* ahl = AHlo; size_t ahstr = NB;
        if (t > 0) {
            bf16* dsth = AShi + (size_t)(t - 1) * NB;
            bf16* dstl = ASlo + (size_t)(t - 1) * NB;
            k_mma<<<GSTEP, 128, 0, s0>>>(Ahi, Alo, Hhi, Hlo, dsth, dstl, NB, NCSEQ);
            cudaEventRecord(ev[t - 1], s0);
            ahh = dsth; ahl = dstl; ahstr = NCSEQ;
        }
        k_pn<128, false, true><<<NN, 128, 0, s0>>>(X0hi, X0lo, NC0, (size_t)t * 64,
            Hhi, Hlo, AX0hi, AX0lo, NC0, (size_t)t * 64, ahh, ahl, ahstr,
            WG0h, WG0l, Bg0, R, H, ZHhi, ZHlo, (bf16*)0, (bf16*)0, 0);
        if (t > 0)
            k_mma<<<GSTEP, 128, 0, s0>>>(Ahi, Alo, ZHhi, ZHlo, AZHhi, AZHlo, NB, NB);
        k_pn<64, true, true><<<NN, 128, 0, s0>>>(X0hi, X0lo, NC0, (size_t)t * 64,
            ZHhi, ZHlo, AX0hi, AX0lo, NC0, (size_t)t * 64, AZHhi, AZHlo, (size_t)NB,
            WC0h, WC0l, Bc0, R, H, Hhi, Hlo, Shi, Slo, (size_t)t * NB);
    }
    k_mma<<<GSTEP, 128, 0, s0>>>(Ahi, Alo, Shi + (size_t)11 * NB, Slo + (size_t)11 * NB,
                                 AShi + (size_t)11 * NB, ASlo + (size_t)11 * NB, NCSEQ, NCSEQ);
    cudaEventRecord(ev[11], s0);

    // layer 1 on s2, gated per step
    for (int t = 0; t < TT; t++) {
        cudaStreamWaitEvent(s2, ev[t], 0);
        if (t > 0)
            k_mma<<<GSTEP, 128, 0, s2>>>(Ahi, Alo, H2hi, H2lo, AH2hi, AH2lo, NB, NB);
        k_pn<128, false, false><<<NN, 128, 0, s2>>>(Shi, Slo, NCSEQ, (size_t)t * NB,
            H2hi, H2lo, AShi, ASlo, NCSEQ, (size_t)t * NB, AH2hi, AH2lo, (size_t)NB,
            WG1h, WG1l, Bg1, R2, H2, ZH2hi, ZH2lo, (bf16*)0, (bf16*)0, 0);
        if (t > 0)
            k_mma<<<GSTEP, 128, 0, s2>>>(Ahi, Alo, ZH2hi, ZH2lo, AZH2hi, AZH2lo, NB, NB);
        k_pn<64, true, false><<<NN, 128, 0, s2>>>(Shi, Slo, NCSEQ, (size_t)t * NB,
            ZH2hi, ZH2lo, AShi, ASlo, NCSEQ, (size_t)t * NB, AZH2hi, AZH2lo, (size_t)NB,
            WC1h, WC1l, Bc1, R2, H2, H2hi, H2lo, (bf16*)0, (bf16*)0, 0);
    }
    k_final<<<(BB * NN + 255) / 256, 256, 0, s2>>>(H2, cw, cb, out);

    cudaEventRecord(evJoin, s2);
    cudaStreamWaitEvent(s0, evJoin, 0);

    cudaStreamCaptureStatus st = cudaStreamCaptureStatusNone;
    cudaStreamIsCapturing(s0, &st);
    if (st == cudaStreamCaptureStatusNone) {
        cudaStreamDestroy(s2);
        for (int i = 0; i < TT; i++) cudaEventDestroy(ev[i]);
        cudaEventDestroy(evFork);
        cudaEventDestroy(evJoin);
    }
}

// round 15
// speedup vs baseline: 1.6769x; 1.0033x over previous
#include <cuda_runtime.h>
#include <cuda_bf16.h>
#include <math.h>
#include <stdint.h>

#define NN 883
#define NP 896
#define BB 64
#define TT 12
#define HID 64
#define EMBD 10
#define NB 4096
#define NCSEQ 49152
#define NC0 768
typedef __nv_bfloat16 bf16;

__device__ bf16 g_Ahi[NP * NP];
__device__ bf16 g_Alo[NP * NP];
__device__ bf16 g_X0hi[NP * NC0];
__device__ bf16 g_X0lo[NP * NC0];
__device__ bf16 g_AX0hi[NP * NC0];
__device__ bf16 g_AX0lo[NP * NC0];
__device__ bf16 g_WG0h[NN * 144 * 128];
__device__ bf16 g_WG0l[NN * 144 * 128];
__device__ bf16 g_WC0h[NN * 144 * 64];
__device__ bf16 g_WC0l[NN * 144 * 64];
__device__ bf16 g_WG1h[NN * 256 * 128];
__device__ bf16 g_WG1l[NN * 256 * 128];
__device__ bf16 g_WC1h[NN * 256 * 64];
__device__ bf16 g_WC1l[NN * 256 * 64];
__device__ float g_Bg0[NN * 128];
__device__ float g_Bc0[NN * 64];
__device__ float g_Bg1[NN * 128];
__device__ float g_Bc1[NN * 64];
__device__ float g_H[NN * NB];
__device__ float g_R[NN * NB];
__device__ bf16 g_Hhi[NP * NB];
__device__ bf16 g_Hlo[NP * NB];
__device__ bf16 g_ZHhi[NP * NB];
__device__ bf16 g_ZHlo[NP * NB];
__device__ bf16 g_AHhi[NP * NB];
__device__ bf16 g_AHlo[NP * NB];
__device__ bf16 g_AZHhi[NP * NB];
__device__ bf16 g_AZHlo[NP * NB];
__device__ float g_H2[NN * NB];
__device__ float g_R2[NN * NB];
__device__ bf16 g_H2hi[NP * NB];
__device__ bf16 g_H2lo[NP * NB];
__device__ bf16 g_ZH2hi[NP * NB];
__device__ bf16 g_ZH2lo[NP * NB];
__device__ bf16 g_AH2hi[NP * NB];
__device__ bf16 g_AH2lo[NP * NB];
__device__ bf16 g_AZH2hi[NP * NB];
__device__ bf16 g_AZH2lo[NP * NB];
__device__ bf16 g_SEQhi[(size_t)NP * NCSEQ];
__device__ bf16 g_SEQlo[(size_t)NP * NCSEQ];
__device__ bf16 g_ASEQhi[(size_t)NP * NCSEQ];
__device__ bf16 g_ASEQlo[(size_t)NP * NCSEQ];

__device__ __forceinline__ void bsplit(float v, bf16& hi, bf16& lo) {
    hi = __float2bfloat16_rn(v);
    lo = __float2bfloat16_rn(v - __bfloat162float(hi));
}
__device__ __forceinline__ unsigned s2u(const void* p) {
    return (unsigned)__cvta_generic_to_shared(p);
}
__device__ __forceinline__ void cp16(void* s, const void* g) {
    asm volatile("cp.async.cg.shared.global [%0], [%1], 16;" :: "r"(s2u(s)), "l"(g));
}
__device__ __forceinline__ void ldsm4(unsigned* r, unsigned a) {
    asm volatile("ldmatrix.sync.aligned.m8n8.x4.shared.b16 {%0,%1,%2,%3}, [%4];"
                 : "=r"(r[0]), "=r"(r[1]), "=r"(r[2]), "=r"(r[3]) : "r"(a));
}
__device__ __forceinline__ void ldsm4t(unsigned* r, unsigned a) {
    asm volatile("ldmatrix.sync.aligned.m8n8.x4.trans.shared.b16 {%0,%1,%2,%3}, [%4];"
                 : "=r"(r[0]), "=r"(r[1]), "=r"(r[2]), "=r"(r[3]) : "r"(a));
}
__device__ __forceinline__ void mma16816(float* c, const unsigned* a, const unsigned* b) {
    asm volatile(
        "mma.sync.aligned.m16n8k16.row.col.f32.bf16.bf16.f32 "
        "{%0,%1,%2,%3},{%4,%5,%6,%7},{%8,%9},{%0,%1,%2,%3};"
        : "+f"(c[0]), "+f"(c[1]), "+f"(c[2]), "+f"(c[3])
        : "r"(a[0]), "r"(a[1]), "r"(a[2]), "r"(a[3]), "r"(b[0]), "r"(b[1]));
}
__device__ __forceinline__ void st2(bf16* p, bf16 a, bf16 b) {
    __nv_bfloat162 v; v.x = a; v.y = b;
    *(__nv_bfloat162*)p = v;
}

__global__ void __launch_bounds__(256) k_supports(const float* __restrict__ E,
                                                  bf16* __restrict__ Ahi,
                                                  bf16* __restrict__ Alo) {
    int n = blockIdx.x, tid = threadIdx.x;
    if (n >= NN) {
        for (int m = tid; m < NP; m += 256) { Ahi[n * NP + m] = __float2bfloat16(0.f); Alo[n * NP + m] = __float2bfloat16(0.f); }
        return;
    }
    __shared__ float row[NN];
    __shared__ float red[8];
    __shared__ float ssum;
    float en[EMBD];
#pragma unroll
    for (int d = 0; d < EMBD; d++) en[d] = E[n * EMBD + d];
    float lmax = -1e30f;
    for (int m = tid; m < NN; m += 256) {
        float s = 0.f;
#pragma unroll
        for (int d = 0; d < EMBD; d++) s = fmaf(en[d], E[m * EMBD + d], s);
        s = fmaxf(s, 0.f);
        row[m] = s;
        lmax = fmaxf(lmax, s);
    }
#pragma unroll
    for (int o = 16; o; o >>= 1) lmax = fmaxf(lmax, __shfl_xor_sync(~0u, lmax, o));
    if ((tid & 31) == 0) red[tid >> 5] = lmax;
    __syncthreads();
    if (tid == 0) { float mx = red[0]; for (int w = 1; w < 8; w++) mx = fmaxf(mx, red[w]); red[0] = mx; }
    __syncthreads();
    float mx = red[0];
    __syncthreads();
    float lsum = 0.f;
    for (int m = tid; m < NN; m += 256) { float e = expf(row[m] - mx); row[m] = e; lsum += e; }
#pragma unroll
    for (int o = 16; o; o >>= 1) lsum += __shfl_xor_sync(~0u, lsum, o);
    if ((tid & 31) == 0) red[tid >> 5] = lsum;
    __syncthreads();
    if (tid == 0) { float s = 0.f; for (int w = 0; w < 8; w++) s += red[w]; ssum = s; }
    __syncthreads();
    float inv = 1.f / ssum;
    for (int m = tid; m < NP; m += 256) {
        float v = (m < NN) ? row[m] * inv : 0.f;
        bf16 h, l; bsplit(v, h, l);
        Ahi[n * NP + m] = h; Alo[n * NP + m] = l;
    }
}

__global__ void k_srcsplit(const float* __restrict__ src, bf16* __restrict__ hi,
                           bf16* __restrict__ lo) {
    int idx = blockIdx.x * 256 + threadIdx.x;
    if (idx >= NP * NC0) return;
    int n = idx / NC0, col = idx % NC0, t = col >> 6, b = col & 63;
    float v = (n < NN) ? src[((size_t)b * TT + t) * NN + n] : 0.f;
    bf16 h, l; bsplit(v, h, l);
    hi[idx] = h; lo[idx] = l;
}

__global__ void __launch_bounds__(256) k_nodewsplit(
    const float* __restrict__ E, const float* __restrict__ pool,
    bf16* __restrict__ Whi, bf16* __restrict__ Wlo, int COUT, int KDp, int layer) {
    __shared__ float Es[64][EMBD];
    __shared__ float Ps[EMBD][256];
    const int tid = threadIdx.x;
    const int colBase = blockIdx.x * 256;
    const int nBase = blockIdx.y * 64;
    const long RC = (long)KDp * COUT;

    for (int i = tid; i < 64 * EMBD; i += 256) {
        int nn = nBase + i / EMBD;
        Es[i / EMBD][i % EMBD] = (nn < NN) ? E[nn * EMBD + i % EMBD] : 0.f;
    }
    {
        int c = colBase + tid;
        int k = c / COUT, o = c % COUT;
        int row, ROWS;
        if (layer == 0) {
            ROWS = 130;
            if (k < 64) row = k + 1;
            else if (k < 128) row = k + 2;
            else if (k == 128) row = 0;
            else if (k == 129) row = 65;
            else row = -1;
        } else { ROWS = 256; row = k; }
#pragma unroll
        for (int d = 0; d < EMBD; d++)
            Ps[d][tid] = (row >= 0) ? pool[((long)d * ROWS + row) * COUT + o] : 0.f;
    }
    __syncthreads();

    float pv[EMBD];
#pragma unroll
    for (int d = 0; d < EMBD; d++) pv[d] = Ps[d][tid];
#pragma unroll 4
    for (int i = 0; i < 64; i++) {
        int nn = nBase + i;
        if (nn >= NN) break;
        float s = 0.f;
#pragma unroll
        for (int d = 0; d < EMBD; d++) s = fmaf(Es[i][d], pv[d], s);
        bf16 h, l; bsplit(s, h, l);
        size_t ix = (size_t)nn * RC + colBase + tid;
        Whi[ix] = h; Wlo[ix] = l;
    }
}

__global__ void k_nodew(const float* __restrict__ E, const float* __restrict__ pool,
                        float* __restrict__ out, int RC) {
    long idx = (long)blockIdx.x * 256 + threadIdx.x;
    if (idx >= (long)NN * RC) return;
    int n = (int)(idx / RC), rem = (int)(idx % RC);
    float s = 0.f;
#pragma unroll
    for (int d = 0; d < EMBD; d++) s = fmaf(E[n * EMBD + d], pool[(long)d * RC + rem], s);
    out[idx] = s;
}

__global__ void k_zeroH(float* H, bf16* Hhi, bf16* Hlo, bf16* AHhi, bf16* AHlo,
                        bf16* AZHhi, bf16* AZHlo) {
    int i = blockIdx.x * 256 + threadIdx.x;
    if (i < NN * NB) H[i] = 0.f;
    if (i < NP * NB / 2) {
        ((uint32_t*)Hhi)[i] = 0u; ((uint32_t*)Hlo)[i] = 0u;
        ((uint32_t*)AHhi)[i] = 0u; ((uint32_t*)AHlo)[i] = 0u;
        ((uint32_t*)AZHhi)[i] = 0u; ((uint32_t*)AZHlo)[i] = 0u;
    }
}

__global__ void __launch_bounds__(128) k_mma(const bf16* __restrict__ Ahi,
                                             const bf16* __restrict__ Alo,
                                             const bf16* __restrict__ Xhi,
                                             const bf16* __restrict__ Xlo,
                                             bf16* __restrict__ Chi,
                                             bf16* __restrict__ Clo,
                                             int NCin, int NCout) {
    __shared__ bf16 sAh[2][64 * 16], sAl[2][64 * 16];
    __shared__ bf16 sXh[2][16 * 128], sXl[2][16 * 128];
    const int tid = threadIdx.x, lane = tid & 31, warp = tid >> 5;
    const int rowBase = blockIdx.y * 64, colBase = blockIdx.x * 128;
    const int ar = tid >> 1, ac = (tid & 1) * 8;

    float acc[4][4][4];
#pragma unroll
    for (int i = 0; i < 4; i++)
#pragma unroll
        for (int j = 0; j < 4; j++)
#pragma unroll
            for (int q = 0; q < 4; q++) acc[i][j][q] = 0.f;

    auto prefetch = [&](int kt, int buf) {
        int k0 = kt * 16;
        cp16(&sAh[buf][ar * 16 + ac], Ahi + (size_t)(rowBase + ar) * NP + k0 + ac);
        cp16(&sAl[buf][ar * 16 + ac], Alo + (size_t)(rowBase + ar) * NP + k0 + ac);
#pragma unroll
        for (int i = 0; i < 2; i++) {
            int idx = tid + i * 128;
            int r = idx >> 4, cc = idx & 15;
            int dst = r * 128 + ((cc ^ r) & 15) * 8;
            cp16(&sXh[buf][dst], Xhi + (size_t)(k0 + r) * NCin + colBase + cc * 8);
            cp16(&sXl[buf][dst], Xlo + (size_t)(k0 + r) * NCin + colBase + cc * 8);
        }
        asm volatile("cp.async.commit_group;");
    };

    prefetch(0, 0);
    const int aoff = (lane & 15) * 32 + (lane >> 4) * 16;
    const int bk = lane & 15, bch = lane >> 4;

#pragma unroll 1
    for (int kt = 0; kt < 56; ++kt) {
        if (kt < 55) {
            prefetch(kt + 1, (kt + 1) & 1);
            asm volatile("cp.async.wait_group 1;");
        } else {
            asm volatile("cp.async.wait_group 0;");
        }
        __syncthreads();
        int buf = kt & 1;
        unsigned bAh = s2u(&sAh[buf][0]);
        unsigned bAl = s2u(&sAl[buf][0]);
        unsigned bXh = s2u(&sXh[buf][0]);
        unsigned bXl = s2u(&sXl[buf][0]);
        unsigned ah[4][4], al[4][4], bh[2][4], bl[2][4];
#pragma unroll
        for (int i = 0; i < 4; i++) {
            ldsm4(ah[i], bAh + i * 512 + aoff);
            ldsm4(al[i], bAl + i * 512 + aoff);
        }
#pragma unroll
        for (int j = 0; j < 2; j++) {
            int c = warp * 4 + j * 2 + bch;
            int cp = c ^ bk;
            ldsm4t(bh[j], bXh + bk * 256 + cp * 16);
            ldsm4t(bl[j], bXl + bk * 256 + cp * 16);
        }
#pragma unroll
        for (int i = 0; i < 4; i++)
#pragma unroll
            for (int j = 0; j < 2; j++)
#pragma unroll
                for (int h = 0; h < 2; h++) {
                    unsigned bph[2] = {bh[j][h * 2], bh[j][h * 2 + 1]};
                    unsigned bpl[2] = {bl[j][h * 2], bl[j][h * 2 + 1]};
                    float* cc = acc[i][j * 2 + h];
                    mma16816(cc, ah[i], bph);
                    mma16816(cc, ah[i], bpl);
                    mma16816(cc, al[i], bph);
                }
        __syncthreads();
    }
#pragma unroll
    for (int i = 0; i < 4; i++) {
        int r0 = rowBase + i * 16 + (lane >> 2);
#pragma unroll
        for (int jn = 0; jn < 4; jn++) {
            int c0 = colBase + warp * 32 + jn * 8 + (lane & 3) * 2;
            bf16 h0, l0, h1, l1;
            bsplit(acc[i][jn][0], h0, l0); bsplit(acc[i][jn][1], h1, l1);
            st2(&Chi[(size_t)r0 * NCout + c0], h0, h1);
            st2(&Clo[(size_t)r0 * NCout + c0], l0, l1);
            bsplit(acc[i][jn][2], h0, l0); bsplit(acc[i][jn][3], h1, l1);
            st2(&Chi[(size_t)(r0 + 8) * NCout + c0], h0, h1);
            st2(&Clo[(size_t)(r0 + 8) * NCout + c0], l0, l1);
        }
    }
}

// per-node GEMM + fused epilogue; c0 = first K-chunk (earlier chunks exactly 0)
template <int COUT, bool CAND, bool L0>
__global__ void __launch_bounds__(128) k_pn(
    const bf16* __restrict__ xh, const bf16* __restrict__ xl, size_t xstr, size_t xoff,
    const bf16* __restrict__ hh, const bf16* __restrict__ hl,
    const bf16* __restrict__ axh, const bf16* __restrict__ axl, size_t axstr, size_t axoff,
    const bf16* __restrict__ ahh, const bf16* __restrict__ ahl, size_t ahstr,
    const bf16* __restrict__ Whi, const bf16* __restrict__ Wlo,
    const float* __restrict__ Bias, float* __restrict__ R, float* __restrict__ Hfp,
    bf16* __restrict__ o1h, bf16* __restrict__ o1l,
    bf16* __restrict__ s1h, bf16* __restrict__ s1l, size_t seqOff, int c0) {
    constexpr int NCH = L0 ? 9 : 16;
    constexpr int SLICE = COUT / 4;
    constexpr int NJ = SLICE / 16;
    constexpr int WCH = COUT / 8;
    __shared__ bf16 sXh[2][64 * 24], sXl[2][64 * 24];
    __shared__ bf16 sWh[2][16 * COUT], sWl[2][16 * COUT];
    const int n = blockIdx.x, tid = threadIdx.x, lane = tid & 31, wn = tid >> 5;
    const bf16* Wh = Whi + (size_t)n * NCH * 16 * COUT;
    const bf16* Wl = Wlo + (size_t)n * NCH * 16 * COUT;

    float acc[4][NJ * 2][4];
#pragma unroll
    for (int i = 0; i < 4; i++)
#pragma unroll
        for (int j = 0; j < NJ * 2; j++)
#pragma unroll
            for (int q = 0; q < 4; q++) acc[i][j][q] = 0.f;

    auto prefetch = [&](int c) {
        int buf = c & 1;
#pragma unroll
        for (int q = tid; q < 16 * WCH; q += 128) {
            int r = q / WCH, cc = q % WCH;
            int dst = r * COUT + (cc ^ (r & (WCH - 1))) * 8;
            size_t src = (size_t)(c * 16 + r) * COUT + cc * 8;
            cp16(&sWh[buf][dst], Wh + src);
            cp16(&sWl[buf][dst], Wl + src);
        }
        if (L0 && c == 8) {
            if (tid < 64) {
                int b = tid;
                bf16 z = __float2bfloat16(0.f);
#pragma unroll
                for (int k = 0; k < 16; k++) { sXh[buf][b * 24 + k] = z; sXl[buf][b * 24 + k] = z; }
                sXh[buf][b * 24 + 0] = xh[n * xstr + xoff + b];
                sXl[buf][b * 24 + 0] = xl[n * xstr + xoff + b];
                sXh[buf][b * 24 + 1] = axh[n * axstr + axoff + b];
                sXl[buf][b * 24 + 1] = axl[n * axstr + axoff + b];
            }
        } else {
            int b = tid >> 1, half = tid & 1;
            const bf16 *ph, *pl; size_t base;
            if (L0) {
                if (c < 4) { ph = hh; pl = hl; base = (size_t)n * NB + b * 64 + c * 16 + half * 8; }
                else { ph = ahh; pl = ahl; base = (size_t)n * ahstr + b * 64 + (c - 4) * 16 + half * 8; }
            } else {
                int g = c >> 2, kl = (c & 3) * 16 + half * 8;
                if (g == 0) { ph = xh; pl = xl; base = (size_t)n * xstr + xoff + b * 64 + kl; }
                else if (g == 1) { ph = hh; pl = hl; base = (size_t)n * NB + b * 64 + kl; }
                else if (g == 2) { ph = axh; pl = axl; base = (size_t)n * axstr + axoff + b * 64 + kl; }
                else { ph = ahh; pl = ahl; base = (size_t)n * ahstr + b * 64 + kl; }
            }
            cp16(&sXh[buf][b * 24 + half * 8], ph + base);
            cp16(&sXl[buf][b * 24 + half * 8], pl + base);
        }
        asm volatile("cp.async.commit_group;");
    };

    prefetch(c0);
#pragma unroll 1
    for (int c = c0; c < NCH; c++) {
        if (c + 1 < NCH) { prefetch(c + 1); asm volatile("cp.async.wait_group 1;"); }
        else asm volatile("cp.async.wait_group 0;");
        __syncthreads();
        int buf = c & 1;
        unsigned bXh = s2u(&sXh[buf][0]);
        unsigned bXl = s2u(&sXl[buf][0]);
        unsigned bWh = s2u(&sWh[buf][0]);
        unsigned bWl = s2u(&sWl[buf][0]);
        unsigned ah[4][4], al[4][4], bh[NJ][4], bl[NJ][4];
#pragma unroll
        for (int i = 0; i < 4; i++) {
            unsigned off = (i * 16 + (lane & 15)) * 48 + (lane >> 4) * 16;
            ldsm4(ah[i], bXh + off);
            ldsm4(al[i], bXl + off);
        }
        int bk = lane & 15;
#pragma unroll
        for (int j = 0; j < NJ; j++) {
            int cch = wn * (SLICE / 8) + j * 2 + (lane >> 4);
            unsigned off = bk * (COUT * 2) + (cch ^ (bk & (WCH - 1))) * 16;
            ldsm4t(bh[j], bWh + off);
            ldsm4t(bl[j], bWl + off);
        }
#pragma unroll
        for (int i = 0; i < 4; i++)
#pragma unroll
            for (int j = 0; j < NJ; j++)
#pragma unroll
                for (int h = 0; h < 2; h++) {
                    unsigned bph[2] = {bh[j][h * 2], bh[j][h * 2 + 1]};
                    unsigned bpl[2] = {bl[j][h * 2], bl[j][h * 2 + 1]};
                    float* cc = acc[i][j * 2 + h];
                    mma16816(cc, ah[i], bph);
                    mma16816(cc, ah[i], bpl);
                    mma16816(cc, al[i], bph);
                }
        __syncthreads();
    }

#pragma unroll
    for (int i = 0; i < 4; i++) {
        int b0 = i * 16 + (lane >> 2);
#pragma unroll
        for (int jn = 0; jn < NJ * 2; jn++) {
            int o = wn * SLICE + jn * 8 + (lane & 3) * 2;
#pragma unroll
            for (int rr = 0; rr < 2; rr++) {
                int b = b0 + rr * 8;
                size_t ix = (size_t)n * NB + b * 64;
                float v0 = acc[i][jn][rr * 2 + 0] + Bias[n * COUT + o];
                float v1 = acc[i][jn][rr * 2 + 1] + Bias[n * COUT + o + 1];
                if (!CAND) {
                    float s0 = 1.f / (1.f + expf(-v0));
                    float s1 = 1.f / (1.f + expf(-v1));
                    if (o < 64) {
                        float z0 = s0 * Hfp[ix + o], z1 = s1 * Hfp[ix + o + 1];
                        bf16 h0, l0, h1, l1;
                        bsplit(z0, h0, l0); bsplit(z1, h1, l1);
                        st2(&o1h[ix + o], h0, h1);
                        st2(&o1l[ix + o], l0, l1);
                    } else {
                        R[ix + o - 64] = s0; R[ix + o - 63] = s1;
                    }
                } else {
                    float hc0 = tanhf(v0), hc1 = tanhf(v1);
                    float r0 = R[ix + o], r1 = R[ix + o + 1];
                    float hn0 = r0 * Hfp[ix + o] + (1.f - r0) * hc0;
                    float hn1 = r1 * Hfp[ix + o + 1] + (1.f - r1) * hc1;
                    Hfp[ix + o] = hn0; Hfp[ix + o + 1] = hn1;
                    bf16 h0, l0, h1, l1;
                    bsplit(hn0, h0, l0); bsplit(hn1, h1, l1);
                    st2(&o1h[ix + o], h0, h1);
                    st2(&o1l[ix + o], l0, l1);
                    if (s1h) {
                        size_t s = (size_t)n * NCSEQ + seqOff + b * 64 + o;
                        st2(&s1h[s], h0, h1);
                        st2(&s1l[s], l0, l1);
                    }
                }
            }
        }
    }
}

__global__ void k_final(const float* __restrict__ H, const float* __restrict__ cw,
                        const float* __restrict__ cb, float* __restrict__ out) {
    int idx = blockIdx.x * 256 + threadIdx.x;
    if (idx >= BB * NN) return;
    int n = idx % NN, b = idx / NN;
    const float* h = H + (size_t)n * NB + b * 64;
    float hv[HID];
#pragma unroll
    for (int j = 0; j < HID; j++) hv[j] = h[j];
#pragma unroll
    for (int o = 0; o < TT; o++) {
        float s = cb[o];
#pragma unroll
        for (int j = 0; j < HID; j++) s = fmaf(hv[j], cw[o * HID + j], s);
        out[((size_t)b * TT + o) * NN + n] = s;
    }
}

extern "C" void kernel_launch(void* const* d_in, const int* in_sizes, int n_in,
                              void* d_out, int out_size) {
    const float* src = (const float*)d_in[0];
    const float* E = (const float*)d_in[1];
    const float* cw = (const float*)d_in[10];
    const float* cb = (const float*)d_in[11];
    float* out = (float*)d_out;

#define SYM(T, v, s) T* v; cudaGetSymbolAddress((void**)&v, s)
    SYM(bf16, Ahi, g_Ahi); SYM(bf16, Alo, g_Alo);
    SYM(bf16, X0hi, g_X0hi); SYM(bf16, X0lo, g_X0lo);
    SYM(bf16, AX0hi, g_AX0hi); SYM(bf16, AX0lo, g_AX0lo);
    SYM(bf16, WG0h, g_WG0h); SYM(bf16, WG0l, g_WG0l);
    SYM(bf16, WC0h, g_WC0h); SYM(bf16, WC0l, g_WC0l);
    SYM(bf16, WG1h, g_WG1h); SYM(bf16, WG1l, g_WG1l);
    SYM(bf16, WC1h, g_WC1h); SYM(bf16, WC1l, g_WC1l);
    SYM(float, Bg0, g_Bg0); SYM(float, Bc0, g_Bc0);
    SYM(float, Bg1, g_Bg1); SYM(float, Bc1, g_Bc1);
    SYM(float, H, g_H); SYM(float, R, g_R);
    SYM(bf16, Hhi, g_Hhi); SYM(bf16, Hlo, g_Hlo);
    SYM(bf16, ZHhi, g_ZHhi); SYM(bf16, ZHlo, g_ZHlo);
    SYM(bf16, AHhi, g_AHhi); SYM(bf16, AHlo, g_AHlo);
    SYM(bf16, AZHhi, g_AZHhi); SYM(bf16, AZHlo, g_AZHlo);
    SYM(float, H2, g_H2); SYM(float, R2, g_R2);
    SYM(bf16, H2hi, g_H2hi); SYM(bf16, H2lo, g_H2lo);
    SYM(bf16, ZH2hi, g_ZH2hi); SYM(bf16, ZH2lo, g_ZH2lo);
    SYM(bf16, AH2hi, g_AH2hi); SYM(bf16, AH2lo, g_AH2lo);
    SYM(bf16, AZH2hi, g_AZH2hi); SYM(bf16, AZH2lo, g_AZH2lo);
    SYM(bf16, Shi, g_SEQhi); SYM(bf16, Slo, g_SEQlo);
    SYM(bf16, AShi, g_ASEQhi); SYM(bf16, ASlo, g_ASEQlo);

    cudaStream_t s0 = 0, s2;
    int loPri = 0, hiPri = 0;
    cudaDeviceGetStreamPriorityRange(&loPri, &hiPri);
    cudaStreamCreateWithPriority(&s2, cudaStreamNonBlocking, loPri);
    cudaEvent_t ev[TT], evFork, evJoin;
    for (int i = 0; i < TT; i++) cudaEventCreateWithFlags(&ev[i], cudaEventDisableTiming);
    cudaEventCreateWithFlags(&evFork, cudaEventDisableTiming);
    cudaEventCreateWithFlags(&evJoin, cudaEventDisableTiming);

    const int ZG = (NN * NB + 255) / 256;
    const dim3 GSTEP(NB / 128, 14);

    // fork s2 immediately: layer-1-private prologue overlaps s0's prologue
    cudaEventRecord(evFork, s0);
    cudaStreamWaitEvent(s2, evFork, 0);
    k_nodewsplit<<<dim3(256 * 128 / 256, 14), 256, 0, s2>>>(E, (const float*)d_in[6], WG1h, WG1l, 128, 256, 1);
    k_nodew<<<((long)NN * 128 + 255) / 256, 256, 0, s2>>>(E, (const float*)d_in[7], Bg1, 128);
    k_nodewsplit<<<dim3(256 * 64 / 256, 14), 256, 0, s2>>>(E, (const float*)d_in[8], WC1h, WC1l, 64, 256, 1);
    k_nodew<<<((long)NN * 64 + 255) / 256, 256, 0, s2>>>(E, (const float*)d_in[9], Bc1, 64);
    k_zeroH<<<ZG, 256, 0, s2>>>(H2, H2hi, H2lo, AH2hi, AH2lo, AZH2hi, AZH2lo);

    // s0 prologue (layer-0 deps only)
    k_supports<<<NP, 256, 0, s0>>>(E, Ahi, Alo);
    k_srcsplit<<<(NP * NC0 + 255) / 256, 256, 0, s0>>>(src, X0hi, X0lo);
    k_nodewsplit<<<dim3(144 * 128 / 256, 14), 256, 0, s0>>>(E, (const float*)d_in[2], WG0h, WG0l, 128, 144, 0);
    k_nodew<<<((long)NN * 128 + 255) / 256, 256, 0, s0>>>(E, (const float*)d_in[3], Bg0, 128);
    k_nodewsplit<<<dim3(144 * 64 / 256, 14), 256, 0, s0>>>(E, (const float*)d_in[4], WC0h, WC0l, 64, 144, 0);
    k_nodew<<<((long)NN * 64 + 255) / 256, 256, 0, s0>>>(E, (const float*)d_in[5], Bc0, 64);
    k_mma<<<dim3(NC0 / 128, 14), 128, 0, s0>>>(Ahi, Alo, X0hi, X0lo, AX0hi, AX0lo, NC0, NC0);

    // layer 0 on s0; per-step A@H lands directly into ASEQ slot (t-1)
    k_zeroH<<<ZG, 256, 0, s0>>>(H, Hhi, Hlo, AHhi, AHlo, AZHhi, AZHlo);
    for (int t = 0; t < TT; t++) {
        const bf16* ahh = AHhi; const bf16* ahl = AHlo; size_t ahstr = NB;
        if (t > 0) {
            bf16* dsth = AShi + (size_t)(t - 1) * NB;
            bf16* dstl = ASlo + (size_t)(t - 1) * NB;
            k_mma<<<GSTEP, 128, 0, s0>>>(Ahi, Alo, Hhi, Hlo, dsth, dstl, NB, NCSEQ);
            cudaEventRecord(ev[t - 1], s0);
            ahh = dsth; ahl = dstl; ahstr = NCSEQ;
        }
        int c0g = (t == 0) ? 8 : 0;   // t=0: h and Ah chunks are exactly zero
        k_pn<128, false, true><<<NN, 128, 0, s0>>>(X0hi, X0lo, NC0, (size_t)t * 64,
            Hhi, Hlo, AX0hi, AX0lo, NC0, (size_t)t * 64, ahh, ahl, ahstr,
            WG0h, WG0l, Bg0, R, H, ZHhi, ZHlo, (bf16*)0, (bf16*)0, 0, c0g);
        if (t > 0)
            k_mma<<<GSTEP, 128, 0, s0>>>(Ahi, Alo, ZHhi, ZHlo, AZHhi, AZHlo, NB, NB);
        k_pn<64, true, true><<<NN, 128, 0, s0>>>(X0hi, X0lo, NC0, (size_t)t * 64,
            ZHhi, ZHlo, AX0hi, AX0lo, NC0, (size_t)t * 64, AZHhi, AZHlo, (size_t)NB,
            WC0h, WC0l, Bc0, R, H, Hhi, Hlo, Shi, Slo, (size_t)t * NB, c0g);
    }
    k_mma<<<GSTEP, 128, 0, s0>>>(Ahi, Alo, Shi + (size_t)11 * NB, Slo + (size_t)11 * NB,
                                 AShi + (size_t)11 * NB, ASlo + (size_t)11 * NB, NCSEQ, NCSEQ);
    cudaEventRecord(ev[11], s0);

    // layer 1 on s2, gated per step
    for (int t = 0; t < TT; t++) {
        cudaStreamWaitEvent(s2, ev[t], 0);
        if (t > 0)
            k_mma<<<GSTEP, 128, 0, s2>>>(Ahi, Alo, H2hi, H2lo, AH2hi, AH2lo, NB, NB);
        k_pn<128, false, false><<<NN, 128, 0, s2>>>(Shi, Slo, NCSEQ, (size_t)t * NB,
            H2hi, H2lo, AShi, ASlo, NCSEQ, (size_t)t * NB, AH2hi, AH2lo, (size_t)NB,
            WG1h, WG1l, Bg1, R2, H2, ZH2hi, ZH2lo, (bf16*)0, (bf16*)0, 0, 0);
        if (t > 0)
            k_mma<<<GSTEP, 128, 0, s2>>>(Ahi, Alo, ZH2hi, ZH2lo, AZH2hi, AZH2lo, NB, NB);
        k_pn<64, true, false><<<NN, 128, 0, s2>>>(Shi, Slo, NCSEQ, (size_t)t * NB,
            ZH2hi, ZH2lo, AShi, ASlo, NCSEQ, (size_t)t * NB, AZH2hi, AZH2lo, (size_t)NB,
            WC1h, WC1l, Bc1, R2, H2, H2hi, H2lo, (bf16*)0, (bf16*)0, 0, 0);
    }
    k_final<<<(BB * NN + 255) / 256, 256, 0, s2>>>(H2, cw, cb, out);

    cudaEventRecord(evJoin, s2);
    cudaStreamWaitEvent(s0, evJoin, 0);

    cudaStreamCaptureStatus st = cudaStreamCaptureStatusNone;
    cudaStreamIsCapturing(s0, &st);
    if (st == cudaStreamCaptureStatusNone) {
        cudaStreamDestroy(s2);
        for (int i = 0; i < TT; i++) cudaEventDestroy(ev[i]);
        cudaEventDestroy(evFork);
        cudaEventDestroy(evJoin);
    }
}

// round 16
// speedup vs baseline: 1.6930x; 1.0096x over previous
#include <cuda_runtime.h>
#include <cuda_bf16.h>
#include <math.h>
#include <stdint.h>

#define NN 883
#define NP 896
#define BB 64
#define TT 12
#define HID 64
#define EMBD 10
#define NB 4096
#define NCSEQ 49152
#define NC0 768
typedef __nv_bfloat16 bf16;

__device__ bf16 g_Ahi[NP * NP];
__device__ bf16 g_Alo[NP * NP];
__device__ bf16 g_X0hi[NP * NC0];
__device__ bf16 g_X0lo[NP * NC0];
__device__ bf16 g_AX0hi[NP * NC0];
__device__ bf16 g_AX0lo[NP * NC0];
__device__ bf16 g_WG0h[NN * 144 * 128];
__device__ bf16 g_WG0l[NN * 144 * 128];
__device__ bf16 g_WC0h[NN * 144 * 64];
__device__ bf16 g_WC0l[NN * 144 * 64];
__device__ bf16 g_WG1h[NN * 256 * 128];
__device__ bf16 g_WG1l[NN * 256 * 128];
__device__ bf16 g_WC1h[NN * 256 * 64];
__device__ bf16 g_WC1l[NN * 256 * 64];
__device__ float g_Bg0[NN * 128];
__device__ float g_Bc0[NN * 64];
__device__ float g_Bg1[NN * 128];
__device__ float g_Bc1[NN * 64];
__device__ float g_H[NN * NB];
__device__ float g_R[NN * NB];
__device__ bf16 g_Hhi[NP * NB];
__device__ bf16 g_Hlo[NP * NB];
__device__ bf16 g_ZHhi[NP * NB];
__device__ bf16 g_ZHlo[NP * NB];
__device__ bf16 g_AHhi[NP * NB];
__device__ bf16 g_AHlo[NP * NB];
__device__ bf16 g_AZHhi[NP * NB];
__device__ bf16 g_AZHlo[NP * NB];
__device__ float g_H2[NN * NB];
__device__ float g_R2[NN * NB];
__device__ bf16 g_H2hi[NP * NB];
__device__ bf16 g_H2lo[NP * NB];
__device__ bf16 g_ZH2hi[NP * NB];
__device__ bf16 g_ZH2lo[NP * NB];
__device__ bf16 g_AH2hi[NP * NB];
__device__ bf16 g_AH2lo[NP * NB];
__device__ bf16 g_AZH2hi[NP * NB];
__device__ bf16 g_AZH2lo[NP * NB];
__device__ bf16 g_SEQhi[(size_t)NP * NCSEQ];
__device__ bf16 g_SEQlo[(size_t)NP * NCSEQ];
__device__ bf16 g_ASEQhi[(size_t)NP * NCSEQ];
__device__ bf16 g_ASEQlo[(size_t)NP * NCSEQ];

__device__ __forceinline__ void bsplit(float v, bf16& hi, bf16& lo) {
    hi = __float2bfloat16_rn(v);
    lo = __float2bfloat16_rn(v - __bfloat162float(hi));
}
__device__ __forceinline__ unsigned s2u(const void* p) {
    return (unsigned)__cvta_generic_to_shared(p);
}
__device__ __forceinline__ void cp16(void* s, const void* g) {
    asm volatile("cp.async.cg.shared.global [%0], [%1], 16;" :: "r"(s2u(s)), "l"(g));
}
__device__ __forceinline__ void ldsm4(unsigned* r, unsigned a) {
    asm volatile("ldmatrix.sync.aligned.m8n8.x4.shared.b16 {%0,%1,%2,%3}, [%4];"
                 : "=r"(r[0]), "=r"(r[1]), "=r"(r[2]), "=r"(r[3]) : "r"(a));
}
__device__ __forceinline__ void ldsm4t(unsigned* r, unsigned a) {
    asm volatile("ldmatrix.sync.aligned.m8n8.x4.trans.shared.b16 {%0,%1,%2,%3}, [%4];"
                 : "=r"(r[0]), "=r"(r[1]), "=r"(r[2]), "=r"(r[3]) : "r"(a));
}
__device__ __forceinline__ void mma16816(float* c, const unsigned* a, const unsigned* b) {
    asm volatile(
        "mma.sync.aligned.m16n8k16.row.col.f32.bf16.bf16.f32 "
        "{%0,%1,%2,%3},{%4,%5,%6,%7},{%8,%9},{%0,%1,%2,%3};"
        : "+f"(c[0]), "+f"(c[1]), "+f"(c[2]), "+f"(c[3])
        : "r"(a[0]), "r"(a[1]), "r"(a[2]), "r"(a[3]), "r"(b[0]), "r"(b[1]));
}
__device__ __forceinline__ void st2(bf16* p, bf16 a, bf16 b) {
    __nv_bfloat162 v; v.x = a; v.y = b;
    *(__nv_bfloat162*)p = v;
}

__global__ void __launch_bounds__(256) k_supports(const float* __restrict__ E,
                                                  bf16* __restrict__ Ahi,
                                                  bf16* __restrict__ Alo) {
    int n = blockIdx.x, tid = threadIdx.x;
    if (n >= NN) {
        for (int m = tid; m < NP; m += 256) { Ahi[n * NP + m] = __float2bfloat16(0.f); Alo[n * NP + m] = __float2bfloat16(0.f); }
        return;
    }
    __shared__ float row[NN];
    __shared__ float red[8];
    __shared__ float ssum;
    float en[EMBD];
#pragma unroll
    for (int d = 0; d < EMBD; d++) en[d] = E[n * EMBD + d];
    float lmax = -1e30f;
    for (int m = tid; m < NN; m += 256) {
        float s = 0.f;
#pragma unroll
        for (int d = 0; d < EMBD; d++) s = fmaf(en[d], E[m * EMBD + d], s);
        s = fmaxf(s, 0.f);
        row[m] = s;
        lmax = fmaxf(lmax, s);
    }
#pragma unroll
    for (int o = 16; o; o >>= 1) lmax = fmaxf(lmax, __shfl_xor_sync(~0u, lmax, o));
    if ((tid & 31) == 0) red[tid >> 5] = lmax;
    __syncthreads();
    if (tid == 0) { float mx = red[0]; for (int w = 1; w < 8; w++) mx = fmaxf(mx, red[w]); red[0] = mx; }
    __syncthreads();
    float mx = red[0];
    __syncthreads();
    float lsum = 0.f;
    for (int m = tid; m < NN; m += 256) { float e = expf(row[m] - mx); row[m] = e; lsum += e; }
#pragma unroll
    for (int o = 16; o; o >>= 1) lsum += __shfl_xor_sync(~0u, lsum, o);
    if ((tid & 31) == 0) red[tid >> 5] = lsum;
    __syncthreads();
    if (tid == 0) { float s = 0.f; for (int w = 0; w < 8; w++) s += red[w]; ssum = s; }
    __syncthreads();
    float inv = 1.f / ssum;
    for (int m = tid; m < NP; m += 256) {
        float v = (m < NN) ? row[m] * inv : 0.f;
        bf16 h, l; bsplit(v, h, l);
        Ahi[n * NP + m] = h; Alo[n * NP + m] = l;
    }
}

__global__ void k_srcsplit(const float* __restrict__ src, bf16* __restrict__ hi,
                           bf16* __restrict__ lo) {
    int idx = blockIdx.x * 256 + threadIdx.x;
    if (idx >= NP * NC0) return;
    int n = idx / NC0, col = idx % NC0, t = col >> 6, b = col & 63;
    float v = (n < NN) ? src[((size_t)b * TT + t) * NN + n] : 0.f;
    bf16 h, l; bsplit(v, h, l);
    hi[idx] = h; lo[idx] = l;
}

__global__ void __launch_bounds__(256) k_nodewsplit(
    const float* __restrict__ E, const float* __restrict__ pool,
    bf16* __restrict__ Whi, bf16* __restrict__ Wlo, int COUT, int KDp, int layer) {
    __shared__ float Es[64][EMBD];
    __shared__ float Ps[EMBD][256];
    const int tid = threadIdx.x;
    const int colBase = blockIdx.x * 256;
    const int nBase = blockIdx.y * 64;
    const long RC = (long)KDp * COUT;

    for (int i = tid; i < 64 * EMBD; i += 256) {
        int nn = nBase + i / EMBD;
        Es[i / EMBD][i % EMBD] = (nn < NN) ? E[nn * EMBD + i % EMBD] : 0.f;
    }
    {
        int c = colBase + tid;
        int k = c / COUT, o = c % COUT;
        int row, ROWS;
        if (layer == 0) {
            ROWS = 130;
            if (k < 64) row = k + 1;
            else if (k < 128) row = k + 2;
            else if (k == 128) row = 0;
            else if (k == 129) row = 65;
            else row = -1;
        } else { ROWS = 256; row = k; }
#pragma unroll
        for (int d = 0; d < EMBD; d++)
            Ps[d][tid] = (row >= 0) ? pool[((long)d * ROWS + row) * COUT + o] : 0.f;
    }
    __syncthreads();

    float pv[EMBD];
#pragma unroll
    for (int d = 0; d < EMBD; d++) pv[d] = Ps[d][tid];
#pragma unroll 4
    for (int i = 0; i < 64; i++) {
        int nn = nBase + i;
        if (nn >= NN) break;
        float s = 0.f;
#pragma unroll
        for (int d = 0; d < EMBD; d++) s = fmaf(Es[i][d], pv[d], s);
        bf16 h, l; bsplit(s, h, l);
        size_t ix = (size_t)nn * RC + colBase + tid;
        Whi[ix] = h; Wlo[ix] = l;
    }
}

__global__ void k_nodew(const float* __restrict__ E, const float* __restrict__ pool,
                        float* __restrict__ out, int RC) {
    long idx = (long)blockIdx.x * 256 + threadIdx.x;
    if (idx >= (long)NN * RC) return;
    int n = (int)(idx / RC), rem = (int)(idx % RC);
    float s = 0.f;
#pragma unroll
    for (int d = 0; d < EMBD; d++) s = fmaf(E[n * EMBD + d], pool[(long)d * RC + rem], s);
    out[idx] = s;
}

__global__ void k_zeroH(float* H, bf16* Hhi, bf16* Hlo, bf16* AHhi, bf16* AHlo,
                        bf16* AZHhi, bf16* AZHlo) {
    int i = blockIdx.x * 256 + threadIdx.x;
    if (i < NN * NB) H[i] = 0.f;
    if (i < NP * NB / 2) {
        ((uint32_t*)Hhi)[i] = 0u; ((uint32_t*)Hlo)[i] = 0u;
        ((uint32_t*)AHhi)[i] = 0u; ((uint32_t*)AHlo)[i] = 0u;
        ((uint32_t*)AZHhi)[i] = 0u; ((uint32_t*)AZHlo)[i] = 0u;
    }
}

__global__ void __launch_bounds__(128) k_mma(const bf16* __restrict__ Ahi,
                                             const bf16* __restrict__ Alo,
                                             const bf16* __restrict__ Xhi,
                                             const bf16* __restrict__ Xlo,
                                             bf16* __restrict__ Chi,
                                             bf16* __restrict__ Clo,
                                             int NCin, int NCout) {
    __shared__ bf16 sAh[2][64 * 16], sAl[2][64 * 16];
    __shared__ bf16 sXh[2][16 * 128], sXl[2][16 * 128];
    const int tid = threadIdx.x, lane = tid & 31, warp = tid >> 5;
    const int rowBase = blockIdx.y * 64, colBase = blockIdx.x * 128;
    const int ar = tid >> 1, ac = (tid & 1) * 8;

    float acc[4][4][4];
#pragma unroll
    for (int i = 0; i < 4; i++)
#pragma unroll
        for (int j = 0; j < 4; j++)
#pragma unroll
            for (int q = 0; q < 4; q++) acc[i][j][q] = 0.f;

    auto prefetch = [&](int kt, int buf) {
        int k0 = kt * 16;
        cp16(&sAh[buf][ar * 16 + ac], Ahi + (size_t)(rowBase + ar) * NP + k0 + ac);
        cp16(&sAl[buf][ar * 16 + ac], Alo + (size_t)(rowBase + ar) * NP + k0 + ac);
#pragma unroll
        for (int i = 0; i < 2; i++) {
            int idx = tid + i * 128;
            int r = idx >> 4, cc = idx & 15;
            int dst = r * 128 + ((cc ^ r) & 15) * 8;
            cp16(&sXh[buf][dst], Xhi + (size_t)(k0 + r) * NCin + colBase + cc * 8);
            cp16(&sXl[buf][dst], Xlo + (size_t)(k0 + r) * NCin + colBase + cc * 8);
        }
        asm volatile("cp.async.commit_group;");
    };

    prefetch(0, 0);
    const int aoff = (lane & 15) * 32 + (lane >> 4) * 16;
    const int bk = lane & 15, bch = lane >> 4;

#pragma unroll 1
    for (int kt = 0; kt < 56; ++kt) {
        if (kt < 55) {
            prefetch(kt + 1, (kt + 1) & 1);
            asm volatile("cp.async.wait_group 1;");
        } else {
            asm volatile("cp.async.wait_group 0;");
        }
        __syncthreads();
        int buf = kt & 1;
        unsigned bAh = s2u(&sAh[buf][0]);
        unsigned bAl = s2u(&sAl[buf][0]);
        unsigned bXh = s2u(&sXh[buf][0]);
        unsigned bXl = s2u(&sXl[buf][0]);
        unsigned ah[4][4], al[4][4], bh[2][4], bl[2][4];
#pragma unroll
        for (int i = 0; i < 4; i++) {
            ldsm4(ah[i], bAh + i * 512 + aoff);
            ldsm4(al[i], bAl + i * 512 + aoff);
        }
#pragma unroll
        for (int j = 0; j < 2; j++) {
            int c = warp * 4 + j * 2 + bch;
            int cp = c ^ bk;
            ldsm4t(bh[j], bXh + bk * 256 + cp * 16);
            ldsm4t(bl[j], bXl + bk * 256 + cp * 16);
        }
#pragma unroll
        for (int i = 0; i < 4; i++)
#pragma unroll
            for (int j = 0; j < 2; j++)
#pragma unroll
                for (int h = 0; h < 2; h++) {
                    unsigned bph[2] = {bh[j][h * 2], bh[j][h * 2 + 1]};
                    unsigned bpl[2] = {bl[j][h * 2], bl[j][h * 2 + 1]};
                    float* cc = acc[i][j * 2 + h];
                    mma16816(cc, ah[i], bph);
                    mma16816(cc, ah[i], bpl);
                    mma16816(cc, al[i], bph);
                }
        __syncthreads();
    }
#pragma unroll
    for (int i = 0; i < 4; i++) {
        int r0 = rowBase + i * 16 + (lane >> 2);
#pragma unroll
        for (int jn = 0; jn < 4; jn++) {
            int c0 = colBase + warp * 32 + jn * 8 + (lane & 3) * 2;
            bf16 h0, l0, h1, l1;
            bsplit(acc[i][jn][0], h0, l0); bsplit(acc[i][jn][1], h1, l1);
            st2(&Chi[(size_t)r0 * NCout + c0], h0, h1);
            st2(&Clo[(size_t)r0 * NCout + c0], l0, l1);
            bsplit(acc[i][jn][2], h0, l0); bsplit(acc[i][jn][3], h1, l1);
            st2(&Chi[(size_t)(r0 + 8) * NCout + c0], h0, h1);
            st2(&Clo[(size_t)(r0 + 8) * NCout + c0], l0, l1);
        }
    }
}

// per-node GEMM + fused epilogue.
// Chunk iteration: actual = startC + it + (gap && it>=4 ? 4 : 0), it in [0,nCh).
// Skipped chunks contribute exactly +0.0f (pre-zeroed operands) — bitwise safe.
template <int COUT, bool CAND, bool L0>
__global__ void __launch_bounds__(128) k_pn(
    const bf16* __restrict__ xh, const bf16* __restrict__ xl, size_t xstr, size_t xoff,
    const bf16* __restrict__ hh, const bf16* __restrict__ hl,
    const bf16* __restrict__ axh, const bf16* __restrict__ axl, size_t axstr, size_t axoff,
    const bf16* __restrict__ ahh, const bf16* __restrict__ ahl, size_t ahstr,
    const bf16* __restrict__ Whi, const bf16* __restrict__ Wlo,
    const float* __restrict__ Bias, float* __restrict__ R, float* __restrict__ Hfp,
    bf16* __restrict__ o1h, bf16* __restrict__ o1l,
    bf16* __restrict__ s1h, bf16* __restrict__ s1l, size_t seqOff,
    int startC, int nCh, int gap) {
    constexpr int NCH = L0 ? 9 : 16;
    constexpr int SLICE = COUT / 4;
    constexpr int NJ = SLICE / 16;
    constexpr int WCH = COUT / 8;
    __shared__ bf16 sXh[2][64 * 24], sXl[2][64 * 24];
    __shared__ bf16 sWh[2][16 * COUT], sWl[2][16 * COUT];
    const int n = blockIdx.x, tid = threadIdx.x, lane = tid & 31, wn = tid >> 5;
    const bf16* Wh = Whi + (size_t)n * NCH * 16 * COUT;
    const bf16* Wl = Wlo + (size_t)n * NCH * 16 * COUT;

    float acc[4][NJ * 2][4];
#pragma unroll
    for (int i = 0; i < 4; i++)
#pragma unroll
        for (int j = 0; j < NJ * 2; j++)
#pragma unroll
            for (int q = 0; q < 4; q++) acc[i][j][q] = 0.f;

    auto remap = [&](int it) { return startC + it + ((gap && it >= 4) ? 4 : 0); };

    auto prefetch = [&](int c, int buf) {
#pragma unroll
        for (int q = tid; q < 16 * WCH; q += 128) {
            int r = q / WCH, cc = q % WCH;
            int dst = r * COUT + (cc ^ (r & (WCH - 1))) * 8;
            size_t src = (size_t)(c * 16 + r) * COUT + cc * 8;
            cp16(&sWh[buf][dst], Wh + src);
            cp16(&sWl[buf][dst], Wl + src);
        }
        if (L0 && c == 8) {
            if (tid < 64) {
                int b = tid;
                bf16 z = __float2bfloat16(0.f);
#pragma unroll
                for (int k = 0; k < 16; k++) { sXh[buf][b * 24 + k] = z; sXl[buf][b * 24 + k] = z; }
                sXh[buf][b * 24 + 0] = xh[n * xstr + xoff + b];
                sXl[buf][b * 24 + 0] = xl[n * xstr + xoff + b];
                sXh[buf][b * 24 + 1] = axh[n * axstr + axoff + b];
                sXl[buf][b * 24 + 1] = axl[n * axstr + axoff + b];
            }
        } else {
            int b = tid >> 1, half = tid & 1;
            const bf16 *ph, *pl; size_t base;
            if (L0) {
                if (c < 4) { ph = hh; pl = hl; base = (size_t)n * NB + b * 64 + c * 16 + half * 8; }
                else { ph = ahh; pl = ahl; base = (size_t)n * ahstr + b * 64 + (c - 4) * 16 + half * 8; }
            } else {
                int g = c >> 2, kl = (c & 3) * 16 + half * 8;
                if (g == 0) { ph = xh; pl = xl; base = (size_t)n * xstr + xoff + b * 64 + kl; }
                else if (g == 1) { ph = hh; pl = hl; base = (size_t)n * NB + b * 64 + kl; }
                else if (g == 2) { ph = axh; pl = axl; base = (size_t)n * axstr + axoff + b * 64 + kl; }
                else { ph = ahh; pl = ahl; base = (size_t)n * ahstr + b * 64 + kl; }
            }
            cp16(&sXh[buf][b * 24 + half * 8], ph + base);
            cp16(&sXl[buf][b * 24 + half * 8], pl + base);
        }
        asm volatile("cp.async.commit_group;");
    };

    prefetch(remap(0), 0);
#pragma unroll 1
    for (int it = 0; it < nCh; it++) {
        if (it + 1 < nCh) { prefetch(remap(it + 1), (it + 1) & 1); asm volatile("cp.async.wait_group 1;"); }
        else asm volatile("cp.async.wait_group 0;");
        __syncthreads();
        int buf = it & 1;
        unsigned bXh = s2u(&sXh[buf][0]);
        unsigned bXl = s2u(&sXl[buf][0]);
        unsigned bWh = s2u(&sWh[buf][0]);
        unsigned bWl = s2u(&sWl[buf][0]);
        unsigned ah[4][4], al[4][4], bh[NJ][4], bl[NJ][4];
#pragma unroll
        for (int i = 0; i < 4; i++) {
            unsigned off = (i * 16 + (lane & 15)) * 48 + (lane >> 4) * 16;
            ldsm4(ah[i], bXh + off);
            ldsm4(al[i], bXl + off);
        }
        int bk = lane & 15;
#pragma unroll
        for (int j = 0; j < NJ; j++) {
            int cch = wn * (SLICE / 8) + j * 2 + (lane >> 4);
            unsigned off = bk * (COUT * 2) + (cch ^ (bk & (WCH - 1))) * 16;
            ldsm4t(bh[j], bWh + off);
            ldsm4t(bl[j], bWl + off);
        }
#pragma unroll
        for (int i = 0; i < 4; i++)
#pragma unroll
            for (int j = 0; j < NJ; j++)
#pragma unroll
                for (int h = 0; h < 2; h++) {
                    unsigned bph[2] = {bh[j][h * 2], bh[j][h * 2 + 1]};
                    unsigned bpl[2] = {bl[j][h * 2], bl[j][h * 2 + 1]};
                    float* cc = acc[i][j * 2 + h];
                    mma16816(cc, ah[i], bph);
                    mma16816(cc, ah[i], bpl);
                    mma16816(cc, al[i], bph);
                }
        __syncthreads();
    }

#pragma unroll
    for (int i = 0; i < 4; i++) {
        int b0 = i * 16 + (lane >> 2);
#pragma unroll
        for (int jn = 0; jn < NJ * 2; jn++) {
            int o = wn * SLICE + jn * 8 + (lane & 3) * 2;
#pragma unroll
            for (int rr = 0; rr < 2; rr++) {
                int b = b0 + rr * 8;
                size_t ix = (size_t)n * NB + b * 64;
                float v0 = acc[i][jn][rr * 2 + 0] + Bias[n * COUT + o];
                float v1 = acc[i][jn][rr * 2 + 1] + Bias[n * COUT + o + 1];
                if (!CAND) {
                    float s0 = 1.f / (1.f + expf(-v0));
                    float s1 = 1.f / (1.f + expf(-v1));
                    if (o < 64) {
                        float z0 = s0 * Hfp[ix + o], z1 = s1 * Hfp[ix + o + 1];
                        bf16 h0, l0, h1, l1;
                        bsplit(z0, h0, l0); bsplit(z1, h1, l1);
                        st2(&o1h[ix + o], h0, h1);
                        st2(&o1l[ix + o], l0, l1);
                    } else {
                        R[ix + o - 64] = s0; R[ix + o - 63] = s1;
                    }
                } else {
                    float hc0 = tanhf(v0), hc1 = tanhf(v1);
                    float r0 = R[ix + o], r1 = R[ix + o + 1];
                    float hn0 = r0 * Hfp[ix + o] + (1.f - r0) * hc0;
                    float hn1 = r1 * Hfp[ix + o + 1] + (1.f - r1) * hc1;
                    Hfp[ix + o] = hn0; Hfp[ix + o + 1] = hn1;
                    bf16 h0, l0, h1, l1;
                    bsplit(hn0, h0, l0); bsplit(hn1, h1, l1);
                    st2(&o1h[ix + o], h0, h1);
                    st2(&o1l[ix + o], l0, l1);
                    if (s1h) {
                        size_t s = (size_t)n * NCSEQ + seqOff + b * 64 + o;
                        st2(&s1h[s], h0, h1);
                        st2(&s1l[s], l0, l1);
                    }
                }
            }
        }
    }
}

__global__ void k_final(const float* __restrict__ H, const float* __restrict__ cw,
                        const float* __restrict__ cb, float* __restrict__ out) {
    int idx = blockIdx.x * 256 + threadIdx.x;
    if (idx >= BB * NN) return;
    int n = idx % NN, b = idx / NN;
    const float* h = H + (size_t)n * NB + b * 64;
    float hv[HID];
#pragma unroll
    for (int j = 0; j < HID; j++) hv[j] = h[j];
#pragma unroll
    for (int o = 0; o < TT; o++) {
        float s = cb[o];
#pragma unroll
        for (int j = 0; j < HID; j++) s = fmaf(hv[j], cw[o * HID + j], s);
        out[((size_t)b * TT + o) * NN + n] = s;
    }
}

extern "C" void kernel_launch(void* const* d_in, const int* in_sizes, int n_in,
                              void* d_out, int out_size) {
    const float* src = (const float*)d_in[0];
    const float* E = (const float*)d_in[1];
    const float* cw = (const float*)d_in[10];
    const float* cb = (const float*)d_in[11];
    float* out = (float*)d_out;

#define SYM(T, v, s) T* v; cudaGetSymbolAddress((void**)&v, s)
    SYM(bf16, Ahi, g_Ahi); SYM(bf16, Alo, g_Alo);
    SYM(bf16, X0hi, g_X0hi); SYM(bf16, X0lo, g_X0lo);
    SYM(bf16, AX0hi, g_AX0hi); SYM(bf16, AX0lo, g_AX0lo);
    SYM(bf16, WG0h, g_WG0h); SYM(bf16, WG0l, g_WG0l);
    SYM(bf16, WC0h, g_WC0h); SYM(bf16, WC0l, g_WC0l);
    SYM(bf16, WG1h, g_WG1h); SYM(bf16, WG1l, g_WG1l);
    SYM(bf16, WC1h, g_WC1h); SYM(bf16, WC1l, g_WC1l);
    SYM(float, Bg0, g_Bg0); SYM(float, Bc0, g_Bc0);
    SYM(float, Bg1, g_Bg1); SYM(float, Bc1, g_Bc1);
    SYM(float, H, g_H); SYM(float, R, g_R);
    SYM(bf16, Hhi, g_Hhi); SYM(bf16, Hlo, g_Hlo);
    SYM(bf16, ZHhi, g_ZHhi); SYM(bf16, ZHlo, g_ZHlo);
    SYM(bf16, AHhi, g_AHhi); SYM(bf16, AHlo, g_AHlo);
    SYM(bf16, AZHhi, g_AZHhi); SYM(bf16, AZHlo, g_AZHlo);
    SYM(float, H2, g_H2); SYM(float, R2, g_R2);
    SYM(bf16, H2hi, g_H2hi); SYM(bf16, H2lo, g_H2lo);
    SYM(bf16, ZH2hi, g_ZH2hi); SYM(bf16, ZH2lo, g_ZH2lo);
    SYM(bf16, AH2hi, g_AH2hi); SYM(bf16, AH2lo, g_AH2lo);
    SYM(bf16, AZH2hi, g_AZH2hi); SYM(bf16, AZH2lo, g_AZH2lo);
    SYM(bf16, Shi, g_SEQhi); SYM(bf16, Slo, g_SEQlo);
    SYM(bf16, AShi, g_ASEQhi); SYM(bf16, ASlo, g_ASEQlo);

    cudaStream_t s0 = 0, s2;
    int loPri = 0, hiPri = 0;
    cudaDeviceGetStreamPriorityRange(&loPri, &hiPri);
    cudaStreamCreateWithPriority(&s2, cudaStreamNonBlocking, loPri);
    cudaEvent_t ev[TT], evFork, evJoin;
    for (int i = 0; i < TT; i++) cudaEventCreateWithFlags(&ev[i], cudaEventDisableTiming);
    cudaEventCreateWithFlags(&evFork, cudaEventDisableTiming);
    cudaEventCreateWithFlags(&evJoin, cudaEventDisableTiming);

    const int ZG = (NN * NB + 255) / 256;
    const dim3 GSTEP(NB / 128, 14);

    cudaEventRecord(evFork, s0);
    cudaStreamWaitEvent(s2, evFork, 0);
    k_nodewsplit<<<dim3(256 * 128 / 256, 14), 256, 0, s2>>>(E, (const float*)d_in[6], WG1h, WG1l, 128, 256, 1);
    k_nodew<<<((long)NN * 128 + 255) / 256, 256, 0, s2>>>(E, (const float*)d_in[7], Bg1, 128);
    k_nodewsplit<<<dim3(256 * 64 / 256, 14), 256, 0, s2>>>(E, (const float*)d_in[8], WC1h, WC1l, 64, 256, 1);
    k_nodew<<<((long)NN * 64 + 255) / 256, 256, 0, s2>>>(E, (const float*)d_in[9], Bc1, 64);
    k_zeroH<<<ZG, 256, 0, s2>>>(H2, H2hi, H2lo, AH2hi, AH2lo, AZH2hi, AZH2lo);

    k_supports<<<NP, 256, 0, s0>>>(E, Ahi, Alo);
    k_srcsplit<<<(NP * NC0 + 255) / 256, 256, 0, s0>>>(src, X0hi, X0lo);
    k_nodewsplit<<<dim3(144 * 128 / 256, 14), 256, 0, s0>>>(E, (const float*)d_in[2], WG0h, WG0l, 128, 144, 0);
    k_nodew<<<((long)NN * 128 + 255) / 256, 256, 0, s0>>>(E, (const float*)d_in[3], Bg0, 128);
    k_nodewsplit<<<dim3(144 * 64 / 256, 14), 256, 0, s0>>>(E, (const float*)d_in[4], WC0h, WC0l, 64, 144, 0);
    k_nodew<<<((long)NN * 64 + 255) / 256, 256, 0, s0>>>(E, (const float*)d_in[5], Bc0, 64);
    k_mma<<<dim3(NC0 / 128, 14), 128, 0, s0>>>(Ahi, Alo, X0hi, X0lo, AX0hi, AX0lo, NC0, NC0);

    // layer 0 on s0; per-step A@H lands directly into ASEQ slot (t-1)
    k_zeroH<<<ZG, 256, 0, s0>>>(H, Hhi, Hlo, AHhi, AHlo, AZHhi, AZHlo);
    for (int t = 0; t < TT; t++) {
        const bf16* ahh = AHhi; const bf16* ahl = AHlo; size_t ahstr = NB;
        if (t > 0) {
            bf16* dsth = AShi + (size_t)(t - 1) * NB;
            bf16* dstl = ASlo + (size_t)(t - 1) * NB;
            k_mma<<<GSTEP, 128, 0, s0>>>(Ahi, Alo, Hhi, Hlo, dsth, dstl, NB, NCSEQ);
            cudaEventRecord(ev[t - 1], s0);
            ahh = dsth; ahl = dstl; ahstr = NCSEQ;
        }
        int sc = (t == 0) ? 8 : 0, nc = (t == 0) ? 1 : 9;   // t=0: only chunk 8
        k_pn<128, false, true><<<NN, 128, 0, s0>>>(X0hi, X0lo, NC0, (size_t)t * 64,
            Hhi, Hlo, AX0hi, AX0lo, NC0, (size_t)t * 64, ahh, ahl, ahstr,
            WG0h, WG0l, Bg0, R, H, ZHhi, ZHlo, (bf16*)0, (bf16*)0, 0, sc, nc, 0);
        if (t > 0)
            k_mma<<<GSTEP, 128, 0, s0>>>(Ahi, Alo, ZHhi, ZHlo, AZHhi, AZHlo, NB, NB);
        k_pn<64, true, true><<<NN, 128, 0, s0>>>(X0hi, X0lo, NC0, (size_t)t * 64,
            ZHhi, ZHlo, AX0hi, AX0lo, NC0, (size_t)t * 64, AZHhi, AZHlo, (size_t)NB,
            WC0h, WC0l, Bc0, R, H, Hhi, Hlo, Shi, Slo, (size_t)t * NB, sc, nc, 0);
    }
    k_mma<<<GSTEP, 128, 0, s0>>>(Ahi, Alo, Shi + (size_t)11 * NB, Slo + (size_t)11 * NB,
                                 AShi + (size_t)11 * NB, ASlo + (size_t)11 * NB, NCSEQ, NCSEQ);
    cudaEventRecord(ev[11], s0);

    // layer 1 on s2, gated per step; t=0 skips zero h/Ah chunk groups
    for (int t = 0; t < TT; t++) {
        cudaStreamWaitEvent(s2, ev[t], 0);
        if (t > 0)
            k_mma<<<GSTEP, 128, 0, s2>>>(Ahi, Alo, H2hi, H2lo, AH2hi, AH2lo, NB, NB);
        int nc1 = (t == 0) ? 8 : 16, gp1 = (t == 0) ? 1 : 0;  // t=0: chunks 0-3,8-11
        k_pn<128, false, false><<<NN, 128, 0, s2>>>(Shi, Slo, NCSEQ, (size_t)t * NB,
            H2hi, H2lo, AShi, ASlo, NCSEQ, (size_t)t * NB, AH2hi, AH2lo, (size_t)NB,
            WG1h, WG1l, Bg1, R2, H2, ZH2hi, ZH2lo, (bf16*)0, (bf16*)0, 0, 0, nc1, gp1);
        if (t > 0)
            k_mma<<<GSTEP, 128, 0, s2>>>(Ahi, Alo, ZH2hi, ZH2lo, AZH2hi, AZH2lo, NB, NB);
        k_pn<64, true, false><<<NN, 128, 0, s2>>>(Shi, Slo, NCSEQ, (size_t)t * NB,
            ZH2hi, ZH2lo, AShi, ASlo, NCSEQ, (size_t)t * NB, AZH2hi, AZH2lo, (size_t)NB,
            WC1h, WC1l, Bc1, R2, H2, H2hi, H2lo, (bf16*)0, (bf16*)0, 0, 0, nc1, gp1);
    }
    k_final<<<(BB * NN + 255) / 256, 256, 0, s2>>>(H2, cw, cb, out);

    cudaEventRecord(evJoin, s2);
    cudaStreamWaitEvent(s0, evJoin, 0);

    cudaStreamCaptureStatus st = cudaStreamCaptureStatusNone;
    cudaStreamIsCapturing(s0, &st);
    if (st == cudaStreamCaptureStatusNone) {
        cudaStreamDestroy(s2);
        for (int i = 0; i < TT; i++) cudaEventDestroy(ev[i]);
        cudaEventDestroy(evFork);
        cudaEventDestroy(evJoin);
    }
}